// round 3
// baseline (speedup 1.0000x reference)
#include <cuda_runtime.h>

#define BB 8
#define TT 2048
#define BT 16384
#define DD 512
#define KK 1024
#define HALF_N 8388608u   // BT*KK/2

// ---------------- scratch (static device allocations only) ----------------
__device__ float g_h1[BT * 256];
__device__ float g_res[BT * DD];
__device__ float g_qout[BT * DD];
__device__ float g_cbT[DD * KK];          // codebook transposed [d][k]
__device__ float g_dist[BT * KK];         // scaled scores s10, 64MB
__device__ unsigned g_rowmax[BT];         // fmap-encoded row max of s10
__device__ float g_csq[KK];
__device__ float g_window;                // gumbel max-min window (+margin)
__device__ float g_acc[2];   // [0]=commit sum, [1]=mse sum

// ---------------- packed f32x2 helpers ----------------
__device__ __forceinline__ void splat2(unsigned long long& d, float a) {
    asm("mov.b64 %0, {%1, %1};" : "=l"(d) : "f"(a));
}
__device__ __forceinline__ void pack2(unsigned long long& d, float a, float b) {
    asm("mov.b64 %0, {%1, %2};" : "=l"(d) : "f"(a), "f"(b));
}
__device__ __forceinline__ void unpack2(float& a, float& b, unsigned long long d) {
    asm("mov.b64 {%0, %1}, %2;" : "=f"(a), "=f"(b) : "l"(d));
}
__device__ __forceinline__ void ffma2(unsigned long long& acc,
                                      unsigned long long a, unsigned long long b) {
    asm("fma.rn.f32x2 %0, %1, %2, %0;" : "+l"(acc) : "l"(a), "l"(b));
}

// ---------------- JAX threefry2x32 (exact) ----------------
__host__ __device__ inline void tf2x32(unsigned k0, unsigned k1,
                                       unsigned x0, unsigned x1,
                                       unsigned& o0, unsigned& o1) {
    unsigned ks2 = k0 ^ k1 ^ 0x1BD11BDAu;
    x0 += k0; x1 += k1;
#define TF_RND(r) { x0 += x1; x1 = (x1 << (r)) | (x1 >> (32 - (r))); x1 ^= x0; }
    TF_RND(13) TF_RND(15) TF_RND(26) TF_RND(6)
    x0 += k1;  x1 += ks2 + 1u;
    TF_RND(17) TF_RND(29) TF_RND(16) TF_RND(24)
    x0 += ks2; x1 += k0 + 2u;
    TF_RND(13) TF_RND(15) TF_RND(26) TF_RND(6)
    x0 += k0;  x1 += k1 + 3u;
    TF_RND(17) TF_RND(29) TF_RND(16) TF_RND(24)
    x0 += k1;  x1 += ks2 + 4u;
    TF_RND(13) TF_RND(15) TF_RND(26) TF_RND(6)
    x0 += ks2; x1 += k0 + 5u;
#undef TF_RND
    o0 = x0; o1 = x1;
}

__device__ inline float gumbel_from_bits(unsigned bits) {
    float f = __uint_as_float((bits >> 9) | 0x3f800000u) - 1.0f;
    float u = (f == 0.0f) ? 1.17549435e-38f : f;
    return -__logf(-__logf(u));
}

__device__ inline unsigned fmap(float f) {   // monotone float -> uint
    unsigned u = __float_as_uint(f);
    return (u & 0x80000000u) ? ~u : (u | 0x80000000u);
}
__device__ inline float unfmap(unsigned u) {
    unsigned v = (u & 0x80000000u) ? (u ^ 0x80000000u) : ~u;
    return __uint_as_float(v);
}

__device__ inline float gelu_exact(float v) {
    return 0.5f * v * (1.0f + erff(v * 0.7071067811865476f));
}

// ---------------- codebook transpose: cbT[d][k] = cb[k][d] ----------------
__global__ void transpose_cb(const float* __restrict__ cb) {
    __shared__ float t[32][33];
    int k0 = blockIdx.x * 32;
    int d0 = blockIdx.y * 32;
    int tx = threadIdx.x, ty = threadIdx.y;  // 32 x 8
    for (int l = 0; l < 32; l += 8)
        t[ty + l][tx] = cb[(k0 + ty + l) * DD + d0 + tx];
    __syncthreads();
    for (int l = 0; l < 32; l += 8)
        g_cbT[(d0 + ty + l) * KK + k0 + tx] = t[tx][ty + l];
}

// ---------------- conv3 (same-pad, per-batch halo), float4 + FFMA2 core ----
// in:[BT,CIN]  w:[COUT,CIN,3]  out:[BT,COUT]
// Tile 128 rows x 128 cols. Thread (tx,ty): rows ty*4+{0..3} & 64+ty*4+{0..3},
// cols tx*4+{0..3} & 64+tx*4+{0..3}.
#define SAS 136
template<int CIN, int COUT, bool FUSE_MSE>
__global__ void __launch_bounds__(256) conv3(
    const float* __restrict__ in, const float* __restrict__ w,
    const float* __restrict__ bias, float* __restrict__ out,
    const float* __restrict__ xref)
{
    __shared__ __align__(16) float As[16][SAS];
    __shared__ __align__(16) float Bs[16][SAS];
    const int tid = threadIdx.x;
    const int tx = tid & 15, ty = tid >> 4;
    const int r0 = blockIdx.x * 128;
    const int n0 = blockIdx.y * 128;

    // staging maps
    const int sm  = tid >> 1;            // A: row m 0..127
    const int skq = (tid & 1) * 8;       // A: k offset (8 k's)
    const int arow = r0 + sm;
    const int t    = arow & (TT - 1);
    const int bk  = tid >> 4;            // B: k row 0..15
    const int bn  = (tid & 15) * 8;      // B: 8 cols

    unsigned long long acc2[8][4];
#pragma unroll
    for (int i = 0; i < 8; ++i)
#pragma unroll
        for (int j = 0; j < 4; ++j) acc2[i][j] = 0ull;

    for (int tap = 0; tap < 3; ++tap) {
        const int st = t + tap - 1;
        const bool rvalid = (st >= 0 && st < TT);
        const float* aptr = in + (size_t)(arow + tap - 1) * CIN;
        for (int cc = 0; cc < CIN; cc += 16) {
            // ---- stage A [16k][128m] ----
            if (cc + 16 <= CIN) {
                float4 av0, av1;
                if (rvalid) {
                    av0 = *(const float4*)(aptr + cc + skq);
                    av1 = *(const float4*)(aptr + cc + skq + 4);
                } else {
                    av0 = make_float4(0.f, 0.f, 0.f, 0.f);
                    av1 = av0;
                }
                As[skq + 0][sm] = av0.x; As[skq + 1][sm] = av0.y;
                As[skq + 2][sm] = av0.z; As[skq + 3][sm] = av0.w;
                As[skq + 4][sm] = av1.x; As[skq + 5][sm] = av1.y;
                As[skq + 6][sm] = av1.z; As[skq + 7][sm] = av1.w;
            } else {
#pragma unroll
                for (int q = 0; q < 8; ++q) {
                    int ci = cc + skq + q;
                    float v = (rvalid && ci < CIN) ? aptr[ci] : 0.0f;
                    As[skq + q][sm] = v;
                }
            }
            // ---- stage B [16k][128n] ----
            {
                int ci = cc + bk;
#pragma unroll
                for (int c = 0; c < 8; ++c) {
                    int co = n0 + bn + c;
                    float v = 0.0f;
                    if (co < COUT && ci < CIN)
                        v = w[((size_t)co * CIN + ci) * 3 + tap];
                    Bs[bk][bn + c] = v;
                }
            }
            __syncthreads();
#pragma unroll
            for (int kk = 0; kk < 16; ++kk) {
                float4 aL = *(const float4*)&As[kk][ty * 4];
                float4 aH = *(const float4*)&As[kk][64 + ty * 4];
                float4 bL = *(const float4*)&Bs[kk][tx * 4];
                float4 bH = *(const float4*)&Bs[kk][64 + tx * 4];
                unsigned long long b2[4], a2;
                pack2(b2[0], bL.x, bL.y);
                pack2(b2[1], bL.z, bL.w);
                pack2(b2[2], bH.x, bH.y);
                pack2(b2[3], bH.z, bH.w);
                float ar[8] = {aL.x, aL.y, aL.z, aL.w, aH.x, aH.y, aH.z, aH.w};
#pragma unroll
                for (int i = 0; i < 8; ++i) {
                    splat2(a2, ar[i]);
#pragma unroll
                    for (int j = 0; j < 4; ++j) ffma2(acc2[i][j], a2, b2[j]);
                }
            }
            __syncthreads();
        }
    }

    float local = 0.0f;
#pragma unroll
    for (int i = 0; i < 8; ++i) {
        int m = (i < 4) ? (ty * 4 + i) : (64 + ty * 4 + (i - 4));
        int r = r0 + m;
#pragma unroll
        for (int jp = 0; jp < 4; ++jp) {
            float v0, v1;
            unpack2(v0, v1, acc2[i][jp]);
            float vv[2] = {v0, v1};
#pragma unroll
            for (int h = 0; h < 2; ++h) {
                int jc = 2 * jp + h;  // 0..7
                int co = n0 + ((jc < 4) ? (tx * 4 + jc) : (64 + tx * 4 + (jc - 4)));
                if (co < COUT) {
                    float v = gelu_exact(vv[h] + bias[co]);
                    if (FUSE_MSE) {
                        float d = xref[(size_t)r * COUT + co] - v;
                        local += d * d;
                    } else {
                        out[(size_t)r * COUT + co] = v;
                    }
                }
            }
        }
    }
    if (FUSE_MSE) {
        __shared__ float red[256];
        red[tid] = local;
        __syncthreads();
        for (int s = 128; s > 0; s >>= 1) {
            if (tid < s) red[tid] += red[tid + s];
            __syncthreads();
        }
        if (tid == 0) atomicAdd(&g_acc[1], red[0]);
    }
}

// ---------------- VQ score GEMM: store s10, track row max ----------------
// Tile 128 rows x 128 cols; thread rows ty*4+{0..3} & 64+ty*4+{0..3},
// cols tx*4+{0..3} & 64+tx*4+{0..3}.
__global__ void __launch_bounds__(256) vq_score_gemm() {
    __shared__ __align__(16) float As[16][SAS];
    __shared__ __align__(16) float Bs[16][SAS];
    __shared__ unsigned sRowMax[128];
    const int tid = threadIdx.x;
    const int tx = tid & 15, ty = tid >> 4;
    const int r0 = blockIdx.x * 128;
    const int k0 = blockIdx.y * 128;

    if (tid < 128) sRowMax[tid] = 0u;

    const int sm  = tid >> 1;
    const int skq = (tid & 1) * 8;
    const float* aptr = &g_res[(size_t)(r0 + sm) * DD];
    const int bk  = tid >> 4;
    const int bn4 = (tid & 15) * 4;

    unsigned long long acc2[8][4];
#pragma unroll
    for (int i = 0; i < 8; ++i)
#pragma unroll
        for (int j = 0; j < 4; ++j) acc2[i][j] = 0ull;

    for (int cc = 0; cc < DD; cc += 16) {
        float4 av0 = *(const float4*)(aptr + cc + skq);
        float4 av1 = *(const float4*)(aptr + cc + skq + 4);
        As[skq + 0][sm] = av0.x; As[skq + 1][sm] = av0.y;
        As[skq + 2][sm] = av0.z; As[skq + 3][sm] = av0.w;
        As[skq + 4][sm] = av1.x; As[skq + 5][sm] = av1.y;
        As[skq + 6][sm] = av1.z; As[skq + 7][sm] = av1.w;
        const float* bptr = &g_cbT[(size_t)(cc + bk) * KK + k0];
        *(float4*)&Bs[bk][bn4]      = *(const float4*)(bptr + bn4);
        *(float4*)&Bs[bk][64 + bn4] = *(const float4*)(bptr + 64 + bn4);
        __syncthreads();
#pragma unroll
        for (int kk = 0; kk < 16; ++kk) {
            float4 aL = *(const float4*)&As[kk][ty * 4];
            float4 aH = *(const float4*)&As[kk][64 + ty * 4];
            float4 bL = *(const float4*)&Bs[kk][tx * 4];
            float4 bH = *(const float4*)&Bs[kk][64 + tx * 4];
            unsigned long long b2[4], a2;
            pack2(b2[0], bL.x, bL.y);
            pack2(b2[1], bL.z, bL.w);
            pack2(b2[2], bH.x, bH.y);
            pack2(b2[3], bH.z, bH.w);
            float ar[8] = {aL.x, aL.y, aL.z, aL.w, aH.x, aH.y, aH.z, aH.w};
#pragma unroll
            for (int i = 0; i < 8; ++i) {
                splat2(a2, ar[i]);
#pragma unroll
                for (int j = 0; j < 4; ++j) ffma2(acc2[i][j], a2, b2[j]);
            }
        }
        __syncthreads();
    }

    // epilogue: s10 = (2*dot - csq)*10 ; store + row max
    float csq[8];
#pragma unroll
    for (int h = 0; h < 2; ++h)
#pragma unroll
        for (int c = 0; c < 4; ++c)
            csq[4 * h + c] = g_csq[k0 + 64 * h + tx * 4 + c];

#pragma unroll
    for (int i = 0; i < 8; ++i) {
        int m = (i < 4) ? (ty * 4 + i) : (64 + ty * 4 + (i - 4));
        int r = r0 + m;
        float s[8];
        float tmax = -3.0e38f;
#pragma unroll
        for (int jp = 0; jp < 4; ++jp) {
            float d0, d1;
            unpack2(d0, d1, acc2[i][jp]);
            s[2 * jp]     = (2.0f * d0 - csq[2 * jp])     * 10.0f;
            s[2 * jp + 1] = (2.0f * d1 - csq[2 * jp + 1]) * 10.0f;
        }
#pragma unroll
        for (int c = 0; c < 8; ++c) tmax = fmaxf(tmax, s[c]);
        float4 v0 = make_float4(s[0], s[1], s[2], s[3]);
        float4 v1 = make_float4(s[4], s[5], s[6], s[7]);
        float* drow = &g_dist[(size_t)r * KK + k0];
        *(float4*)(drow + tx * 4)      = v0;
        *(float4*)(drow + 64 + tx * 4) = v1;
        atomicMax(&sRowMax[m], fmap(tmax));
    }
    __syncthreads();
    if (tid < 128) atomicMax(&g_rowmax[r0 + tid], sRowMax[tid]);
}

// ---------------- pick (filtered gumbel argmax) + update, fused ----------
__global__ void __launch_bounds__(128) vq_pick_update(
    const float* __restrict__ cb, int stage, unsigned fk0, unsigned fk1)
{
    const int bt = blockIdx.x;
    const int tid = threadIdx.x;   // 128
    __shared__ unsigned long long best;
    __shared__ float s_tau;

    if (tid == 0) {
        float rm = unfmap(g_rowmax[bt]);
        s_tau = rm - g_window;
        g_rowmax[bt] = 0u;         // reset for next stage
        best = 0ull;
    }
    __syncthreads();
    const float tau = s_tau;

    const float* drow = &g_dist[(size_t)bt * KK];
    float4 v0 = *(const float4*)(drow + tid * 8);
    float4 v1 = *(const float4*)(drow + tid * 8 + 4);
    float s[8] = {v0.x, v0.y, v0.z, v0.w, v1.x, v1.y, v1.z, v1.w};
    unsigned long long loc = 0ull;
#pragma unroll
    for (int c = 0; c < 8; ++c) {
        if (s[c] >= tau) {
            unsigned k = (unsigned)(tid * 8 + c);
            unsigned n, b0, b1, bits;
            if (bt < 8192) {
                n = (unsigned)bt * 1024u + k;
                tf2x32(fk0, fk1, n, n + HALF_N, b0, b1);
                bits = b0;
            } else {
                n = (unsigned)(bt - 8192) * 1024u + k;
                tf2x32(fk0, fk1, n, n + HALF_N, b0, b1);
                bits = b1;
            }
            float sc = s[c] + gumbel_from_bits(bits);
            unsigned long long cand =
                ((unsigned long long)fmap(sc) << 32) | (unsigned long long)(~k);
            if (cand > loc) loc = cand;
        }
    }
    if (loc) atomicMax(&best, loc);
    __syncthreads();

    int k = (int)(~(unsigned)(best & 0xffffffffull));

    // update residual / qout / commit loss
    float local = 0.0f;
#pragma unroll
    for (int l = 0; l < 4; ++l) {
        int d = tid + 128 * l;
        float r = g_res[(size_t)bt * DD + d];
        float q = cb[(size_t)k * DD + d];
        float diff = q - r;
        float qst = r + diff;
        float qo = (stage == 0) ? qst : (g_qout[(size_t)bt * DD + d] + qst);
        g_qout[(size_t)bt * DD + d] = qo;
        g_res[(size_t)bt * DD + d] = r - q;
        local += diff * diff;
    }
    __shared__ float red[128];
    red[tid] = local;
    __syncthreads();
    for (int ss = 64; ss > 0; ss >>= 1) {
        if (tid < ss) red[tid] += red[tid + ss];
        __syncthreads();
    }
    if (tid == 0) atomicAdd(&g_acc[0], red[0]);
}

// ---------------- init: csq, rowmax reset, window, accumulators ----------
__global__ void vq_init(const float* __restrict__ cb) {
    int k = blockIdx.x;
    int tid = threadIdx.x;  // 128
    float local = 0.0f;
#pragma unroll
    for (int l = 0; l < 4; ++l) {
        float c = cb[(size_t)k * DD + tid + 128 * l];
        local += c * c;
    }
    __shared__ float red[128];
    red[tid] = local;
    __syncthreads();
    for (int s = 64; s > 0; s >>= 1) {
        if (tid < s) red[tid] += red[tid + s];
        __syncthreads();
    }
    if (tid == 0) g_csq[k] = red[0];
    if (tid < 16) g_rowmax[blockIdx.x * 16 + tid] = 0u;
    if (blockIdx.x == 0 && tid < 2) g_acc[tid] = 0.0f;
    if (blockIdx.x == 0 && tid == 0) {
        // self-calibrated gumbel window on THIS hardware's __logf
        float ghi = gumbel_from_bits(0xFFFFFFFFu);
        float glo = gumbel_from_bits(0u);
        g_window = (ghi - glo) + 0.5f;
    }
}

__global__ void finalize_k(float* __restrict__ out) {
    out[0] = g_acc[1] * (1.0f / 1638400.0f)      // mse: /(BT*100)
           + g_acc[0] * (1.0f / 67108864.0f);    // commit: /(8*BT*512)
}

// ---------------- host launcher (graph-capturable, alloc-free) -------------
extern "C" void kernel_launch(void* const* d_in, const int* in_sizes, int n_in,
                              void* d_out, int out_size) {
    const float* x   = (const float*)d_in[0];
    const float* ew1 = (const float*)d_in[1];
    const float* eb1 = (const float*)d_in[2];
    const float* ew2 = (const float*)d_in[3];
    const float* eb2 = (const float*)d_in[4];
    const float* cb  = (const float*)d_in[5];
    const float* dw1 = (const float*)d_in[6];
    const float* db1 = (const float*)d_in[7];
    const float* dw2 = (const float*)d_in[8];
    const float* db2 = (const float*)d_in[9];
    float* out = (float*)d_out;

    float *h1, *res, *qout;
    cudaGetSymbolAddress((void**)&h1,   g_h1);
    cudaGetSymbolAddress((void**)&res,  g_res);
    cudaGetSymbolAddress((void**)&qout, g_qout);

    // fold-in keys for each VQ stage: threefry((0,42),(0,i))
    unsigned fk0[8], fk1[8];
    for (int s = 0; s < 8; ++s) tf2x32(0u, 42u, 0u, (unsigned)s, fk0[s], fk1[s]);

    vq_init<<<KK, 128>>>(cb);
    transpose_cb<<<dim3(KK / 32, DD / 32), dim3(32, 8)>>>(cb);

    // encoder
    conv3<100, 256, false><<<dim3(128, 2), 256>>>(x,  ew1, eb1, h1,  nullptr);
    conv3<256, 512, false><<<dim3(128, 4), 256>>>(h1, ew2, eb2, res, nullptr);

    // residual VQ, 8 stages
    for (int s = 0; s < 8; ++s) {
        vq_score_gemm<<<dim3(128, 8), 256>>>();
        vq_pick_update<<<BT, 128>>>(cb, s, fk0[s], fk1[s]);
    }

    // decoder (+ fused MSE on the last conv)
    conv3<512, 256, false><<<dim3(128, 2), 256>>>(qout, dw1, db1, h1, nullptr);
    conv3<256, 100, true ><<<dim3(128, 1), 256>>>(h1,  dw2, db2, nullptr, x);

    finalize_k<<<1, 1>>>(out);
}

// round 6
// speedup vs baseline: 1.0477x; 1.0477x over previous
#include <cuda_runtime.h>
#include <cstdint>

#define TT 2048
#define BT 16384
#define DD 512
#define KK 1024
#define HALF_N 8388608u   // BT*KK/2

// ---------------- scratch (static device allocations only) ----------------
__device__ float g_h1[BT * 256];
__device__ float g_res[BT * DD];
__device__ float g_qout[BT * DD];
__device__ float g_cbT[DD * KK];          // codebook transposed [d][k]
__device__ unsigned long long g_best[BT];
__device__ float g_csq[KK];
__device__ float g_window;                // gumbel hi-lo window + margin
__device__ float g_acc[2];   // [0]=commit sum, [1]=mse sum

// ---------------- packed f32x2 helpers ----------------
__device__ __forceinline__ void splat2(unsigned long long& d, float a) {
    asm("mov.b64 %0, {%1, %1};" : "=l"(d) : "f"(a));
}
__device__ __forceinline__ void pack2(unsigned long long& d, float a, float b) {
    asm("mov.b64 %0, {%1, %2};" : "=l"(d) : "f"(a), "f"(b));
}
__device__ __forceinline__ void unpack2(float& a, float& b, unsigned long long d) {
    asm("mov.b64 {%0, %1}, %2;" : "=f"(a), "=f"(b) : "l"(d));
}
__device__ __forceinline__ void ffma2(unsigned long long& acc,
                                      unsigned long long a, unsigned long long b) {
    asm("fma.rn.f32x2 %0, %1, %2, %0;" : "+l"(acc) : "l"(a), "l"(b));
}

// ---------------- JAX threefry2x32 (exact) ----------------
__host__ __device__ inline void tf2x32(unsigned k0, unsigned k1,
                                       unsigned x0, unsigned x1,
                                       unsigned& o0, unsigned& o1) {
    unsigned ks2 = k0 ^ k1 ^ 0x1BD11BDAu;
    x0 += k0; x1 += k1;
#define TF_RND(r) { x0 += x1; x1 = (x1 << (r)) | (x1 >> (32 - (r))); x1 ^= x0; }
    TF_RND(13) TF_RND(15) TF_RND(26) TF_RND(6)
    x0 += k1;  x1 += ks2 + 1u;
    TF_RND(17) TF_RND(29) TF_RND(16) TF_RND(24)
    x0 += ks2; x1 += k0 + 2u;
    TF_RND(13) TF_RND(15) TF_RND(26) TF_RND(6)
    x0 += k0;  x1 += k1 + 3u;
    TF_RND(17) TF_RND(29) TF_RND(16) TF_RND(24)
    x0 += k1;  x1 += ks2 + 4u;
    TF_RND(13) TF_RND(15) TF_RND(26) TF_RND(6)
    x0 += ks2; x1 += k0 + 5u;
#undef TF_RND
    o0 = x0; o1 = x1;
}

__device__ inline float gumbel_from_bits(unsigned bits) {
    float f = __uint_as_float((bits >> 9) | 0x3f800000u) - 1.0f;
    float u = (f == 0.0f) ? 1.17549435e-38f : f;
    return -__logf(-__logf(u));
}

__device__ inline unsigned fmap(float f) {   // monotone float -> uint
    unsigned u = __float_as_uint(f);
    return (u & 0x80000000u) ? ~u : (u | 0x80000000u);
}
__device__ inline float unfmap(unsigned u) {
    unsigned v = (u & 0x80000000u) ? (u ^ 0x80000000u) : ~u;
    return __uint_as_float(v);
}

__device__ inline float gelu_exact(float v) {
    return 0.5f * v * (1.0f + erff(v * 0.7071067811865476f));
}

// ---------------- codebook transpose: cbT[d][k] = cb[k][d] ----------------
__global__ void transpose_cb(const float* __restrict__ cb) {
    __shared__ float t[32][33];
    int k0 = blockIdx.x * 32;
    int d0 = blockIdx.y * 32;
    int tx = threadIdx.x, ty = threadIdx.y;  // 32 x 8
    for (int l = 0; l < 32; l += 8)
        t[ty + l][tx] = cb[(k0 + ty + l) * DD + d0 + tx];
    __syncthreads();
    for (int l = 0; l < 32; l += 8)
        g_cbT[(d0 + ty + l) * KK + k0 + tx] = t[tx][ty + l];
}

// ---------------- conv3 (round-2 proven version, untouched) ----------------
template<int CIN, int COUT, bool FUSE_MSE>
__global__ void __launch_bounds__(256) conv3(
    const float* __restrict__ in, const float* __restrict__ w,
    const float* __restrict__ bias, float* __restrict__ out,
    const float* __restrict__ xref)
{
    __shared__ float As[16][129];
    __shared__ float Bs[16][129];
    const int tid = threadIdx.x;
    const int tx = tid & 15, ty = tid >> 4;
    const int r0 = blockIdx.x * 128;
    const int n0 = blockIdx.y * 128;
    const int lk = tid & 15, lm = tid >> 4;

    unsigned long long acc2[8][4];
#pragma unroll
    for (int i = 0; i < 8; ++i)
#pragma unroll
        for (int j = 0; j < 4; ++j) acc2[i][j] = 0ull;

    for (int tap = 0; tap < 3; ++tap) {
        for (int cc = 0; cc < CIN; cc += 16) {
#pragma unroll
            for (int l = 0; l < 8; ++l) {
                int m = lm + 16 * l;
                int r = r0 + m;
                int t = r & (TT - 1);
                int st = t + tap - 1;
                int ci = cc + lk;
                float v = 0.0f;
                if (st >= 0 && st < TT && ci < CIN)
                    v = in[(size_t)(r + tap - 1) * CIN + ci];
                As[lk][m] = v;
            }
#pragma unroll
            for (int l = 0; l < 8; ++l) {
                int n = lm + 16 * l;
                int co = n0 + n;
                int ci = cc + lk;
                float v = 0.0f;
                if (co < COUT && ci < CIN)
                    v = w[((size_t)co * CIN + ci) * 3 + tap];
                Bs[lk][n] = v;
            }
            __syncthreads();
#pragma unroll
            for (int kk = 0; kk < 16; ++kk) {
                float a[8], b[8];
#pragma unroll
                for (int i = 0; i < 8; ++i) a[i] = As[kk][ty + 16 * i];
#pragma unroll
                for (int j = 0; j < 8; ++j) b[j] = Bs[kk][tx + 16 * j];
                unsigned long long b2[4], a2;
#pragma unroll
                for (int j = 0; j < 4; ++j) pack2(b2[j], b[2 * j], b[2 * j + 1]);
#pragma unroll
                for (int i = 0; i < 8; ++i) {
                    splat2(a2, a[i]);
#pragma unroll
                    for (int j = 0; j < 4; ++j) ffma2(acc2[i][j], a2, b2[j]);
                }
            }
            __syncthreads();
        }
    }

    float local = 0.0f;
#pragma unroll
    for (int i = 0; i < 8; ++i) {
        int r = r0 + ty + 16 * i;
#pragma unroll
        for (int jp = 0; jp < 4; ++jp) {
            float v0, v1;
            unpack2(v0, v1, acc2[i][jp]);
            float vv[2] = {v0, v1};
#pragma unroll
            for (int h = 0; h < 2; ++h) {
                int j = 2 * jp + h;
                int co = n0 + tx + 16 * j;
                if (co < COUT) {
                    float v = gelu_exact(vv[h] + bias[co]);
                    if (FUSE_MSE) {
                        float d = xref[(size_t)r * COUT + co] - v;
                        local += d * d;
                    } else {
                        out[(size_t)r * COUT + co] = v;
                    }
                }
            }
        }
    }
    if (FUSE_MSE) {
        __shared__ float red[256];
        red[tid] = local;
        __syncthreads();
        for (int s = 128; s > 0; s >>= 1) {
            if (tid < s) red[tid] += red[tid + s];
            __syncthreads();
        }
        if (tid == 0) atomicAdd(&g_acc[1], red[0]);
    }
}

// ---------------- VQ score: dup-A FFMA2 GEMM + windowed gumbel argmax ------
// Tile 128 rows (m<64: bt=r0+m ; m>=64: bt=8192+r0+(m-64)) x 128 cols.
// grid.x MUST be 128 (r0 covers 0..8191 only; high half comes via +8192).
#define SAS2 264   // dup-A row stride (floats): 256 + 8
#define SBS 136    // B row stride (floats)
__global__ void __launch_bounds__(256) vq_score(unsigned fk0, unsigned fk1)
{
    __shared__ __align__(16) float As2[16][SAS2];
    __shared__ __align__(16) float Bs[16][SBS];
    __shared__ unsigned sMax[128];
    const int tid = threadIdx.x;
    const int tx = tid & 15, ty = tid >> 4;
    const int r0 = blockIdx.x * 64;
    const int k0 = blockIdx.y * 128;

    // staging maps
    const int sm  = tid >> 1;            // A: row m 0..127
    const int skq = (tid & 1) * 8;       // A: k offset (8 k's)
    const int arow = (sm < 64) ? (r0 + sm) : (8192 + r0 + (sm - 64));
    const float* aptr = &g_res[(size_t)arow * DD];
    const int bk  = tid >> 4;            // B: k row 0..15
    const int bn4 = (tid & 15) * 4;

    unsigned long long acc2[8][4];
#pragma unroll
    for (int i = 0; i < 8; ++i)
#pragma unroll
        for (int j = 0; j < 4; ++j) acc2[i][j] = 0ull;

    // prefetch chunk 0
    float4 av0 = *(const float4*)(aptr + skq);
    float4 av1 = *(const float4*)(aptr + skq + 4);
    const float* bptr0 = &g_cbT[(size_t)bk * KK + k0];
    float4 bv0 = *(const float4*)(bptr0 + bn4);
    float4 bv1 = *(const float4*)(bptr0 + 64 + bn4);

    for (int cc = 0; cc < DD; cc += 16) {
        // ---- store staged regs to smem (A duplicated) ----
        {
            unsigned long long d;
            pack2(d, av0.x, av0.x); *(unsigned long long*)&As2[skq + 0][2 * sm] = d;
            pack2(d, av0.y, av0.y); *(unsigned long long*)&As2[skq + 1][2 * sm] = d;
            pack2(d, av0.z, av0.z); *(unsigned long long*)&As2[skq + 2][2 * sm] = d;
            pack2(d, av0.w, av0.w); *(unsigned long long*)&As2[skq + 3][2 * sm] = d;
            pack2(d, av1.x, av1.x); *(unsigned long long*)&As2[skq + 4][2 * sm] = d;
            pack2(d, av1.y, av1.y); *(unsigned long long*)&As2[skq + 5][2 * sm] = d;
            pack2(d, av1.z, av1.z); *(unsigned long long*)&As2[skq + 6][2 * sm] = d;
            pack2(d, av1.w, av1.w); *(unsigned long long*)&As2[skq + 7][2 * sm] = d;
            *(float4*)&Bs[bk][bn4]      = bv0;
            *(float4*)&Bs[bk][64 + bn4] = bv1;
        }
        __syncthreads();
        // ---- prefetch next chunk into regs (overlaps compute) ----
        if (cc + 16 < DD) {
            av0 = *(const float4*)(aptr + cc + 16 + skq);
            av1 = *(const float4*)(aptr + cc + 16 + skq + 4);
            const float* bptr = &g_cbT[(size_t)(cc + 16 + bk) * KK + k0];
            bv0 = *(const float4*)(bptr + bn4);
            bv1 = *(const float4*)(bptr + 64 + bn4);
        }
        // ---- compute ----
#pragma unroll
        for (int kk = 0; kk < 16; ++kk) {
            ulonglong2 a01 = *(const ulonglong2*)&As2[kk][ty * 8];
            ulonglong2 a23 = *(const ulonglong2*)&As2[kk][ty * 8 + 4];
            ulonglong2 a45 = *(const ulonglong2*)&As2[kk][128 + ty * 8];
            ulonglong2 a67 = *(const ulonglong2*)&As2[kk][128 + ty * 8 + 4];
            ulonglong2 bLo = *(const ulonglong2*)&Bs[kk][tx * 4];
            ulonglong2 bHi = *(const ulonglong2*)&Bs[kk][64 + tx * 4];
            unsigned long long av[8] = {a01.x, a01.y, a23.x, a23.y,
                                        a45.x, a45.y, a67.x, a67.y};
            unsigned long long bv[4] = {bLo.x, bLo.y, bHi.x, bHi.y};
#pragma unroll
            for (int i = 0; i < 8; ++i)
#pragma unroll
                for (int j = 0; j < 4; ++j)
                    ffma2(acc2[i][j], av[i], bv[j]);
        }
        __syncthreads();
    }

    // ---- epilogue: tile-local max, then windowed threefry on survivors ----
    float csq[8];
#pragma unroll
    for (int h = 0; h < 2; ++h)
#pragma unroll
        for (int c = 0; c < 4; ++c)
            csq[4 * h + c] = g_csq[k0 + 64 * h + tx * 4 + c];

    if (tid < 128) sMax[tid] = 0u;
    __syncthreads();

    // pass 1: per-row max of s over this thread's 8 cols
    float sreg[8][8];
#pragma unroll
    for (int i = 0; i < 8; ++i) {
        int m = (i < 4) ? (ty * 4 + i) : (64 + ty * 4 + (i - 4));
        float lmax = -3.0e38f;
#pragma unroll
        for (int jp = 0; jp < 4; ++jp) {
            float d0, d1;
            unpack2(d0, d1, acc2[i][jp]);
            float s0 = (2.0f * d0 - csq[2 * jp])     * 10.0f;
            float s1 = (2.0f * d1 - csq[2 * jp + 1]) * 10.0f;
            sreg[i][2 * jp] = s0;
            sreg[i][2 * jp + 1] = s1;
            lmax = fmaxf(lmax, fmaxf(s0, s1));
        }
        atomicMax(&sMax[m], fmap(lmax));
    }
    __syncthreads();

    const float win = g_window;
#pragma unroll
    for (int q = 0; q < 4; ++q) {
        const int mL = ty * 4 + q;
        const float tauL = unfmap(sMax[mL]) - win;
        const float tauH = unfmap(sMax[64 + mL]) - win;
        const unsigned btL = (unsigned)(r0 + mL);
#pragma unroll
        for (int c = 0; c < 8; ++c) {
            float sL = sreg[q][c];
            float sH = sreg[q + 4][c];
            if (sL >= tauL || sH >= tauH) {
                unsigned k = (unsigned)(k0 + ((c < 4) ? (tx * 4 + c)
                                                      : (64 + tx * 4 + (c - 4))));
                unsigned n = btL * 1024u + k;
                unsigned bb0, bb1;
                tf2x32(fk0, fk1, n, n + HALF_N, bb0, bb1);
                unsigned long long low = (unsigned long long)(~k);
                if (sL >= tauL) {
                    float sc = sL + gumbel_from_bits(bb0);
                    atomicMax(&g_best[btL],
                              ((unsigned long long)fmap(sc) << 32) | low);
                }
                if (sH >= tauH) {
                    float sc = sH + gumbel_from_bits(bb1);
                    atomicMax(&g_best[8192u + btL],
                              ((unsigned long long)fmap(sc) << 32) | low);
                }
            }
        }
    }
}

// ---------------- VQ update ----------------
__global__ void vq_update(const float* __restrict__ cb, int stage) {
    int bt = blockIdx.x;
    int tid = threadIdx.x;  // 128
    unsigned kinv = (unsigned)(g_best[bt] & 0xffffffffull);
    int k = (int)(~kinv);
    float local = 0.0f;
#pragma unroll
    for (int ll = 0; ll < 4; ++ll) {
        int d = tid + 128 * ll;
        float r = g_res[(size_t)bt * DD + d];
        float q = cb[(size_t)k * DD + d];
        float diff = q - r;
        float qst = r + diff;
        float qo = (stage == 0) ? qst : (g_qout[(size_t)bt * DD + d] + qst);
        g_qout[(size_t)bt * DD + d] = qo;
        g_res[(size_t)bt * DD + d] = r - q;
        local += diff * diff;
    }
    __shared__ float red[128];
    red[tid] = local;
    __syncthreads();
    if (tid == 0) g_best[bt] = 0ull;   // reset for next stage (all reads done)
    for (int s = 64; s > 0; s >>= 1) {
        if (tid < s) red[tid] += red[tid + s];
        __syncthreads();
    }
    if (tid == 0) atomicAdd(&g_acc[0], red[0]);
}

// ---------------- init ----------------
__global__ void vq_init(const float* __restrict__ cb) {
    int k = blockIdx.x;
    int tid = threadIdx.x;  // 128
    float local = 0.0f;
#pragma unroll
    for (int ll = 0; ll < 4; ++ll) {
        float c = cb[(size_t)k * DD + tid + 128 * ll];
        local += c * c;
    }
    __shared__ float red[128];
    red[tid] = local;
    __syncthreads();
    for (int s = 64; s > 0; s >>= 1) {
        if (tid < s) red[tid] += red[tid + s];
        __syncthreads();
    }
    if (tid == 0) g_csq[k] = red[0];
    if (tid < 16) g_best[blockIdx.x * 16 + tid] = 0ull;
    if (blockIdx.x == 0 && tid < 2) g_acc[tid] = 0.0f;
    if (blockIdx.x == 0 && tid == 0) {
        // self-calibrated gumbel window on THIS hardware's __logf (+0.5 margin)
        float ghi = gumbel_from_bits(0xFFFFFFFFu);
        float glo = gumbel_from_bits(0u);
        g_window = (ghi - glo) + 0.5f;
    }
}

__global__ void finalize_k(float* __restrict__ out) {
    out[0] = g_acc[1] * (1.0f / 1638400.0f)      // mse /(BT*100)
           + g_acc[0] * (1.0f / 67108864.0f);    // commit /(8*BT*512)
}

// ---------------- host launcher (graph-capturable, alloc-free) -------------
extern "C" void kernel_launch(void* const* d_in, const int* in_sizes, int n_in,
                              void* d_out, int out_size) {
    const float* x   = (const float*)d_in[0];
    const float* ew1 = (const float*)d_in[1];
    const float* eb1 = (const float*)d_in[2];
    const float* ew2 = (const float*)d_in[3];
    const float* eb2 = (const float*)d_in[4];
    const float* cb  = (const float*)d_in[5];
    const float* dw1 = (const float*)d_in[6];
    const float* db1 = (const float*)d_in[7];
    const float* dw2 = (const float*)d_in[8];
    const float* db2 = (const float*)d_in[9];
    float* out = (float*)d_out;

    float *h1, *res, *qout;
    cudaGetSymbolAddress((void**)&h1,   g_h1);
    cudaGetSymbolAddress((void**)&res,  g_res);
    cudaGetSymbolAddress((void**)&qout, g_qout);

    // fold-in keys for each VQ stage: threefry((0,42),(0,i))
    unsigned fk0[8], fk1[8];
    for (int s = 0; s < 8; ++s) tf2x32(0u, 42u, 0u, (unsigned)s, fk0[s], fk1[s]);

    vq_init<<<KK, 128>>>(cb);
    transpose_cb<<<dim3(KK / 32, DD / 32), dim3(32, 8)>>>(cb);

    // encoder
    conv3<100, 256, false><<<dim3(128, 2), 256>>>(x,  ew1, eb1, h1,  nullptr);
    conv3<256, 512, false><<<dim3(128, 4), 256>>>(h1, ew2, eb2, res, nullptr);

    // residual VQ, 8 stages  (grid.x = 128: 64 low rows/block + partner rows)
    for (int s = 0; s < 8; ++s) {
        vq_score<<<dim3(128, 8), 256>>>(fk0[s], fk1[s]);
        vq_update<<<BT, 128>>>(cb, s);
    }

    // decoder (+ fused MSE on the last conv)
    conv3<512, 256, false><<<dim3(128, 2), 256>>>(qout, dw1, db1, h1, nullptr);
    conv3<256, 100, true ><<<dim3(128, 1), 256>>>(h1,  dw2, db2, nullptr, x);

    finalize_k<<<1, 1>>>(out);
}

// round 7
// speedup vs baseline: 1.1596x; 1.1068x over previous
#include <cuda_runtime.h>
#include <cstdint>

#define TT 2048
#define BT 16384
#define DD 512
#define KK 1024
#define HALF_N 8388608u   // BT*KK/2

// ---------------- scratch (static device allocations only) ----------------
__device__ float g_h1[BT * 256];
__device__ float g_res[BT * DD];
__device__ float g_qout[BT * DD];
__device__ float g_cbT[DD * KK];          // codebook transposed [d][k]
__device__ unsigned long long g_best[BT];
__device__ float g_csq[KK];
__device__ float g_window;                // gumbel hi-lo window + margin
__device__ float g_acc[2];   // [0]=commit sum, [1]=mse sum

// ---------------- packed f32x2 helpers ----------------
__device__ __forceinline__ void splat2(unsigned long long& d, float a) {
    asm("mov.b64 %0, {%1, %1};" : "=l"(d) : "f"(a));
}
__device__ __forceinline__ void pack2(unsigned long long& d, float a, float b) {
    asm("mov.b64 %0, {%1, %2};" : "=l"(d) : "f"(a), "f"(b));
}
__device__ __forceinline__ void unpack2(float& a, float& b, unsigned long long d) {
    asm("mov.b64 {%0, %1}, %2;" : "=f"(a), "=f"(b) : "l"(d));
}
__device__ __forceinline__ void ffma2(unsigned long long& acc,
                                      unsigned long long a, unsigned long long b) {
    asm("fma.rn.f32x2 %0, %1, %2, %0;" : "+l"(acc) : "l"(a), "l"(b));
}

// ---------------- JAX threefry2x32 (exact) ----------------
__host__ __device__ inline void tf2x32(unsigned k0, unsigned k1,
                                       unsigned x0, unsigned x1,
                                       unsigned& o0, unsigned& o1) {
    unsigned ks2 = k0 ^ k1 ^ 0x1BD11BDAu;
    x0 += k0; x1 += k1;
#define TF_RND(r) { x0 += x1; x1 = (x1 << (r)) | (x1 >> (32 - (r))); x1 ^= x0; }
    TF_RND(13) TF_RND(15) TF_RND(26) TF_RND(6)
    x0 += k1;  x1 += ks2 + 1u;
    TF_RND(17) TF_RND(29) TF_RND(16) TF_RND(24)
    x0 += ks2; x1 += k0 + 2u;
    TF_RND(13) TF_RND(15) TF_RND(26) TF_RND(6)
    x0 += k0;  x1 += k1 + 3u;
    TF_RND(17) TF_RND(29) TF_RND(16) TF_RND(24)
    x0 += k1;  x1 += ks2 + 4u;
    TF_RND(13) TF_RND(15) TF_RND(26) TF_RND(6)
    x0 += ks2; x1 += k0 + 5u;
#undef TF_RND
    o0 = x0; o1 = x1;
}

__device__ inline float gumbel_from_bits(unsigned bits) {
    float f = __uint_as_float((bits >> 9) | 0x3f800000u) - 1.0f;
    float u = (f == 0.0f) ? 1.17549435e-38f : f;
    return -__logf(-__logf(u));
}

__device__ inline unsigned fmap(float f) {   // monotone float -> uint
    unsigned u = __float_as_uint(f);
    return (u & 0x80000000u) ? ~u : (u | 0x80000000u);
}
__device__ inline float unfmap(unsigned u) {
    unsigned v = (u & 0x80000000u) ? (u ^ 0x80000000u) : ~u;
    return __uint_as_float(v);
}

__device__ inline float gelu_exact(float v) {
    return 0.5f * v * (1.0f + erff(v * 0.7071067811865476f));
}

// ---------------- codebook transpose: cbT[d][k] = cb[k][d] ----------------
__global__ void transpose_cb(const float* __restrict__ cb) {
    __shared__ float t[32][33];
    int k0 = blockIdx.x * 32;
    int d0 = blockIdx.y * 32;
    int tx = threadIdx.x, ty = threadIdx.y;  // 32 x 8
    for (int l = 0; l < 32; l += 8)
        t[ty + l][tx] = cb[(k0 + ty + l) * DD + d0 + tx];
    __syncthreads();
    for (int l = 0; l < 32; l += 8)
        g_cbT[(d0 + ty + l) * KK + k0 + tx] = t[tx][ty + l];
}

// ---------------- conv3 (round-2 proven version, untouched) ----------------
template<int CIN, int COUT, bool FUSE_MSE>
__global__ void __launch_bounds__(256) conv3(
    const float* __restrict__ in, const float* __restrict__ w,
    const float* __restrict__ bias, float* __restrict__ out,
    const float* __restrict__ xref)
{
    __shared__ float As[16][129];
    __shared__ float Bs[16][129];
    const int tid = threadIdx.x;
    const int tx = tid & 15, ty = tid >> 4;
    const int r0 = blockIdx.x * 128;
    const int n0 = blockIdx.y * 128;
    const int lk = tid & 15, lm = tid >> 4;

    unsigned long long acc2[8][4];
#pragma unroll
    for (int i = 0; i < 8; ++i)
#pragma unroll
        for (int j = 0; j < 4; ++j) acc2[i][j] = 0ull;

    for (int tap = 0; tap < 3; ++tap) {
        for (int cc = 0; cc < CIN; cc += 16) {
#pragma unroll
            for (int l = 0; l < 8; ++l) {
                int m = lm + 16 * l;
                int r = r0 + m;
                int t = r & (TT - 1);
                int st = t + tap - 1;
                int ci = cc + lk;
                float v = 0.0f;
                if (st >= 0 && st < TT && ci < CIN)
                    v = in[(size_t)(r + tap - 1) * CIN + ci];
                As[lk][m] = v;
            }
#pragma unroll
            for (int l = 0; l < 8; ++l) {
                int n = lm + 16 * l;
                int co = n0 + n;
                int ci = cc + lk;
                float v = 0.0f;
                if (co < COUT && ci < CIN)
                    v = w[((size_t)co * CIN + ci) * 3 + tap];
                Bs[lk][n] = v;
            }
            __syncthreads();
#pragma unroll
            for (int kk = 0; kk < 16; ++kk) {
                float a[8], b[8];
#pragma unroll
                for (int i = 0; i < 8; ++i) a[i] = As[kk][ty + 16 * i];
#pragma unroll
                for (int j = 0; j < 8; ++j) b[j] = Bs[kk][tx + 16 * j];
                unsigned long long b2[4], a2;
#pragma unroll
                for (int j = 0; j < 4; ++j) pack2(b2[j], b[2 * j], b[2 * j + 1]);
#pragma unroll
                for (int i = 0; i < 8; ++i) {
                    splat2(a2, a[i]);
#pragma unroll
                    for (int j = 0; j < 4; ++j) ffma2(acc2[i][j], a2, b2[j]);
                }
            }
            __syncthreads();
        }
    }

    float local = 0.0f;
#pragma unroll
    for (int i = 0; i < 8; ++i) {
        int r = r0 + ty + 16 * i;
#pragma unroll
        for (int jp = 0; jp < 4; ++jp) {
            float v0, v1;
            unpack2(v0, v1, acc2[i][jp]);
            float vv[2] = {v0, v1};
#pragma unroll
            for (int h = 0; h < 2; ++h) {
                int j = 2 * jp + h;
                int co = n0 + tx + 16 * j;
                if (co < COUT) {
                    float v = gelu_exact(vv[h] + bias[co]);
                    if (FUSE_MSE) {
                        float d = xref[(size_t)r * COUT + co] - v;
                        local += d * d;
                    } else {
                        out[(size_t)r * COUT + co] = v;
                    }
                }
            }
        }
    }
    if (FUSE_MSE) {
        __shared__ float red[256];
        red[tid] = local;
        __syncthreads();
        for (int s = 128; s > 0; s >>= 1) {
            if (tid < s) red[tid] += red[tid + s];
            __syncthreads();
        }
        if (tid == 0) atomicAdd(&g_acc[1], red[0]);
    }
}

// ---------------- VQ score (round-2 GEMM) + windowed-filter epilogue ------
// Block tile: rows = 64 low-half bt [r0,r0+64) at m=0..63 + partners
// [8192+r0,...) at m=64..127.  Cols = 128 codes [k0,k0+128).
// Thread (tx,ty): rows ty*4+{0..3} (low) & 64+ty*4+{0..3} (high),
//                 cols tx*4+{0..3} & 64+tx*4+{0..3}.  grid.x MUST be 128.
#define SAS 136   // smem row stride in floats
__global__ void __launch_bounds__(256) vq_score(unsigned fk0, unsigned fk1)
{
    __shared__ __align__(16) float As[16][SAS];
    __shared__ __align__(16) float Bs[16][SAS];
    __shared__ unsigned sMax[128];
    const int tid = threadIdx.x;
    const int tx = tid & 15, ty = tid >> 4;
    const int r0 = blockIdx.x * 64;
    const int k0 = blockIdx.y * 128;

    if (tid < 128) sMax[tid] = 0u;

    // staging maps (round-2 exact)
    const int sm  = tid >> 1;            // A: row m 0..127
    const int skq = tid & 1;             // A: k-chunk (8 k's each)
    const int arow = (sm < 64) ? (r0 + sm) : (8192 + r0 + (sm - 64));
    const float* aptr = &g_res[(size_t)arow * DD];
    const int bk  = tid >> 4;            // B: k row 0..15
    const int bn4 = (tid & 15) * 4;      // B: n offset

    unsigned long long acc2[8][4];
#pragma unroll
    for (int i = 0; i < 8; ++i)
#pragma unroll
        for (int j = 0; j < 4; ++j) acc2[i][j] = 0ull;

    for (int cc = 0; cc < DD; cc += 16) {
        float4 av0 = *(const float4*)(aptr + cc + 8 * skq);
        float4 av1 = *(const float4*)(aptr + cc + 8 * skq + 4);
        As[8 * skq + 0][sm] = av0.x;
        As[8 * skq + 1][sm] = av0.y;
        As[8 * skq + 2][sm] = av0.z;
        As[8 * skq + 3][sm] = av0.w;
        As[8 * skq + 4][sm] = av1.x;
        As[8 * skq + 5][sm] = av1.y;
        As[8 * skq + 6][sm] = av1.z;
        As[8 * skq + 7][sm] = av1.w;
        const float* bptr = &g_cbT[(size_t)(cc + bk) * KK + k0];
        *(float4*)&Bs[bk][bn4]      = *(const float4*)(bptr + bn4);
        *(float4*)&Bs[bk][64 + bn4] = *(const float4*)(bptr + 64 + bn4);
        __syncthreads();
#pragma unroll
        for (int kk = 0; kk < 16; ++kk) {
            float4 aL = *(const float4*)&As[kk][ty * 4];
            float4 aH = *(const float4*)&As[kk][64 + ty * 4];
            float4 bL = *(const float4*)&Bs[kk][tx * 4];
            float4 bH = *(const float4*)&Bs[kk][64 + tx * 4];
            unsigned long long b2[4], a2;
            pack2(b2[0], bL.x, bL.y);
            pack2(b2[1], bL.z, bL.w);
            pack2(b2[2], bH.x, bH.y);
            pack2(b2[3], bH.z, bH.w);
            float ar[8] = {aL.x, aL.y, aL.z, aL.w, aH.x, aH.y, aH.z, aH.w};
#pragma unroll
            for (int i = 0; i < 8; ++i) {
                splat2(a2, ar[i]);
#pragma unroll
                for (int j = 0; j < 4; ++j) ffma2(acc2[i][j], a2, b2[j]);
            }
        }
        __syncthreads();
    }

    // ---- epilogue pass 1: per-row tile maxes (recompute s, no caching) ----
    float csq[8];
#pragma unroll
    for (int h = 0; h < 2; ++h)
#pragma unroll
        for (int c = 0; c < 4; ++c)
            csq[4 * h + c] = g_csq[k0 + 64 * h + tx * 4 + c];

#pragma unroll
    for (int i = 0; i < 8; ++i) {
        int m = (i < 4) ? (ty * 4 + i) : (64 + ty * 4 + (i - 4));
        float lmax = -3.0e38f;
#pragma unroll
        for (int jp = 0; jp < 4; ++jp) {
            float d0, d1;
            unpack2(d0, d1, acc2[i][jp]);
            lmax = fmaxf(lmax, fmaxf(
                fmaf(20.0f, d0, -10.0f * csq[2 * jp]),
                fmaf(20.0f, d1, -10.0f * csq[2 * jp + 1])));
        }
        atomicMax(&sMax[m], fmap(lmax));
    }
    __syncthreads();

    // ---- pass 2: threefry only for windowed survivors ----
    const float win = g_window;
#pragma unroll
    for (int q = 0; q < 4; ++q) {
        const int mL = ty * 4 + q;
        const float tauL = unfmap(sMax[mL]) - win;
        const float tauH = unfmap(sMax[64 + mL]) - win;
        const unsigned btL = (unsigned)(r0 + mL);
#pragma unroll
        for (int jp = 0; jp < 4; ++jp) {
            float dL0, dL1, dH0, dH1;
            unpack2(dL0, dL1, acc2[q][jp]);
            unpack2(dH0, dH1, acc2[q + 4][jp]);
#pragma unroll
            for (int h = 0; h < 2; ++h) {
                const int c = 2 * jp + h;
                const float sL = fmaf(20.0f, h ? dL1 : dL0, -10.0f * csq[c]);
                const float sH = fmaf(20.0f, h ? dH1 : dH0, -10.0f * csq[c]);
                if (sL >= tauL || sH >= tauH) {
                    unsigned k = (unsigned)(k0 + ((c < 4) ? (tx * 4 + c)
                                                          : (64 + tx * 4 + (c - 4))));
                    unsigned n = btL * 1024u + k;
                    unsigned bb0, bb1;
                    tf2x32(fk0, fk1, n, n + HALF_N, bb0, bb1);
                    unsigned long long low = (unsigned long long)(~k);
                    if (sL >= tauL) {
                        float sc = sL + gumbel_from_bits(bb0);
                        atomicMax(&g_best[btL],
                                  ((unsigned long long)fmap(sc) << 32) | low);
                    }
                    if (sH >= tauH) {
                        float sc = sH + gumbel_from_bits(bb1);
                        atomicMax(&g_best[8192u + btL],
                                  ((unsigned long long)fmap(sc) << 32) | low);
                    }
                }
            }
        }
    }
}

// ---------------- VQ update ----------------
__global__ void vq_update(const float* __restrict__ cb, int stage) {
    int bt = blockIdx.x;
    int tid = threadIdx.x;  // 128
    unsigned kinv = (unsigned)(g_best[bt] & 0xffffffffull);
    int k = (int)(~kinv);
    float local = 0.0f;
#pragma unroll
    for (int ll = 0; ll < 4; ++ll) {
        int d = tid + 128 * ll;
        float r = g_res[(size_t)bt * DD + d];
        float q = cb[(size_t)k * DD + d];
        float diff = q - r;
        float qst = r + diff;
        float qo = (stage == 0) ? qst : (g_qout[(size_t)bt * DD + d] + qst);
        g_qout[(size_t)bt * DD + d] = qo;
        g_res[(size_t)bt * DD + d] = r - q;
        local += diff * diff;
    }
    __shared__ float red[128];
    red[tid] = local;
    __syncthreads();
    if (tid == 0) g_best[bt] = 0ull;   // reset for next stage (all reads done)
    for (int s = 64; s > 0; s >>= 1) {
        if (tid < s) red[tid] += red[tid + s];
        __syncthreads();
    }
    if (tid == 0) atomicAdd(&g_acc[0], red[0]);
}

// ---------------- init ----------------
__global__ void vq_init(const float* __restrict__ cb) {
    int k = blockIdx.x;
    int tid = threadIdx.x;  // 128
    float local = 0.0f;
#pragma unroll
    for (int ll = 0; ll < 4; ++ll) {
        float c = cb[(size_t)k * DD + tid + 128 * ll];
        local += c * c;
    }
    __shared__ float red[128];
    red[tid] = local;
    __syncthreads();
    for (int s = 64; s > 0; s >>= 1) {
        if (tid < s) red[tid] += red[tid + s];
        __syncthreads();
    }
    if (tid == 0) g_csq[k] = red[0];
    if (tid < 16) g_best[blockIdx.x * 16 + tid] = 0ull;
    if (blockIdx.x == 0 && tid < 2) g_acc[tid] = 0.0f;
    if (blockIdx.x == 0 && tid == 0) {
        // self-calibrated gumbel window on THIS hardware's __logf (+0.5 margin)
        float ghi = gumbel_from_bits(0xFFFFFFFFu);
        float glo = gumbel_from_bits(0u);
        g_window = (ghi - glo) + 0.5f;
    }
}

__global__ void finalize_k(float* __restrict__ out) {
    out[0] = g_acc[1] * (1.0f / 1638400.0f)      // mse /(BT*100)
           + g_acc[0] * (1.0f / 67108864.0f);    // commit /(8*BT*512)
}

// ---------------- host launcher (graph-capturable, alloc-free) -------------
extern "C" void kernel_launch(void* const* d_in, const int* in_sizes, int n_in,
                              void* d_out, int out_size) {
    const float* x   = (const float*)d_in[0];
    const float* ew1 = (const float*)d_in[1];
    const float* eb1 = (const float*)d_in[2];
    const float* ew2 = (const float*)d_in[3];
    const float* eb2 = (const float*)d_in[4];
    const float* cb  = (const float*)d_in[5];
    const float* dw1 = (const float*)d_in[6];
    const float* db1 = (const float*)d_in[7];
    const float* dw2 = (const float*)d_in[8];
    const float* db2 = (const float*)d_in[9];
    float* out = (float*)d_out;

    float *h1, *res, *qout;
    cudaGetSymbolAddress((void**)&h1,   g_h1);
    cudaGetSymbolAddress((void**)&res,  g_res);
    cudaGetSymbolAddress((void**)&qout, g_qout);

    // fold-in keys for each VQ stage: threefry((0,42),(0,i))
    unsigned fk0[8], fk1[8];
    for (int s = 0; s < 8; ++s) tf2x32(0u, 42u, 0u, (unsigned)s, fk0[s], fk1[s]);

    vq_init<<<KK, 128>>>(cb);
    transpose_cb<<<dim3(KK / 32, DD / 32), dim3(32, 8)>>>(cb);

    // encoder
    conv3<100, 256, false><<<dim3(128, 2), 256>>>(x,  ew1, eb1, h1,  nullptr);
    conv3<256, 512, false><<<dim3(128, 4), 256>>>(h1, ew2, eb2, res, nullptr);

    // residual VQ, 8 stages  (grid.x = 128: 64 low rows/block + partner rows)
    for (int s = 0; s < 8; ++s) {
        vq_score<<<dim3(128, 8), 256>>>(fk0[s], fk1[s]);
        vq_update<<<BT, 128>>>(cb, s);
    }

    // decoder (+ fused MSE on the last conv)
    conv3<512, 256, false><<<dim3(128, 2), 256>>>(qout, dw1, db1, h1, nullptr);
    conv3<256, 100, true ><<<dim3(128, 1), 256>>>(h1,  dw2, db2, nullptr, x);

    finalize_k<<<1, 1>>>(out);
}

// round 8
// speedup vs baseline: 1.1735x; 1.0120x over previous
#include <cuda_runtime.h>
#include <cstdint>

#define TT 2048
#define BT 16384
#define DD 512
#define KK 1024
#define HALF_N 8388608u   // BT*KK/2

// ---------------- scratch (static device allocations only) ----------------
__device__ float g_h1[BT * 256];
__device__ float g_res[BT * DD];
__device__ float g_qout[BT * DD];
__device__ float g_cbT[DD * KK];          // codebook transposed [d][k]
__device__ unsigned long long g_best[BT];
__device__ float g_csq[KK];
__device__ float g_window;                // gumbel hi-lo window + margin
__device__ float g_acc[2];   // [0]=commit sum, [1]=mse sum

// ---------------- packed f32x2 helpers ----------------
__device__ __forceinline__ void splat2(unsigned long long& d, float a) {
    asm("mov.b64 %0, {%1, %1};" : "=l"(d) : "f"(a));
}
__device__ __forceinline__ void pack2(unsigned long long& d, float a, float b) {
    asm("mov.b64 %0, {%1, %2};" : "=l"(d) : "f"(a), "f"(b));
}
__device__ __forceinline__ void unpack2(float& a, float& b, unsigned long long d) {
    asm("mov.b64 {%0, %1}, %2;" : "=f"(a), "=f"(b) : "l"(d));
}
__device__ __forceinline__ void ffma2(unsigned long long& acc,
                                      unsigned long long a, unsigned long long b) {
    asm("fma.rn.f32x2 %0, %1, %2, %0;" : "+l"(acc) : "l"(a), "l"(b));
}

// ---------------- JAX threefry2x32 (exact) ----------------
__host__ __device__ inline void tf2x32(unsigned k0, unsigned k1,
                                       unsigned x0, unsigned x1,
                                       unsigned& o0, unsigned& o1) {
    unsigned ks2 = k0 ^ k1 ^ 0x1BD11BDAu;
    x0 += k0; x1 += k1;
#define TF_RND(r) { x0 += x1; x1 = (x1 << (r)) | (x1 >> (32 - (r))); x1 ^= x0; }
    TF_RND(13) TF_RND(15) TF_RND(26) TF_RND(6)
    x0 += k1;  x1 += ks2 + 1u;
    TF_RND(17) TF_RND(29) TF_RND(16) TF_RND(24)
    x0 += ks2; x1 += k0 + 2u;
    TF_RND(13) TF_RND(15) TF_RND(26) TF_RND(6)
    x0 += k0;  x1 += k1 + 3u;
    TF_RND(17) TF_RND(29) TF_RND(16) TF_RND(24)
    x0 += k1;  x1 += ks2 + 4u;
    TF_RND(13) TF_RND(15) TF_RND(26) TF_RND(6)
    x0 += ks2; x1 += k0 + 5u;
#undef TF_RND
    o0 = x0; o1 = x1;
}

__device__ inline float gumbel_from_bits(unsigned bits) {
    float f = __uint_as_float((bits >> 9) | 0x3f800000u) - 1.0f;
    float u = (f == 0.0f) ? 1.17549435e-38f : f;
    return -__logf(-__logf(u));
}

__device__ inline unsigned fmap(float f) {   // monotone float -> uint
    unsigned u = __float_as_uint(f);
    return (u & 0x80000000u) ? ~u : (u | 0x80000000u);
}
__device__ inline float unfmap(unsigned u) {
    unsigned v = (u & 0x80000000u) ? (u ^ 0x80000000u) : ~u;
    return __uint_as_float(v);
}

__device__ inline float gelu_exact(float v) {
    return 0.5f * v * (1.0f + erff(v * 0.7071067811865476f));
}

// ---------------- codebook transpose: cbT[d][k] = cb[k][d] ----------------
__global__ void transpose_cb(const float* __restrict__ cb) {
    __shared__ float t[32][33];
    int k0 = blockIdx.x * 32;
    int d0 = blockIdx.y * 32;
    int tx = threadIdx.x, ty = threadIdx.y;  // 32 x 8
    for (int l = 0; l < 32; l += 8)
        t[ty + l][tx] = cb[(k0 + ty + l) * DD + d0 + tx];
    __syncthreads();
    for (int l = 0; l < 32; l += 8)
        g_cbT[(d0 + ty + l) * KK + k0 + tx] = t[tx][ty + l];
}

// ---------------- conv3: round-2 compute, 2-stage software pipeline --------
template<int CIN, int COUT, bool FUSE_MSE>
__global__ void __launch_bounds__(256, 2) conv3(
    const float* __restrict__ in, const float* __restrict__ w,
    const float* __restrict__ bias, float* __restrict__ out,
    const float* __restrict__ xref)
{
    __shared__ float As[2][16][129];
    __shared__ float Bs[2][16][129];
    constexpr int NC = (CIN + 15) / 16;
    constexpr int NS = 3 * NC;
    const int tid = threadIdx.x;
    const int tx = tid & 15, ty = tid >> 4;
    const int r0 = blockIdx.x * 128;
    const int n0 = blockIdx.y * 128;
    const int lk = tid & 15, lm = tid >> 4;

    unsigned long long acc2[8][4];
#pragma unroll
    for (int i = 0; i < 8; ++i)
#pragma unroll
        for (int j = 0; j < 4; ++j) acc2[i][j] = 0ull;

    float ar[8], br[8];

    auto LOAD = [&](int s) {
        const int tap = s / NC;
        const int cc = (s - tap * NC) * 16;
        const int ci = cc + lk;
#pragma unroll
        for (int l = 0; l < 8; ++l) {
            int m = lm + 16 * l;
            int r = r0 + m;
            int t = r & (TT - 1);
            int st = t + tap - 1;
            float v = 0.0f;
            if (st >= 0 && st < TT && ci < CIN)
                v = in[(size_t)(r + tap - 1) * CIN + ci];
            ar[l] = v;
        }
#pragma unroll
        for (int l = 0; l < 8; ++l) {
            int co = n0 + lm + 16 * l;
            float v = 0.0f;
            if (co < COUT && ci < CIN)
                v = w[((size_t)co * CIN + ci) * 3 + tap];
            br[l] = v;
        }
    };
    auto STORE = [&](int p) {
#pragma unroll
        for (int l = 0; l < 8; ++l) As[p][lk][lm + 16 * l] = ar[l];
#pragma unroll
        for (int l = 0; l < 8; ++l) Bs[p][lk][lm + 16 * l] = br[l];
    };

    LOAD(0); STORE(0);
    if (NS > 1) LOAD(1);
    __syncthreads();

    for (int s = 0; s < NS; ++s) {
        const int p = s & 1;
        if (s + 1 < NS) STORE(p ^ 1);
        if (s + 2 < NS) LOAD(s + 2);
#pragma unroll
        for (int kk = 0; kk < 16; ++kk) {
            float a[8], b[8];
#pragma unroll
            for (int i = 0; i < 8; ++i) a[i] = As[p][kk][ty + 16 * i];
#pragma unroll
            for (int j = 0; j < 8; ++j) b[j] = Bs[p][kk][tx + 16 * j];
            unsigned long long b2[4], a2;
#pragma unroll
            for (int j = 0; j < 4; ++j) pack2(b2[j], b[2 * j], b[2 * j + 1]);
#pragma unroll
            for (int i = 0; i < 8; ++i) {
                splat2(a2, a[i]);
#pragma unroll
                for (int j = 0; j < 4; ++j) ffma2(acc2[i][j], a2, b2[j]);
            }
        }
        __syncthreads();
    }

    float local = 0.0f;
#pragma unroll
    for (int i = 0; i < 8; ++i) {
        int r = r0 + ty + 16 * i;
#pragma unroll
        for (int jp = 0; jp < 4; ++jp) {
            float v0, v1;
            unpack2(v0, v1, acc2[i][jp]);
            float vv[2] = {v0, v1};
#pragma unroll
            for (int h = 0; h < 2; ++h) {
                int j = 2 * jp + h;
                int co = n0 + tx + 16 * j;
                if (co < COUT) {
                    float v = gelu_exact(vv[h] + bias[co]);
                    if (FUSE_MSE) {
                        float d = xref[(size_t)r * COUT + co] - v;
                        local += d * d;
                    } else {
                        out[(size_t)r * COUT + co] = v;
                    }
                }
            }
        }
    }
    if (FUSE_MSE) {
        __shared__ float red[256];
        red[tid] = local;
        __syncthreads();
        for (int s = 128; s > 0; s >>= 1) {
            if (tid < s) red[tid] += red[tid + s];
            __syncthreads();
        }
        if (tid == 0) atomicAdd(&g_acc[1], red[0]);
    }
}

// ---------------- VQ score: pipelined GEMM + windowed-filter epilogue ------
// Tile: rows m<64 -> bt=r0+m ; m>=64 -> bt=8192+r0+(m-64). Cols [k0,k0+128).
// grid.x MUST be 128.
#define SAS 136
__global__ void __launch_bounds__(256, 2) vq_score(unsigned fk0, unsigned fk1)
{
    __shared__ __align__(16) float As[2][16][SAS];
    __shared__ __align__(16) float Bs[2][16][SAS];
    __shared__ unsigned sMax[128];
    const int tid = threadIdx.x;
    const int tx = tid & 15, ty = tid >> 4;
    const int r0 = blockIdx.x * 64;
    const int k0 = blockIdx.y * 128;

    if (tid < 128) sMax[tid] = 0u;

    // staging maps (round-2 exact)
    const int sm  = tid >> 1;
    const int skq = tid & 1;
    const int arow = (sm < 64) ? (r0 + sm) : (8192 + r0 + (sm - 64));
    const float* aptr = &g_res[(size_t)arow * DD + 8 * skq];
    const int bk  = tid >> 4;
    const int bn4 = (tid & 15) * 4;
    const float* bbase = &g_cbT[(size_t)bk * KK + k0];

    unsigned long long acc2[8][4];
#pragma unroll
    for (int i = 0; i < 8; ++i)
#pragma unroll
        for (int j = 0; j < 4; ++j) acc2[i][j] = 0ull;

    float4 av0, av1, bv0, bv1;

    auto LOAD = [&](int cc) {
        av0 = *(const float4*)(aptr + cc);
        av1 = *(const float4*)(aptr + cc + 4);
        const float* bp = bbase + (size_t)cc * KK;
        bv0 = *(const float4*)(bp + bn4);
        bv1 = *(const float4*)(bp + 64 + bn4);
    };
    auto STORE = [&](int p) {
        As[p][8 * skq + 0][sm] = av0.x;
        As[p][8 * skq + 1][sm] = av0.y;
        As[p][8 * skq + 2][sm] = av0.z;
        As[p][8 * skq + 3][sm] = av0.w;
        As[p][8 * skq + 4][sm] = av1.x;
        As[p][8 * skq + 5][sm] = av1.y;
        As[p][8 * skq + 6][sm] = av1.z;
        As[p][8 * skq + 7][sm] = av1.w;
        *(float4*)&Bs[p][bk][bn4]      = bv0;
        *(float4*)&Bs[p][bk][64 + bn4] = bv1;
    };

    LOAD(0); STORE(0);
    LOAD(16);
    __syncthreads();

    for (int ch = 0; ch < 32; ++ch) {
        const int p = ch & 1;
        if (ch + 1 < 32) STORE(p ^ 1);
        if (ch + 2 < 32) LOAD((ch + 2) * 16);
#pragma unroll
        for (int kk = 0; kk < 16; ++kk) {
            float4 aL = *(const float4*)&As[p][kk][ty * 4];
            float4 aH = *(const float4*)&As[p][kk][64 + ty * 4];
            float4 bL = *(const float4*)&Bs[p][kk][tx * 4];
            float4 bH = *(const float4*)&Bs[p][kk][64 + tx * 4];
            unsigned long long b2[4], a2;
            pack2(b2[0], bL.x, bL.y);
            pack2(b2[1], bL.z, bL.w);
            pack2(b2[2], bH.x, bH.y);
            pack2(b2[3], bH.z, bH.w);
            float arr[8] = {aL.x, aL.y, aL.z, aL.w, aH.x, aH.y, aH.z, aH.w};
#pragma unroll
            for (int i = 0; i < 8; ++i) {
                splat2(a2, arr[i]);
#pragma unroll
                for (int j = 0; j < 4; ++j) ffma2(acc2[i][j], a2, b2[j]);
            }
        }
        __syncthreads();
    }

    // ---- epilogue pass 1: per-row tile maxes ----
    float csq[8];
#pragma unroll
    for (int h = 0; h < 2; ++h)
#pragma unroll
        for (int c = 0; c < 4; ++c)
            csq[4 * h + c] = g_csq[k0 + 64 * h + tx * 4 + c];

#pragma unroll
    for (int i = 0; i < 8; ++i) {
        int m = (i < 4) ? (ty * 4 + i) : (64 + ty * 4 + (i - 4));
        float lmax = -3.0e38f;
#pragma unroll
        for (int jp = 0; jp < 4; ++jp) {
            float d0, d1;
            unpack2(d0, d1, acc2[i][jp]);
            lmax = fmaxf(lmax, fmaxf(
                fmaf(20.0f, d0, -10.0f * csq[2 * jp]),
                fmaf(20.0f, d1, -10.0f * csq[2 * jp + 1])));
        }
        atomicMax(&sMax[m], fmap(lmax));
    }
    __syncthreads();

    // ---- pass 2: threefry only for windowed survivors ----
    const float win = g_window;
#pragma unroll
    for (int q = 0; q < 4; ++q) {
        const int mL = ty * 4 + q;
        const float tauL = unfmap(sMax[mL]) - win;
        const float tauH = unfmap(sMax[64 + mL]) - win;
        const unsigned btL = (unsigned)(r0 + mL);
#pragma unroll
        for (int jp = 0; jp < 4; ++jp) {
            float dL0, dL1, dH0, dH1;
            unpack2(dL0, dL1, acc2[q][jp]);
            unpack2(dH0, dH1, acc2[q + 4][jp]);
#pragma unroll
            for (int h = 0; h < 2; ++h) {
                const int c = 2 * jp + h;
                const float sL = fmaf(20.0f, h ? dL1 : dL0, -10.0f * csq[c]);
                const float sH = fmaf(20.0f, h ? dH1 : dH0, -10.0f * csq[c]);
                if (sL >= tauL || sH >= tauH) {
                    unsigned k = (unsigned)(k0 + ((c < 4) ? (tx * 4 + c)
                                                          : (64 + tx * 4 + (c - 4))));
                    unsigned n = btL * 1024u + k;
                    unsigned bb0, bb1;
                    tf2x32(fk0, fk1, n, n + HALF_N, bb0, bb1);
                    unsigned long long low = (unsigned long long)(~k);
                    if (sL >= tauL) {
                        float sc = sL + gumbel_from_bits(bb0);
                        atomicMax(&g_best[btL],
                                  ((unsigned long long)fmap(sc) << 32) | low);
                    }
                    if (sH >= tauH) {
                        float sc = sH + gumbel_from_bits(bb1);
                        atomicMax(&g_best[8192u + btL],
                                  ((unsigned long long)fmap(sc) << 32) | low);
                    }
                }
            }
        }
    }
}

// ---------------- VQ update ----------------
__global__ void vq_update(const float* __restrict__ cb, int stage) {
    int bt = blockIdx.x;
    int tid = threadIdx.x;  // 128
    unsigned kinv = (unsigned)(g_best[bt] & 0xffffffffull);
    int k = (int)(~kinv);
    float local = 0.0f;
#pragma unroll
    for (int ll = 0; ll < 4; ++ll) {
        int d = tid + 128 * ll;
        float r = g_res[(size_t)bt * DD + d];
        float q = cb[(size_t)k * DD + d];
        float diff = q - r;
        float qst = r + diff;
        float qo = (stage == 0) ? qst : (g_qout[(size_t)bt * DD + d] + qst);
        g_qout[(size_t)bt * DD + d] = qo;
        g_res[(size_t)bt * DD + d] = r - q;
        local += diff * diff;
    }
    __shared__ float red[128];
    red[tid] = local;
    __syncthreads();
    if (tid == 0) g_best[bt] = 0ull;   // reset for next stage (all reads done)
    for (int s = 64; s > 0; s >>= 1) {
        if (tid < s) red[tid] += red[tid + s];
        __syncthreads();
    }
    if (tid == 0) atomicAdd(&g_acc[0], red[0]);
}

// ---------------- init ----------------
__global__ void vq_init(const float* __restrict__ cb) {
    int k = blockIdx.x;
    int tid = threadIdx.x;  // 128
    float local = 0.0f;
#pragma unroll
    for (int ll = 0; ll < 4; ++ll) {
        float c = cb[(size_t)k * DD + tid + 128 * ll];
        local += c * c;
    }
    __shared__ float red[128];
    red[tid] = local;
    __syncthreads();
    for (int s = 64; s > 0; s >>= 1) {
        if (tid < s) red[tid] += red[tid + s];
        __syncthreads();
    }
    if (tid == 0) g_csq[k] = red[0];
    if (tid < 16) g_best[blockIdx.x * 16 + tid] = 0ull;
    if (blockIdx.x == 0 && tid < 2) g_acc[tid] = 0.0f;
    if (blockIdx.x == 0 && tid == 0) {
        float ghi = gumbel_from_bits(0xFFFFFFFFu);
        float glo = gumbel_from_bits(0u);
        g_window = (ghi - glo) + 0.5f;
    }
}

__global__ void finalize_k(float* __restrict__ out) {
    out[0] = g_acc[1] * (1.0f / 1638400.0f)      // mse /(BT*100)
           + g_acc[0] * (1.0f / 67108864.0f);    // commit /(8*BT*512)
}

// ---------------- host launcher (graph-capturable, alloc-free) -------------
extern "C" void kernel_launch(void* const* d_in, const int* in_sizes, int n_in,
                              void* d_out, int out_size) {
    const float* x   = (const float*)d_in[0];
    const float* ew1 = (const float*)d_in[1];
    const float* eb1 = (const float*)d_in[2];
    const float* ew2 = (const float*)d_in[3];
    const float* eb2 = (const float*)d_in[4];
    const float* cb  = (const float*)d_in[5];
    const float* dw1 = (const float*)d_in[6];
    const float* db1 = (const float*)d_in[7];
    const float* dw2 = (const float*)d_in[8];
    const float* db2 = (const float*)d_in[9];
    float* out = (float*)d_out;

    float *h1, *res, *qout;
    cudaGetSymbolAddress((void**)&h1,   g_h1);
    cudaGetSymbolAddress((void**)&res,  g_res);
    cudaGetSymbolAddress((void**)&qout, g_qout);

    // fold-in keys for each VQ stage: threefry((0,42),(0,i))
    unsigned fk0[8], fk1[8];
    for (int s = 0; s < 8; ++s) tf2x32(0u, 42u, 0u, (unsigned)s, fk0[s], fk1[s]);

    vq_init<<<KK, 128>>>(cb);
    transpose_cb<<<dim3(KK / 32, DD / 32), dim3(32, 8)>>>(cb);

    // encoder
    conv3<100, 256, false><<<dim3(128, 2), 256>>>(x,  ew1, eb1, h1,  nullptr);
    conv3<256, 512, false><<<dim3(128, 4), 256>>>(h1, ew2, eb2, res, nullptr);

    // residual VQ, 8 stages  (grid.x = 128: 64 low rows/block + partner rows)
    for (int s = 0; s < 8; ++s) {
        vq_score<<<dim3(128, 8), 256>>>(fk0[s], fk1[s]);
        vq_update<<<BT, 128>>>(cb, s);
    }

    // decoder (+ fused MSE on the last conv)
    conv3<512, 256, false><<<dim3(128, 2), 256>>>(qout, dw1, db1, h1, nullptr);
    conv3<256, 100, true ><<<dim3(128, 1), 256>>>(h1,  dw2, db2, nullptr, x);

    finalize_k<<<1, 1>>>(out);
}

// round 9
// speedup vs baseline: 3.1480x; 2.6827x over previous
#include <cuda_runtime.h>
#include <cstdint>

#define TT 2048
#define BT 16384
#define DD 512
#define KK 1024
#define HALF_N 8388608u   // BT*KK/2

// ---------------- scratch (static device allocations only) ----------------
__device__ float g_h1[BT * 256];
__device__ float g_res[BT * DD];          // encoder output z
__device__ float g_qout[BT * DD];
__device__ float g_cbT[DD * KK];          // codebook transposed [d][k]
__device__ float g_dist[BT * KK];         // dot products <z, c_k>  (64MB)
__device__ float g_G[KK * KK];            // Gram matrix cb·cbT     (4MB)
__device__ float g_rn2[BT];               // running ||residual||^2
__device__ float g_csq[KK];
__device__ unsigned g_fk[16];             // per-stage threefry fold-in keys
__device__ float g_window;                // gumbel hi-lo window + margin
__device__ float g_acc[2];   // [0]=commit sum, [1]=mse sum

// ---------------- packed f32x2 helpers ----------------
__device__ __forceinline__ void splat2(unsigned long long& d, float a) {
    asm("mov.b64 %0, {%1, %1};" : "=l"(d) : "f"(a));
}
__device__ __forceinline__ void pack2(unsigned long long& d, float a, float b) {
    asm("mov.b64 %0, {%1, %2};" : "=l"(d) : "f"(a), "f"(b));
}
__device__ __forceinline__ void unpack2(float& a, float& b, unsigned long long d) {
    asm("mov.b64 {%0, %1}, %2;" : "=f"(a), "=f"(b) : "l"(d));
}
__device__ __forceinline__ void ffma2(unsigned long long& acc,
                                      unsigned long long a, unsigned long long b) {
    asm("fma.rn.f32x2 %0, %1, %2, %0;" : "+l"(acc) : "l"(a), "l"(b));
}

// ---------------- JAX threefry2x32 (exact) ----------------
__host__ __device__ inline void tf2x32(unsigned k0, unsigned k1,
                                       unsigned x0, unsigned x1,
                                       unsigned& o0, unsigned& o1) {
    unsigned ks2 = k0 ^ k1 ^ 0x1BD11BDAu;
    x0 += k0; x1 += k1;
#define TF_RND(r) { x0 += x1; x1 = (x1 << (r)) | (x1 >> (32 - (r))); x1 ^= x0; }
    TF_RND(13) TF_RND(15) TF_RND(26) TF_RND(6)
    x0 += k1;  x1 += ks2 + 1u;
    TF_RND(17) TF_RND(29) TF_RND(16) TF_RND(24)
    x0 += ks2; x1 += k0 + 2u;
    TF_RND(13) TF_RND(15) TF_RND(26) TF_RND(6)
    x0 += k0;  x1 += k1 + 3u;
    TF_RND(17) TF_RND(29) TF_RND(16) TF_RND(24)
    x0 += k1;  x1 += ks2 + 4u;
    TF_RND(13) TF_RND(15) TF_RND(26) TF_RND(6)
    x0 += ks2; x1 += k0 + 5u;
#undef TF_RND
    o0 = x0; o1 = x1;
}

__device__ inline float gumbel_from_bits(unsigned bits) {
    float f = __uint_as_float((bits >> 9) | 0x3f800000u) - 1.0f;
    float u = (f == 0.0f) ? 1.17549435e-38f : f;
    return -__logf(-__logf(u));
}

__device__ inline unsigned fmap(float f) {   // monotone float -> uint
    unsigned u = __float_as_uint(f);
    return (u & 0x80000000u) ? ~u : (u | 0x80000000u);
}
__device__ inline float unfmap(unsigned u) {
    unsigned v = (u & 0x80000000u) ? (u ^ 0x80000000u) : ~u;
    return __uint_as_float(v);
}

__device__ inline float gelu_exact(float v) {
    return 0.5f * v * (1.0f + erff(v * 0.7071067811865476f));
}

// ---------------- codebook transpose: cbT[d][k] = cb[k][d] ----------------
__global__ void transpose_cb(const float* __restrict__ cb) {
    __shared__ float t[32][33];
    int k0 = blockIdx.x * 32;
    int d0 = blockIdx.y * 32;
    int tx = threadIdx.x, ty = threadIdx.y;  // 32 x 8
    for (int l = 0; l < 32; l += 8)
        t[ty + l][tx] = cb[(k0 + ty + l) * DD + d0 + tx];
    __syncthreads();
    for (int l = 0; l < 32; l += 8)
        g_cbT[(d0 + ty + l) * KK + k0 + tx] = t[tx][ty + l];
}

// ---------------- conv3: round-8 pipelined version (passing) --------------
template<int CIN, int COUT, bool FUSE_MSE>
__global__ void __launch_bounds__(256, 2) conv3(
    const float* __restrict__ in, const float* __restrict__ w,
    const float* __restrict__ bias, float* __restrict__ out,
    const float* __restrict__ xref)
{
    __shared__ float As[2][16][129];
    __shared__ float Bs[2][16][129];
    constexpr int NC = (CIN + 15) / 16;
    constexpr int NS = 3 * NC;
    const int tid = threadIdx.x;
    const int tx = tid & 15, ty = tid >> 4;
    const int r0 = blockIdx.x * 128;
    const int n0 = blockIdx.y * 128;
    const int lk = tid & 15, lm = tid >> 4;

    unsigned long long acc2[8][4];
#pragma unroll
    for (int i = 0; i < 8; ++i)
#pragma unroll
        for (int j = 0; j < 4; ++j) acc2[i][j] = 0ull;

    float ar[8], br[8];

    auto LOAD = [&](int s) {
        const int tap = s / NC;
        const int cc = (s - tap * NC) * 16;
        const int ci = cc + lk;
#pragma unroll
        for (int l = 0; l < 8; ++l) {
            int m = lm + 16 * l;
            int r = r0 + m;
            int t = r & (TT - 1);
            int st = t + tap - 1;
            float v = 0.0f;
            if (st >= 0 && st < TT && ci < CIN)
                v = in[(size_t)(r + tap - 1) * CIN + ci];
            ar[l] = v;
        }
#pragma unroll
        for (int l = 0; l < 8; ++l) {
            int co = n0 + lm + 16 * l;
            float v = 0.0f;
            if (co < COUT && ci < CIN)
                v = w[((size_t)co * CIN + ci) * 3 + tap];
            br[l] = v;
        }
    };
    auto STORE = [&](int p) {
#pragma unroll
        for (int l = 0; l < 8; ++l) As[p][lk][lm + 16 * l] = ar[l];
#pragma unroll
        for (int l = 0; l < 8; ++l) Bs[p][lk][lm + 16 * l] = br[l];
    };

    LOAD(0); STORE(0);
    if (NS > 1) LOAD(1);
    __syncthreads();

    for (int s = 0; s < NS; ++s) {
        const int p = s & 1;
        if (s + 1 < NS) STORE(p ^ 1);
        if (s + 2 < NS) LOAD(s + 2);
#pragma unroll
        for (int kk = 0; kk < 16; ++kk) {
            float a[8], b[8];
#pragma unroll
            for (int i = 0; i < 8; ++i) a[i] = As[p][kk][ty + 16 * i];
#pragma unroll
            for (int j = 0; j < 8; ++j) b[j] = Bs[p][kk][tx + 16 * j];
            unsigned long long b2[4], a2;
#pragma unroll
            for (int j = 0; j < 4; ++j) pack2(b2[j], b[2 * j], b[2 * j + 1]);
#pragma unroll
            for (int i = 0; i < 8; ++i) {
                splat2(a2, a[i]);
#pragma unroll
                for (int j = 0; j < 4; ++j) ffma2(acc2[i][j], a2, b2[j]);
            }
        }
        __syncthreads();
    }

    float local = 0.0f;
#pragma unroll
    for (int i = 0; i < 8; ++i) {
        int r = r0 + ty + 16 * i;
#pragma unroll
        for (int jp = 0; jp < 4; ++jp) {
            float v0, v1;
            unpack2(v0, v1, acc2[i][jp]);
            float vv[2] = {v0, v1};
#pragma unroll
            for (int h = 0; h < 2; ++h) {
                int j = 2 * jp + h;
                int co = n0 + tx + 16 * j;
                if (co < COUT) {
                    float v = gelu_exact(vv[h] + bias[co]);
                    if (FUSE_MSE) {
                        float d = xref[(size_t)r * COUT + co] - v;
                        local += d * d;
                    } else {
                        out[(size_t)r * COUT + co] = v;
                    }
                }
            }
        }
    }
    if (FUSE_MSE) {
        __shared__ float red[256];
        red[tid] = local;
        __syncthreads();
        for (int s = 128; s > 0; s >>= 1) {
            if (tid < s) red[tid] += red[tid + s];
            __syncthreads();
        }
        if (tid == 0) atomicAdd(&g_acc[1], red[0]);
    }
}

// ---------------- shared pipelined-GEMM body (A rows x cbT cols) ----------
// Computes a 128x128 tile of (Arows · cbT) into acc2; caller stores.
#define SAS 136
#define GEMM_BODY(AROW_EXPR)                                                   \
    const int sm  = tid >> 1;                                                  \
    const int skq = tid & 1;                                                   \
    const int arow = (AROW_EXPR);                                              \
    const float* aptr = Abase + (size_t)arow * DD + 8 * skq;                   \
    const int bk  = tid >> 4;                                                  \
    const int bn4 = (tid & 15) * 4;                                            \
    const float* bbase = &g_cbT[(size_t)bk * KK + k0];                         \
    unsigned long long acc2[8][4];                                             \
    _Pragma("unroll")                                                          \
    for (int i = 0; i < 8; ++i)                                                \
        _Pragma("unroll")                                                      \
        for (int j = 0; j < 4; ++j) acc2[i][j] = 0ull;                         \
    float4 av0, av1, bv0, bv1;                                                 \
    auto LOAD = [&](int cc) {                                                  \
        av0 = *(const float4*)(aptr + cc);                                     \
        av1 = *(const float4*)(aptr + cc + 4);                                 \
        const float* bp = bbase + (size_t)cc * KK;                             \
        bv0 = *(const float4*)(bp + bn4);                                      \
        bv1 = *(const float4*)(bp + 64 + bn4);                                 \
    };                                                                         \
    auto STORE = [&](int p) {                                                  \
        As[p][8 * skq + 0][sm] = av0.x;                                        \
        As[p][8 * skq + 1][sm] = av0.y;                                        \
        As[p][8 * skq + 2][sm] = av0.z;                                        \
        As[p][8 * skq + 3][sm] = av0.w;                                        \
        As[p][8 * skq + 4][sm] = av1.x;                                        \
        As[p][8 * skq + 5][sm] = av1.y;                                        \
        As[p][8 * skq + 6][sm] = av1.z;                                        \
        As[p][8 * skq + 7][sm] = av1.w;                                        \
        *(float4*)&Bs[p][bk][bn4]      = bv0;                                  \
        *(float4*)&Bs[p][bk][64 + bn4] = bv1;                                  \
    };                                                                         \
    LOAD(0); STORE(0);                                                         \
    LOAD(16);                                                                  \
    __syncthreads();                                                           \
    for (int ch = 0; ch < 32; ++ch) {                                          \
        const int p = ch & 1;                                                  \
        if (ch + 1 < 32) STORE(p ^ 1);                                         \
        if (ch + 2 < 32) LOAD((ch + 2) * 16);                                  \
        _Pragma("unroll")                                                      \
        for (int kk = 0; kk < 16; ++kk) {                                      \
            float4 aL = *(const float4*)&As[p][kk][ty * 4];                    \
            float4 aH = *(const float4*)&As[p][kk][64 + ty * 4];               \
            float4 bL = *(const float4*)&Bs[p][kk][tx * 4];                    \
            float4 bH = *(const float4*)&Bs[p][kk][64 + tx * 4];               \
            unsigned long long b2[4], a2;                                      \
            pack2(b2[0], bL.x, bL.y);                                          \
            pack2(b2[1], bL.z, bL.w);                                          \
            pack2(b2[2], bH.x, bH.y);                                          \
            pack2(b2[3], bH.z, bH.w);                                          \
            float arr[8] = {aL.x, aL.y, aL.z, aL.w, aH.x, aH.y, aH.z, aH.w};   \
            _Pragma("unroll")                                                  \
            for (int i = 0; i < 8; ++i) {                                      \
                splat2(a2, arr[i]);                                            \
                _Pragma("unroll")                                              \
                for (int j = 0; j < 4; ++j) ffma2(acc2[i][j], a2, b2[j]);      \
            }                                                                  \
        }                                                                      \
        __syncthreads();                                                       \
    }

// ---------------- stage-0 GEMM: dot = z · cbT, store to g_dist -------------
// grid.x = 128 (rows m<64: bt=r0+m ; m>=64: bt=8192+r0+(m-64)); grid.y = 8.
__global__ void __launch_bounds__(256, 2) vq_gemm(const float* __restrict__ zin) {
    __shared__ __align__(16) float As[2][16][SAS];
    __shared__ __align__(16) float Bs[2][16][SAS];
    const int tid = threadIdx.x;
    const int tx = tid & 15, ty = tid >> 4;
    const int r0 = blockIdx.x * 64;
    const int k0 = blockIdx.y * 128;
    const float* Abase = zin;
    GEMM_BODY((tid >> 1) < 64 ? (r0 + (tid >> 1)) : (8192 + r0 + (tid >> 1) - 64))

#pragma unroll
    for (int i = 0; i < 8; ++i) {
        int m = (i < 4) ? (ty * 4 + i) : (64 + ty * 4 + (i - 4));
        int bt = (m < 64) ? (r0 + m) : (8192 + r0 + (m - 64));
        float d0, d1, d2, d3;
        unpack2(d0, d1, acc2[i][0]);
        unpack2(d2, d3, acc2[i][1]);
        *(float4*)&g_dist[(size_t)bt * KK + k0 + tx * 4] = make_float4(d0, d1, d2, d3);
        unpack2(d0, d1, acc2[i][2]);
        unpack2(d2, d3, acc2[i][3]);
        *(float4*)&g_dist[(size_t)bt * KK + k0 + 64 + tx * 4] = make_float4(d0, d1, d2, d3);
    }
}

// ---------------- Gram GEMM: G = cb · cbT (grid 8x8) -----------------------
__global__ void __launch_bounds__(256, 2) gram_gemm(const float* __restrict__ cb) {
    __shared__ __align__(16) float As[2][16][SAS];
    __shared__ __align__(16) float Bs[2][16][SAS];
    const int tid = threadIdx.x;
    const int tx = tid & 15, ty = tid >> 4;
    const int r0 = blockIdx.x * 128;
    const int k0 = blockIdx.y * 128;
    const float* Abase = cb;
    GEMM_BODY(r0 + (tid >> 1))

#pragma unroll
    for (int i = 0; i < 8; ++i) {
        int m = (i < 4) ? (ty * 4 + i) : (64 + ty * 4 + (i - 4));
        int row = r0 + m;
        float d0, d1, d2, d3;
        unpack2(d0, d1, acc2[i][0]);
        unpack2(d2, d3, acc2[i][1]);
        *(float4*)&g_G[(size_t)row * KK + k0 + tx * 4] = make_float4(d0, d1, d2, d3);
        unpack2(d0, d1, acc2[i][2]);
        unpack2(d2, d3, acc2[i][3]);
        *(float4*)&g_G[(size_t)row * KK + k0 + 64 + tx * 4] = make_float4(d0, d1, d2, d3);
    }
}

// ---------------- rn2: ||z||^2 per row (8 rows/block, warp per row) --------
__global__ void rn2_kernel() {
    int w = threadIdx.x >> 5, lane = threadIdx.x & 31;
    int bt = blockIdx.x * 8 + w;
    const float4* p = (const float4*)&g_res[(size_t)bt * DD];
    float sum = 0.0f;
#pragma unroll
    for (int i = 0; i < 4; ++i) {
        float4 v = p[lane + 32 * i];
        sum += v.x * v.x + v.y * v.y + v.z * v.z + v.w * v.w;
    }
#pragma unroll
    for (int off = 16; off > 0; off >>= 1)
        sum += __shfl_xor_sync(0xffffffffu, sum, off);
    if (lane == 0) g_rn2[bt] = sum;
}

// ---------------- pick: all 8 VQ stages per row, one block per bt ----------
__global__ void __launch_bounds__(256) vq_pick(const float* __restrict__ cb) {
    const int bt = blockIdx.x;
    const int tid = threadIdx.x;
    __shared__ unsigned sMaxU;
    __shared__ unsigned long long sBest;
    __shared__ float sDotSel;
    __shared__ int sSel[8];

    if (tid == 0) { sMaxU = 0u; sBest = 0ull; }

    // this thread's 4 columns: c_j = tid + 256*j  (coalesced)
    float d[4], cs[4], s[4];
    const float* drow = &g_dist[(size_t)bt * KK];
#pragma unroll
    for (int j = 0; j < 4; ++j) {
        d[j] = drow[tid + 256 * j];
        cs[j] = g_csq[tid + 256 * j];
        s[j] = fmaf(20.0f, d[j], -10.0f * cs[j]);
    }
    const float win = g_window;
    const unsigned btL = (bt < 8192) ? (unsigned)bt : (unsigned)(bt - 8192);
    const bool hi = (bt >= 8192);
    float rn2 = 0.0f, commit = 0.0f;
    if (tid == 0) rn2 = g_rn2[bt];
    __syncthreads();

    for (int i = 0; i < 8; ++i) {
        // row max
        float lm = fmaxf(fmaxf(s[0], s[1]), fmaxf(s[2], s[3]));
#pragma unroll
        for (int off = 16; off > 0; off >>= 1)
            lm = fmaxf(lm, __shfl_xor_sync(0xffffffffu, lm, off));
        if ((tid & 31) == 0) atomicMax(&sMaxU, fmap(lm));
        __syncthreads();
        const float tau = unfmap(sMaxU) - win;

        // windowed survivors -> gumbel -> best
        const unsigned fk0 = g_fk[2 * i], fk1 = g_fk[2 * i + 1];
#pragma unroll
        for (int j = 0; j < 4; ++j) {
            if (s[j] >= tau) {
                unsigned k = (unsigned)(tid + 256 * j);
                unsigned n = btL * 1024u + k;
                unsigned b0, b1;
                tf2x32(fk0, fk1, n, n + HALF_N, b0, b1);
                float g = gumbel_from_bits(hi ? b1 : b0);
                float sc = s[j] + g;
                unsigned long long cand =
                    ((unsigned long long)fmap(sc) << 32) | (unsigned long long)(~k);
                atomicMax(&sBest, cand);
            }
        }
        __syncthreads();
        const unsigned sel = ~(unsigned)(sBest & 0xffffffffull);
        if (tid == (int)(sel & 255u)) sDotSel = d[sel >> 8];
        __syncthreads();
        if (tid == 0) {
            float rn2n = rn2 - 2.0f * sDotSel + g_csq[sel];
            commit += rn2n;
            rn2 = rn2n;
            sSel[i] = (int)sel;
            sMaxU = 0u;
            sBest = 0ull;
        }
        if (i < 7) {
            const float* grow = &g_G[(size_t)sel * KK];
#pragma unroll
            for (int j = 0; j < 4; ++j) {
                d[j] -= grow[tid + 256 * j];
                s[j] = fmaf(20.0f, d[j], -10.0f * cs[j]);
            }
        }
        __syncthreads();
    }

    // q_out[bt] = sum of selected codebook rows
    float a0 = 0.0f, a1 = 0.0f;
#pragma unroll
    for (int i = 0; i < 8; ++i) {
        const float* cp = cb + (size_t)sSel[i] * DD;
        a0 += cp[tid];
        a1 += cp[tid + 256];
    }
    g_qout[(size_t)bt * DD + tid] = a0;
    g_qout[(size_t)bt * DD + tid + 256] = a1;

    if (tid == 0) atomicAdd(&g_acc[0], commit);
}

// ---------------- init: csq, window, fold-in keys, accumulators ------------
__global__ void vq_init(const float* __restrict__ cb) {
    int k = blockIdx.x;
    int tid = threadIdx.x;  // 128
    float local = 0.0f;
#pragma unroll
    for (int ll = 0; ll < 4; ++ll) {
        float c = cb[(size_t)k * DD + tid + 128 * ll];
        local += c * c;
    }
    __shared__ float red[128];
    red[tid] = local;
    __syncthreads();
    for (int s = 64; s > 0; s >>= 1) {
        if (tid < s) red[tid] += red[tid + s];
        __syncthreads();
    }
    if (tid == 0) g_csq[k] = red[0];
    if (blockIdx.x == 0 && tid < 2) g_acc[tid] = 0.0f;
    if (blockIdx.x == 0 && tid < 8) {
        unsigned a, b;
        tf2x32(0u, 42u, 0u, (unsigned)tid, a, b);
        g_fk[2 * tid] = a;
        g_fk[2 * tid + 1] = b;
    }
    if (blockIdx.x == 0 && tid == 0) {
        float ghi = gumbel_from_bits(0xFFFFFFFFu);
        float glo = gumbel_from_bits(0u);
        g_window = (ghi - glo) + 0.5f;
    }
}

__global__ void finalize_k(float* __restrict__ out) {
    out[0] = g_acc[1] * (1.0f / 1638400.0f)      // mse /(BT*100)
           + g_acc[0] * (1.0f / 67108864.0f);    // commit /(8*BT*512)
}

// ---------------- host launcher (graph-capturable, alloc-free) -------------
extern "C" void kernel_launch(void* const* d_in, const int* in_sizes, int n_in,
                              void* d_out, int out_size) {
    const float* x   = (const float*)d_in[0];
    const float* ew1 = (const float*)d_in[1];
    const float* eb1 = (const float*)d_in[2];
    const float* ew2 = (const float*)d_in[3];
    const float* eb2 = (const float*)d_in[4];
    const float* cb  = (const float*)d_in[5];
    const float* dw1 = (const float*)d_in[6];
    const float* db1 = (const float*)d_in[7];
    const float* dw2 = (const float*)d_in[8];
    const float* db2 = (const float*)d_in[9];
    float* out = (float*)d_out;

    float *h1, *res, *qout;
    cudaGetSymbolAddress((void**)&h1,   g_h1);
    cudaGetSymbolAddress((void**)&res,  g_res);
    cudaGetSymbolAddress((void**)&qout, g_qout);

    vq_init<<<KK, 128>>>(cb);
    transpose_cb<<<dim3(KK / 32, DD / 32), dim3(32, 8)>>>(cb);
    gram_gemm<<<dim3(8, 8), 256>>>(cb);

    // encoder
    conv3<100, 256, false><<<dim3(128, 2), 256>>>(x,  ew1, eb1, h1,  nullptr);
    conv3<256, 512, false><<<dim3(128, 4), 256>>>(h1, ew2, eb2, res, nullptr);

    // residual VQ: one GEMM + per-row 8-stage walk
    rn2_kernel<<<BT / 8, 256>>>();
    vq_gemm<<<dim3(128, 8), 256>>>(res);
    vq_pick<<<BT, 256>>>(cb);

    // decoder (+ fused MSE on the last conv)
    conv3<512, 256, false><<<dim3(128, 2), 256>>>(qout, dw1, db1, h1, nullptr);
    conv3<256, 100, true ><<<dim3(128, 1), 256>>>(h1,  dw2, db2, nullptr, x);

    finalize_k<<<1, 1>>>(out);
}

// round 10
// speedup vs baseline: 3.6694x; 1.1656x over previous
#include <cuda_runtime.h>
#include <cstdint>

#define TT 2048
#define BT 16384
#define DD 512
#define KK 1024
#define HALF_N 8388608u   // BT*KK/2

// ---------------- scratch (static device allocations only) ----------------
__device__ float g_h1[BT * 256];
__device__ float g_res[BT * DD];          // encoder output z
__device__ float g_qout[BT * DD];
__device__ float g_cbT[DD * KK];          // codebook transposed [d][k]
__device__ float g_dist[BT * KK];         // dot products <z, c_k>  (64MB)
__device__ float g_G[KK * KK];            // Gram matrix cb·cbT     (4MB)
__device__ float g_rn2[BT];               // running ||residual||^2
__device__ float g_csq[KK];
__device__ float g_wT[1048576];           // transposed padded weights (4MB)
__device__ unsigned g_fk[16];             // per-stage threefry fold-in keys
__device__ float g_window;                // gumbel hi-lo window + margin
__device__ float g_acc[2];   // [0]=commit sum, [1]=mse sum

// wT offsets (floats): enc1 3*112*256, enc2 3*256*512, dec1 3*512*256, dec2 3*256*128
#define WT_O1 0
#define WT_O2 86016
#define WT_O3 479232
#define WT_O4 872448

// ---------------- packed f32x2 helpers ----------------
__device__ __forceinline__ void splat2(unsigned long long& d, float a) {
    asm("mov.b64 %0, {%1, %1};" : "=l"(d) : "f"(a));
}
__device__ __forceinline__ void pack2(unsigned long long& d, float a, float b) {
    asm("mov.b64 %0, {%1, %2};" : "=l"(d) : "f"(a), "f"(b));
}
__device__ __forceinline__ void unpack2(float& a, float& b, unsigned long long d) {
    asm("mov.b64 {%0, %1}, %2;" : "=f"(a), "=f"(b) : "l"(d));
}
__device__ __forceinline__ void ffma2(unsigned long long& acc,
                                      unsigned long long a, unsigned long long b) {
    asm("fma.rn.f32x2 %0, %1, %2, %0;" : "+l"(acc) : "l"(a), "l"(b));
}

// ---------------- JAX threefry2x32 (exact) ----------------
__host__ __device__ inline void tf2x32(unsigned k0, unsigned k1,
                                       unsigned x0, unsigned x1,
                                       unsigned& o0, unsigned& o1) {
    unsigned ks2 = k0 ^ k1 ^ 0x1BD11BDAu;
    x0 += k0; x1 += k1;
#define TF_RND(r) { x0 += x1; x1 = (x1 << (r)) | (x1 >> (32 - (r))); x1 ^= x0; }
    TF_RND(13) TF_RND(15) TF_RND(26) TF_RND(6)
    x0 += k1;  x1 += ks2 + 1u;
    TF_RND(17) TF_RND(29) TF_RND(16) TF_RND(24)
    x0 += ks2; x1 += k0 + 2u;
    TF_RND(13) TF_RND(15) TF_RND(26) TF_RND(6)
    x0 += k0;  x1 += k1 + 3u;
    TF_RND(17) TF_RND(29) TF_RND(16) TF_RND(24)
    x0 += k1;  x1 += ks2 + 4u;
    TF_RND(13) TF_RND(15) TF_RND(26) TF_RND(6)
    x0 += ks2; x1 += k0 + 5u;
#undef TF_RND
    o0 = x0; o1 = x1;
}

__device__ inline float gumbel_from_bits(unsigned bits) {
    float f = __uint_as_float((bits >> 9) | 0x3f800000u) - 1.0f;
    float u = (f == 0.0f) ? 1.17549435e-38f : f;
    return -__logf(-__logf(u));
}

__device__ inline unsigned fmap(float f) {   // monotone float -> uint
    unsigned u = __float_as_uint(f);
    return (u & 0x80000000u) ? ~u : (u | 0x80000000u);
}
__device__ inline float unfmap(unsigned u) {
    unsigned v = (u & 0x80000000u) ? (u ^ 0x80000000u) : ~u;
    return __uint_as_float(v);
}

__device__ inline float gelu_exact(float v) {
    return 0.5f * v * (1.0f + erff(v * 0.7071067811865476f));
}

// ---------------- codebook transpose: cbT[d][k] = cb[k][d] ----------------
__global__ void transpose_cb(const float* __restrict__ cb) {
    __shared__ float t[32][33];
    int k0 = blockIdx.x * 32;
    int d0 = blockIdx.y * 32;
    int tx = threadIdx.x, ty = threadIdx.y;  // 32 x 8
    for (int l = 0; l < 32; l += 8)
        t[ty + l][tx] = cb[(k0 + ty + l) * DD + d0 + tx];
    __syncthreads();
    for (int l = 0; l < 32; l += 8)
        g_cbT[(d0 + ty + l) * KK + k0 + tx] = t[tx][ty + l];
}

// ---------------- weight transpose: w[CO][CI][3] -> wT[tap][ci][co] pad ----
__global__ void transpose_w(const float* __restrict__ w, float* __restrict__ wT,
                            int CIN, int COUT, int CIN16, int COUT_PAD) {
    int idx = blockIdx.x * 256 + threadIdx.x;
    int total = 3 * CIN16 * COUT_PAD;
    if (idx >= total) return;
    int co = idx % COUT_PAD;
    int rest = idx / COUT_PAD;
    int ci = rest % CIN16;
    int tap = rest / CIN16;
    float v = 0.0f;
    if (ci < CIN && co < COUT)
        v = w[((size_t)co * CIN + ci) * 3 + tap];
    wT[idx] = v;
}

// ---------------- conv3f: vq_gemm-style conv (float4 smem, wT operand) -----
// Tile 128 rows x 128 cols. Thread (tx,ty): rows ty*4+{0..3} & 64+ty*4+{0..3},
// cols tx*4+{0..3} & 64+tx*4+{0..3}.
#define SAS 136
template<int CIN, int COUT, int COUT_PAD, bool FUSE_MSE>
__global__ void __launch_bounds__(256, 2) conv3f(
    const float* __restrict__ in, const float* __restrict__ wT,
    const float* __restrict__ bias, float* __restrict__ out,
    const float* __restrict__ xref)
{
    __shared__ __align__(16) float As[2][16][SAS];
    __shared__ __align__(16) float Bs[2][16][SAS];
    constexpr int NC = (CIN + 15) / 16;
    constexpr int CIN16 = NC * 16;
    constexpr int NS = 3 * NC;
    const int tid = threadIdx.x;
    const int tx = tid & 15, ty = tid >> 4;
    const int r0 = blockIdx.x * 128;
    const int n0 = blockIdx.y * 128;

    // staging maps
    const int sm  = tid >> 1;            // A row m 0..127
    const int skq = tid & 1;             // A ci offset (8 each)
    const int aRow = r0 + sm;
    const int tt = aRow & (TT - 1);
    const int bk  = tid >> 4;            // B k-row 0..15
    const int bn4 = (tid & 15) * 4;

    unsigned long long acc2[8][4];
#pragma unroll
    for (int i = 0; i < 8; ++i)
#pragma unroll
        for (int j = 0; j < 4; ++j) acc2[i][j] = 0ull;

    float4 av0, av1, bv0, bv1;

    auto LOAD = [&](int s) {
        const int tap = s / NC;
        const int ccc = (s - tap * NC) * 16;
        const int ci = ccc + 8 * skq;
        const int st = tt + tap - 1;
        const bool rv = (st >= 0 && st < TT);
        const float* ap = in + (size_t)(aRow + tap - 1) * CIN + ci;
        if ((CIN % 16 == 0) || (ccc + 16 <= CIN)) {
            if (rv) {
                av0 = *(const float4*)(ap);
                av1 = *(const float4*)(ap + 4);
            } else {
                av0 = make_float4(0.f, 0.f, 0.f, 0.f);
                av1 = av0;
            }
        } else {
            float t0[8];
#pragma unroll
            for (int q = 0; q < 8; ++q)
                t0[q] = (rv && ci + q < CIN) ? ap[q] : 0.0f;
            av0 = make_float4(t0[0], t0[1], t0[2], t0[3]);
            av1 = make_float4(t0[4], t0[5], t0[6], t0[7]);
        }
        const float* bp = wT + (size_t)(tap * CIN16 + ccc + bk) * COUT_PAD + n0;
        bv0 = *(const float4*)(bp + bn4);
        bv1 = *(const float4*)(bp + 64 + bn4);
    };
    auto STORE = [&](int p) {
        As[p][8 * skq + 0][sm] = av0.x;
        As[p][8 * skq + 1][sm] = av0.y;
        As[p][8 * skq + 2][sm] = av0.z;
        As[p][8 * skq + 3][sm] = av0.w;
        As[p][8 * skq + 4][sm] = av1.x;
        As[p][8 * skq + 5][sm] = av1.y;
        As[p][8 * skq + 6][sm] = av1.z;
        As[p][8 * skq + 7][sm] = av1.w;
        *(float4*)&Bs[p][bk][bn4]      = bv0;
        *(float4*)&Bs[p][bk][64 + bn4] = bv1;
    };

    LOAD(0); STORE(0);
    LOAD(1);
    __syncthreads();

    for (int s = 0; s < NS; ++s) {
        const int p = s & 1;
        if (s + 1 < NS) STORE(p ^ 1);
        if (s + 2 < NS) LOAD(s + 2);
#pragma unroll
        for (int kk = 0; kk < 16; ++kk) {
            float4 aL = *(const float4*)&As[p][kk][ty * 4];
            float4 aH = *(const float4*)&As[p][kk][64 + ty * 4];
            float4 bL = *(const float4*)&Bs[p][kk][tx * 4];
            float4 bH = *(const float4*)&Bs[p][kk][64 + tx * 4];
            unsigned long long b2[4], a2;
            pack2(b2[0], bL.x, bL.y);
            pack2(b2[1], bL.z, bL.w);
            pack2(b2[2], bH.x, bH.y);
            pack2(b2[3], bH.z, bH.w);
            float arr[8] = {aL.x, aL.y, aL.z, aL.w, aH.x, aH.y, aH.z, aH.w};
#pragma unroll
            for (int i = 0; i < 8; ++i) {
                splat2(a2, arr[i]);
#pragma unroll
                for (int j = 0; j < 4; ++j) ffma2(acc2[i][j], a2, b2[j]);
            }
        }
        __syncthreads();
    }

    // epilogue: bias + gelu; cols acc2[i][0..1] -> n0+tx*4.., [2..3] -> n0+64+tx*4..
    float bl[8];
#pragma unroll
    for (int c = 0; c < 4; ++c) {
        int coL = n0 + tx * 4 + c;
        int coH = n0 + 64 + tx * 4 + c;
        bl[c]     = (COUT % 128 == 0 || coL < COUT) ? bias[coL] : 0.0f;
        bl[4 + c] = (COUT % 128 == 0 || coH < COUT) ? bias[coH] : 0.0f;
    }
    float local = 0.0f;
#pragma unroll
    for (int i = 0; i < 8; ++i) {
        int m = (i < 4) ? (ty * 4 + i) : (64 + ty * 4 + (i - 4));
        int r = r0 + m;
        float v[8];
        unpack2(v[0], v[1], acc2[i][0]);
        unpack2(v[2], v[3], acc2[i][1]);
        unpack2(v[4], v[5], acc2[i][2]);
        unpack2(v[6], v[7], acc2[i][3]);
#pragma unroll
        for (int hf = 0; hf < 2; ++hf) {
            int cobase = n0 + 64 * hf + tx * 4;
            float g0 = gelu_exact(v[4 * hf + 0] + bl[4 * hf + 0]);
            float g1 = gelu_exact(v[4 * hf + 1] + bl[4 * hf + 1]);
            float g2 = gelu_exact(v[4 * hf + 2] + bl[4 * hf + 2]);
            float g3 = gelu_exact(v[4 * hf + 3] + bl[4 * hf + 3]);
            if (FUSE_MSE) {
                float gg[4] = {g0, g1, g2, g3};
#pragma unroll
                for (int c = 0; c < 4; ++c) {
                    int co = cobase + c;
                    if (co < COUT) {
                        float d = xref[(size_t)r * COUT + co] - gg[c];
                        local += d * d;
                    }
                }
            } else if (COUT % 128 == 0) {
                *(float4*)&out[(size_t)r * COUT + cobase] = make_float4(g0, g1, g2, g3);
            } else {
                float gg[4] = {g0, g1, g2, g3};
#pragma unroll
                for (int c = 0; c < 4; ++c) {
                    int co = cobase + c;
                    if (co < COUT) out[(size_t)r * COUT + co] = gg[c];
                }
            }
        }
    }
    if (FUSE_MSE) {
        __shared__ float red[256];
        red[tid] = local;
        __syncthreads();
        for (int s = 128; s > 0; s >>= 1) {
            if (tid < s) red[tid] += red[tid + s];
            __syncthreads();
        }
        if (tid == 0) atomicAdd(&g_acc[1], red[0]);
    }
}

// ---------------- shared pipelined-GEMM body (A rows x cbT cols) ----------
#define GEMM_BODY(AROW_EXPR)                                                   \
    const int sm  = tid >> 1;                                                  \
    const int skq = tid & 1;                                                   \
    const int arow = (AROW_EXPR);                                              \
    const float* aptr = Abase + (size_t)arow * DD + 8 * skq;                   \
    const int bk  = tid >> 4;                                                  \
    const int bn4 = (tid & 15) * 4;                                            \
    const float* bbase = &g_cbT[(size_t)bk * KK + k0];                         \
    unsigned long long acc2[8][4];                                             \
    _Pragma("unroll")                                                          \
    for (int i = 0; i < 8; ++i)                                                \
        _Pragma("unroll")                                                      \
        for (int j = 0; j < 4; ++j) acc2[i][j] = 0ull;                         \
    float4 av0, av1, bv0, bv1;                                                 \
    auto LOAD = [&](int cc) {                                                  \
        av0 = *(const float4*)(aptr + cc);                                     \
        av1 = *(const float4*)(aptr + cc + 4);                                 \
        const float* bp = bbase + (size_t)cc * KK;                             \
        bv0 = *(const float4*)(bp + bn4);                                      \
        bv1 = *(const float4*)(bp + 64 + bn4);                                 \
    };                                                                         \
    auto STORE = [&](int p) {                                                  \
        As[p][8 * skq + 0][sm] = av0.x;                                        \
        As[p][8 * skq + 1][sm] = av0.y;                                        \
        As[p][8 * skq + 2][sm] = av0.z;                                        \
        As[p][8 * skq + 3][sm] = av0.w;                                        \
        As[p][8 * skq + 4][sm] = av1.x;                                        \
        As[p][8 * skq + 5][sm] = av1.y;                                        \
        As[p][8 * skq + 6][sm] = av1.z;                                        \
        As[p][8 * skq + 7][sm] = av1.w;                                        \
        *(float4*)&Bs[p][bk][bn4]      = bv0;                                  \
        *(float4*)&Bs[p][bk][64 + bn4] = bv1;                                  \
    };                                                                         \
    LOAD(0); STORE(0);                                                         \
    LOAD(16);                                                                  \
    __syncthreads();                                                           \
    for (int ch = 0; ch < 32; ++ch) {                                          \
        const int p = ch & 1;                                                  \
        if (ch + 1 < 32) STORE(p ^ 1);                                         \
        if (ch + 2 < 32) LOAD((ch + 2) * 16);                                  \
        _Pragma("unroll")                                                      \
        for (int kk = 0; kk < 16; ++kk) {                                      \
            float4 aL = *(const float4*)&As[p][kk][ty * 4];                    \
            float4 aH = *(const float4*)&As[p][kk][64 + ty * 4];               \
            float4 bL = *(const float4*)&Bs[p][kk][tx * 4];                    \
            float4 bH = *(const float4*)&Bs[p][kk][64 + tx * 4];               \
            unsigned long long b2[4], a2;                                      \
            pack2(b2[0], bL.x, bL.y);                                          \
            pack2(b2[1], bL.z, bL.w);                                          \
            pack2(b2[2], bH.x, bH.y);                                          \
            pack2(b2[3], bH.z, bH.w);                                          \
            float arr[8] = {aL.x, aL.y, aL.z, aL.w, aH.x, aH.y, aH.z, aH.w};   \
            _Pragma("unroll")                                                  \
            for (int i = 0; i < 8; ++i) {                                      \
                splat2(a2, arr[i]);                                            \
                _Pragma("unroll")                                              \
                for (int j = 0; j < 4; ++j) ffma2(acc2[i][j], a2, b2[j]);      \
            }                                                                  \
        }                                                                      \
        __syncthreads();                                                       \
    }

// ---------------- stage-0 GEMM: dot = z · cbT, store to g_dist -------------
__global__ void __launch_bounds__(256, 2) vq_gemm(const float* __restrict__ zin) {
    __shared__ __align__(16) float As[2][16][SAS];
    __shared__ __align__(16) float Bs[2][16][SAS];
    const int tid = threadIdx.x;
    const int tx = tid & 15, ty = tid >> 4;
    const int r0 = blockIdx.x * 64;
    const int k0 = blockIdx.y * 128;
    const float* Abase = zin;
    GEMM_BODY((tid >> 1) < 64 ? (r0 + (tid >> 1)) : (8192 + r0 + (tid >> 1) - 64))

#pragma unroll
    for (int i = 0; i < 8; ++i) {
        int m = (i < 4) ? (ty * 4 + i) : (64 + ty * 4 + (i - 4));
        int bt = (m < 64) ? (r0 + m) : (8192 + r0 + (m - 64));
        float d0, d1, d2, d3;
        unpack2(d0, d1, acc2[i][0]);
        unpack2(d2, d3, acc2[i][1]);
        *(float4*)&g_dist[(size_t)bt * KK + k0 + tx * 4] = make_float4(d0, d1, d2, d3);
        unpack2(d0, d1, acc2[i][2]);
        unpack2(d2, d3, acc2[i][3]);
        *(float4*)&g_dist[(size_t)bt * KK + k0 + 64 + tx * 4] = make_float4(d0, d1, d2, d3);
    }
}

// ---------------- Gram GEMM: G = cb · cbT (grid 8x8) -----------------------
__global__ void __launch_bounds__(256, 2) gram_gemm(const float* __restrict__ cb) {
    __shared__ __align__(16) float As[2][16][SAS];
    __shared__ __align__(16) float Bs[2][16][SAS];
    const int tid = threadIdx.x;
    const int tx = tid & 15, ty = tid >> 4;
    const int r0 = blockIdx.x * 128;
    const int k0 = blockIdx.y * 128;
    const float* Abase = cb;
    GEMM_BODY(r0 + (tid >> 1))

#pragma unroll
    for (int i = 0; i < 8; ++i) {
        int m = (i < 4) ? (ty * 4 + i) : (64 + ty * 4 + (i - 4));
        int row = r0 + m;
        float d0, d1, d2, d3;
        unpack2(d0, d1, acc2[i][0]);
        unpack2(d2, d3, acc2[i][1]);
        *(float4*)&g_G[(size_t)row * KK + k0 + tx * 4] = make_float4(d0, d1, d2, d3);
        unpack2(d0, d1, acc2[i][2]);
        unpack2(d2, d3, acc2[i][3]);
        *(float4*)&g_G[(size_t)row * KK + k0 + 64 + tx * 4] = make_float4(d0, d1, d2, d3);
    }
}

// ---------------- rn2: ||z||^2 per row (8 rows/block, warp per row) --------
__global__ void rn2_kernel() {
    int w = threadIdx.x >> 5, lane = threadIdx.x & 31;
    int bt = blockIdx.x * 8 + w;
    const float4* p = (const float4*)&g_res[(size_t)bt * DD];
    float sum = 0.0f;
#pragma unroll
    for (int i = 0; i < 4; ++i) {
        float4 v = p[lane + 32 * i];
        sum += v.x * v.x + v.y * v.y + v.z * v.z + v.w * v.w;
    }
#pragma unroll
    for (int off = 16; off > 0; off >>= 1)
        sum += __shfl_xor_sync(0xffffffffu, sum, off);
    if (lane == 0) g_rn2[bt] = sum;
}

// ---------------- pick: all 8 VQ stages per row, one block per bt ----------
__global__ void __launch_bounds__(256) vq_pick(const float* __restrict__ cb) {
    const int bt = blockIdx.x;
    const int tid = threadIdx.x;
    __shared__ unsigned sMaxU;
    __shared__ unsigned long long sBest;
    __shared__ float sDotSel;
    __shared__ int sSel[8];

    if (tid == 0) { sMaxU = 0u; sBest = 0ull; }

    float d[4], cs[4], s[4];
    const float* drow = &g_dist[(size_t)bt * KK];
#pragma unroll
    for (int j = 0; j < 4; ++j) {
        d[j] = drow[tid + 256 * j];
        cs[j] = g_csq[tid + 256 * j];
        s[j] = fmaf(20.0f, d[j], -10.0f * cs[j]);
    }
    const float win = g_window;
    const unsigned btL = (bt < 8192) ? (unsigned)bt : (unsigned)(bt - 8192);
    const bool hi = (bt >= 8192);
    float rn2 = 0.0f, commit = 0.0f;
    if (tid == 0) rn2 = g_rn2[bt];
    __syncthreads();

    for (int i = 0; i < 8; ++i) {
        float lm = fmaxf(fmaxf(s[0], s[1]), fmaxf(s[2], s[3]));
#pragma unroll
        for (int off = 16; off > 0; off >>= 1)
            lm = fmaxf(lm, __shfl_xor_sync(0xffffffffu, lm, off));
        if ((tid & 31) == 0) atomicMax(&sMaxU, fmap(lm));
        __syncthreads();
        const float tau = unfmap(sMaxU) - win;

        const unsigned fk0 = g_fk[2 * i], fk1 = g_fk[2 * i + 1];
#pragma unroll
        for (int j = 0; j < 4; ++j) {
            if (s[j] >= tau) {
                unsigned k = (unsigned)(tid + 256 * j);
                unsigned n = btL * 1024u + k;
                unsigned b0, b1;
                tf2x32(fk0, fk1, n, n + HALF_N, b0, b1);
                float g = gumbel_from_bits(hi ? b1 : b0);
                float sc = s[j] + g;
                unsigned long long cand =
                    ((unsigned long long)fmap(sc) << 32) | (unsigned long long)(~k);
                atomicMax(&sBest, cand);
            }
        }
        __syncthreads();
        const unsigned sel = ~(unsigned)(sBest & 0xffffffffull);
        if (tid == (int)(sel & 255u)) sDotSel = d[sel >> 8];
        __syncthreads();
        if (tid == 0) {
            float rn2n = rn2 - 2.0f * sDotSel + g_csq[sel];
            commit += rn2n;
            rn2 = rn2n;
            sSel[i] = (int)sel;
            sMaxU = 0u;
            sBest = 0ull;
        }
        if (i < 7) {
            const float* grow = &g_G[(size_t)sel * KK];
#pragma unroll
            for (int j = 0; j < 4; ++j) {
                d[j] -= grow[tid + 256 * j];
                s[j] = fmaf(20.0f, d[j], -10.0f * cs[j]);
            }
        }
        __syncthreads();
    }

    float a0 = 0.0f, a1 = 0.0f;
#pragma unroll
    for (int i = 0; i < 8; ++i) {
        const float* cp = cb + (size_t)sSel[i] * DD;
        a0 += cp[tid];
        a1 += cp[tid + 256];
    }
    g_qout[(size_t)bt * DD + tid] = a0;
    g_qout[(size_t)bt * DD + tid + 256] = a1;

    if (tid == 0) atomicAdd(&g_acc[0], commit);
}

// ---------------- init: csq, window, fold-in keys, accumulators ------------
__global__ void vq_init(const float* __restrict__ cb) {
    int k = blockIdx.x;
    int tid = threadIdx.x;  // 128
    float local = 0.0f;
#pragma unroll
    for (int ll = 0; ll < 4; ++ll) {
        float c = cb[(size_t)k * DD + tid + 128 * ll];
        local += c * c;
    }
    __shared__ float red[128];
    red[tid] = local;
    __syncthreads();
    for (int s = 64; s > 0; s >>= 1) {
        if (tid < s) red[tid] += red[tid + s];
        __syncthreads();
    }
    if (tid == 0) g_csq[k] = red[0];
    if (blockIdx.x == 0 && tid < 2) g_acc[tid] = 0.0f;
    if (blockIdx.x == 0 && tid < 8) {
        unsigned a, b;
        tf2x32(0u, 42u, 0u, (unsigned)tid, a, b);
        g_fk[2 * tid] = a;
        g_fk[2 * tid + 1] = b;
    }
    if (blockIdx.x == 0 && tid == 0) {
        float ghi = gumbel_from_bits(0xFFFFFFFFu);
        float glo = gumbel_from_bits(0u);
        g_window = (ghi - glo) + 0.5f;
    }
}

__global__ void finalize_k(float* __restrict__ out) {
    out[0] = g_acc[1] * (1.0f / 1638400.0f)      // mse /(BT*100)
           + g_acc[0] * (1.0f / 67108864.0f);    // commit /(8*BT*512)
}

// ---------------- host launcher (graph-capturable, alloc-free) -------------
extern "C" void kernel_launch(void* const* d_in, const int* in_sizes, int n_in,
                              void* d_out, int out_size) {
    const float* x   = (const float*)d_in[0];
    const float* ew1 = (const float*)d_in[1];
    const float* eb1 = (const float*)d_in[2];
    const float* ew2 = (const float*)d_in[3];
    const float* eb2 = (const float*)d_in[4];
    const float* cb  = (const float*)d_in[5];
    const float* dw1 = (const float*)d_in[6];
    const float* db1 = (const float*)d_in[7];
    const float* dw2 = (const float*)d_in[8];
    const float* db2 = (const float*)d_in[9];
    float* out = (float*)d_out;

    float *h1, *res, *qout, *wT;
    cudaGetSymbolAddress((void**)&h1,   g_h1);
    cudaGetSymbolAddress((void**)&res,  g_res);
    cudaGetSymbolAddress((void**)&qout, g_qout);
    cudaGetSymbolAddress((void**)&wT,   g_wT);

    vq_init<<<KK, 128>>>(cb);
    transpose_cb<<<dim3(KK / 32, DD / 32), dim3(32, 8)>>>(cb);

    // transpose+pad all conv weights upfront
    transpose_w<<<(3 * 112 * 256 + 255) / 256, 256>>>(ew1, wT + WT_O1, 100, 256, 112, 256);
    transpose_w<<<(3 * 256 * 512 + 255) / 256, 256>>>(ew2, wT + WT_O2, 256, 512, 256, 512);
    transpose_w<<<(3 * 512 * 256 + 255) / 256, 256>>>(dw1, wT + WT_O3, 512, 256, 512, 256);
    transpose_w<<<(3 * 256 * 128 + 255) / 256, 256>>>(dw2, wT + WT_O4, 256, 100, 256, 128);

    gram_gemm<<<dim3(8, 8), 256>>>(cb);

    // encoder
    conv3f<100, 256, 256, false><<<dim3(128, 2), 256>>>(x,  wT + WT_O1, eb1, h1,  nullptr);
    conv3f<256, 512, 512, false><<<dim3(128, 4), 256>>>(h1, wT + WT_O2, eb2, res, nullptr);

    // residual VQ: one GEMM + per-row 8-stage walk
    rn2_kernel<<<BT / 8, 256>>>();
    vq_gemm<<<dim3(128, 8), 256>>>(res);
    vq_pick<<<BT, 256>>>(cb);

    // decoder (+ fused MSE on the last conv)
    conv3f<512, 256, 256, false><<<dim3(128, 2), 256>>>(qout, wT + WT_O3, db1, h1, nullptr);
    conv3f<256, 100, 128, true ><<<dim3(128, 1), 256>>>(h1,  wT + WT_O4, db2, nullptr, x);

    finalize_k<<<1, 1>>>(out);
}

// round 11
// speedup vs baseline: 3.7155x; 1.0126x over previous
#include <cuda_runtime.h>
#include <cstdint>

#define TT 2048
#define BT 16384
#define DD 512
#define KK 1024
#define HALF_N 8388608u   // BT*KK/2

// ---------------- scratch (static device allocations only) ----------------
__device__ float g_h1[BT * 256];
__device__ float g_res[BT * DD];          // encoder output z
__device__ float g_qout[BT * DD];
__device__ float g_cbT[DD * KK];          // codebook transposed [d][k]
__device__ float g_dist[BT * KK];         // dot products <z, c_k>  (64MB)
__device__ float g_G[KK * KK];            // Gram matrix cb·cbT     (4MB)
__device__ float g_csq[KK];               // = diag(G)
__device__ float g_wT[1048576];           // transposed padded weights (4MB)
__device__ unsigned g_fk[16];             // per-stage threefry fold-in keys
__device__ float g_window;                // gumbel hi-lo window + margin
__device__ float g_acc[2];   // [0]=commit sum, [1]=mse sum

// wT offsets (floats): enc1 3*112*256, enc2 3*256*512, dec1 3*512*256, dec2 3*256*128
#define WT_O1 0
#define WT_O2 86016
#define WT_O3 479232
#define WT_O4 872448
#define WT_END 970752

// ---------------- packed f32x2 helpers ----------------
__device__ __forceinline__ void splat2(unsigned long long& d, float a) {
    asm("mov.b64 %0, {%1, %1};" : "=l"(d) : "f"(a));
}
__device__ __forceinline__ void pack2(unsigned long long& d, float a, float b) {
    asm("mov.b64 %0, {%1, %2};" : "=l"(d) : "f"(a), "f"(b));
}
__device__ __forceinline__ void unpack2(float& a, float& b, unsigned long long d) {
    asm("mov.b64 {%0, %1}, %2;" : "=f"(a), "=f"(b) : "l"(d));
}
__device__ __forceinline__ void ffma2(unsigned long long& acc,
                                      unsigned long long a, unsigned long long b) {
    asm("fma.rn.f32x2 %0, %1, %2, %0;" : "+l"(acc) : "l"(a), "l"(b));
}

// ---------------- JAX threefry2x32 (exact) ----------------
__host__ __device__ inline void tf2x32(unsigned k0, unsigned k1,
                                       unsigned x0, unsigned x1,
                                       unsigned& o0, unsigned& o1) {
    unsigned ks2 = k0 ^ k1 ^ 0x1BD11BDAu;
    x0 += k0; x1 += k1;
#define TF_RND(r) { x0 += x1; x1 = (x1 << (r)) | (x1 >> (32 - (r))); x1 ^= x0; }
    TF_RND(13) TF_RND(15) TF_RND(26) TF_RND(6)
    x0 += k1;  x1 += ks2 + 1u;
    TF_RND(17) TF_RND(29) TF_RND(16) TF_RND(24)
    x0 += ks2; x1 += k0 + 2u;
    TF_RND(13) TF_RND(15) TF_RND(26) TF_RND(6)
    x0 += k0;  x1 += k1 + 3u;
    TF_RND(17) TF_RND(29) TF_RND(16) TF_RND(24)
    x0 += k1;  x1 += ks2 + 4u;
    TF_RND(13) TF_RND(15) TF_RND(26) TF_RND(6)
    x0 += ks2; x1 += k0 + 5u;
#undef TF_RND
    o0 = x0; o1 = x1;
}

__device__ inline float gumbel_from_bits(unsigned bits) {
    float f = __uint_as_float((bits >> 9) | 0x3f800000u) - 1.0f;
    float u = (f == 0.0f) ? 1.17549435e-38f : f;
    return -__logf(-__logf(u));
}

__device__ inline unsigned fmap(float f) {   // monotone float -> uint
    unsigned u = __float_as_uint(f);
    return (u & 0x80000000u) ? ~u : (u | 0x80000000u);
}
__device__ inline float unfmap(unsigned u) {
    unsigned v = (u & 0x80000000u) ? (u ^ 0x80000000u) : ~u;
    return __uint_as_float(v);
}

__device__ inline float gelu_exact(float v) {
    return 0.5f * v * (1.0f + erff(v * 0.7071067811865476f));
}

// ---------------- codebook transpose: cbT[d][k] = cb[k][d] ----------------
__global__ void transpose_cb(const float* __restrict__ cb) {
    __shared__ float t[32][33];
    int k0 = blockIdx.x * 32;
    int d0 = blockIdx.y * 32;
    int tx = threadIdx.x, ty = threadIdx.y;  // 32 x 8
    for (int l = 0; l < 32; l += 8)
        t[ty + l][tx] = cb[(k0 + ty + l) * DD + d0 + tx];
    __syncthreads();
    for (int l = 0; l < 32; l += 8)
        g_cbT[(d0 + ty + l) * KK + k0 + tx] = t[tx][ty + l];
}

// ---------------- merged weight transpose: all 4 conv weights --------------
__device__ __forceinline__ void wt_range(int local, const float* __restrict__ w,
                                         int CIN, int COUT, int CIN16, int PAD,
                                         float* __restrict__ dst) {
    int co = local % PAD;
    int rest = local / PAD;
    int ci = rest % CIN16;
    int tap = rest / CIN16;
    float v = 0.0f;
    if (ci < CIN && co < COUT)
        v = w[((size_t)co * CIN + ci) * 3 + tap];
    dst[local] = v;
}
__global__ void transpose_w_all(const float* __restrict__ w1, const float* __restrict__ w2,
                                const float* __restrict__ w3, const float* __restrict__ w4) {
    int idx = blockIdx.x * 256 + threadIdx.x;
    if (idx >= WT_END) return;
    if (idx < WT_O2)      wt_range(idx - WT_O1, w1, 100, 256, 112, 256, g_wT + WT_O1);
    else if (idx < WT_O3) wt_range(idx - WT_O2, w2, 256, 512, 256, 512, g_wT + WT_O2);
    else if (idx < WT_O4) wt_range(idx - WT_O3, w3, 512, 256, 512, 256, g_wT + WT_O3);
    else                  wt_range(idx - WT_O4, w4, 256, 100, 256, 128, g_wT + WT_O4);
}

// ---------------- conv3f: vq_gemm-style conv (float4 smem, wT operand) -----
#define SAS 136
template<int CIN, int COUT, int COUT_PAD, bool FUSE_MSE>
__global__ void __launch_bounds__(256, 2) conv3f(
    const float* __restrict__ in, const float* __restrict__ wT,
    const float* __restrict__ bias, float* __restrict__ out,
    const float* __restrict__ xref)
{
    __shared__ __align__(16) float As[2][16][SAS];
    __shared__ __align__(16) float Bs[2][16][SAS];
    constexpr int NC = (CIN + 15) / 16;
    constexpr int CIN16 = NC * 16;
    constexpr int NS = 3 * NC;
    const int tid = threadIdx.x;
    const int tx = tid & 15, ty = tid >> 4;
    const int r0 = blockIdx.x * 128;
    const int n0 = blockIdx.y * 128;

    const int sm  = tid >> 1;
    const int skq = tid & 1;
    const int aRow = r0 + sm;
    const int tt = aRow & (TT - 1);
    const int bk  = tid >> 4;
    const int bn4 = (tid & 15) * 4;

    unsigned long long acc2[8][4];
#pragma unroll
    for (int i = 0; i < 8; ++i)
#pragma unroll
        for (int j = 0; j < 4; ++j) acc2[i][j] = 0ull;

    float4 av0, av1, bv0, bv1;

    auto LOAD = [&](int s) {
        const int tap = s / NC;
        const int ccc = (s - tap * NC) * 16;
        const int ci = ccc + 8 * skq;
        const int st = tt + tap - 1;
        const bool rv = (st >= 0 && st < TT);
        const float* ap = in + (size_t)(aRow + tap - 1) * CIN + ci;
        if ((CIN % 16 == 0) || (ccc + 16 <= CIN)) {
            if (rv) {
                av0 = *(const float4*)(ap);
                av1 = *(const float4*)(ap + 4);
            } else {
                av0 = make_float4(0.f, 0.f, 0.f, 0.f);
                av1 = av0;
            }
        } else {
            float t0[8];
#pragma unroll
            for (int q = 0; q < 8; ++q)
                t0[q] = (rv && ci + q < CIN) ? ap[q] : 0.0f;
            av0 = make_float4(t0[0], t0[1], t0[2], t0[3]);
            av1 = make_float4(t0[4], t0[5], t0[6], t0[7]);
        }
        const float* bp = wT + (size_t)(tap * CIN16 + ccc + bk) * COUT_PAD + n0;
        bv0 = *(const float4*)(bp + bn4);
        bv1 = *(const float4*)(bp + 64 + bn4);
    };
    auto STORE = [&](int p) {
        As[p][8 * skq + 0][sm] = av0.x;
        As[p][8 * skq + 1][sm] = av0.y;
        As[p][8 * skq + 2][sm] = av0.z;
        As[p][8 * skq + 3][sm] = av0.w;
        As[p][8 * skq + 4][sm] = av1.x;
        As[p][8 * skq + 5][sm] = av1.y;
        As[p][8 * skq + 6][sm] = av1.z;
        As[p][8 * skq + 7][sm] = av1.w;
        *(float4*)&Bs[p][bk][bn4]      = bv0;
        *(float4*)&Bs[p][bk][64 + bn4] = bv1;
    };

    LOAD(0); STORE(0);
    LOAD(1);
    __syncthreads();

    for (int s = 0; s < NS; ++s) {
        const int p = s & 1;
        if (s + 1 < NS) STORE(p ^ 1);
        if (s + 2 < NS) LOAD(s + 2);
#pragma unroll
        for (int kk = 0; kk < 16; ++kk) {
            float4 aL = *(const float4*)&As[p][kk][ty * 4];
            float4 aH = *(const float4*)&As[p][kk][64 + ty * 4];
            float4 bL = *(const float4*)&Bs[p][kk][tx * 4];
            float4 bH = *(const float4*)&Bs[p][kk][64 + tx * 4];
            unsigned long long b2[4], a2;
            pack2(b2[0], bL.x, bL.y);
            pack2(b2[1], bL.z, bL.w);
            pack2(b2[2], bH.x, bH.y);
            pack2(b2[3], bH.z, bH.w);
            float arr[8] = {aL.x, aL.y, aL.z, aL.w, aH.x, aH.y, aH.z, aH.w};
#pragma unroll
            for (int i = 0; i < 8; ++i) {
                splat2(a2, arr[i]);
#pragma unroll
                for (int j = 0; j < 4; ++j) ffma2(acc2[i][j], a2, b2[j]);
            }
        }
        __syncthreads();
    }

    float bl[8];
#pragma unroll
    for (int c = 0; c < 4; ++c) {
        int coL = n0 + tx * 4 + c;
        int coH = n0 + 64 + tx * 4 + c;
        bl[c]     = (COUT % 128 == 0 || coL < COUT) ? bias[coL] : 0.0f;
        bl[4 + c] = (COUT % 128 == 0 || coH < COUT) ? bias[coH] : 0.0f;
    }
    float local = 0.0f;
#pragma unroll
    for (int i = 0; i < 8; ++i) {
        int m = (i < 4) ? (ty * 4 + i) : (64 + ty * 4 + (i - 4));
        int r = r0 + m;
        float v[8];
        unpack2(v[0], v[1], acc2[i][0]);
        unpack2(v[2], v[3], acc2[i][1]);
        unpack2(v[4], v[5], acc2[i][2]);
        unpack2(v[6], v[7], acc2[i][3]);
#pragma unroll
        for (int hf = 0; hf < 2; ++hf) {
            int cobase = n0 + 64 * hf + tx * 4;
            float g0 = gelu_exact(v[4 * hf + 0] + bl[4 * hf + 0]);
            float g1 = gelu_exact(v[4 * hf + 1] + bl[4 * hf + 1]);
            float g2 = gelu_exact(v[4 * hf + 2] + bl[4 * hf + 2]);
            float g3 = gelu_exact(v[4 * hf + 3] + bl[4 * hf + 3]);
            if (FUSE_MSE) {
                float gg[4] = {g0, g1, g2, g3};
#pragma unroll
                for (int c = 0; c < 4; ++c) {
                    int co = cobase + c;
                    if (co < COUT) {
                        float d = xref[(size_t)r * COUT + co] - gg[c];
                        local += d * d;
                    }
                }
            } else if (COUT % 128 == 0) {
                *(float4*)&out[(size_t)r * COUT + cobase] = make_float4(g0, g1, g2, g3);
            } else {
                float gg[4] = {g0, g1, g2, g3};
#pragma unroll
                for (int c = 0; c < 4; ++c) {
                    int co = cobase + c;
                    if (co < COUT) out[(size_t)r * COUT + co] = gg[c];
                }
            }
        }
    }
    if (FUSE_MSE) {
        __shared__ float red[256];
        red[tid] = local;
        __syncthreads();
        for (int s = 128; s > 0; s >>= 1) {
            if (tid < s) red[tid] += red[tid + s];
            __syncthreads();
        }
        if (tid == 0) atomicAdd(&g_acc[1], red[0]);
    }
}

// ---------------- shared pipelined-GEMM body (A rows x cbT cols) ----------
#define GEMM_BODY(AROW_EXPR)                                                   \
    const int sm  = tid >> 1;                                                  \
    const int skq = tid & 1;                                                   \
    const int arow = (AROW_EXPR);                                              \
    const float* aptr = Abase + (size_t)arow * DD + 8 * skq;                   \
    const int bk  = tid >> 4;                                                  \
    const int bn4 = (tid & 15) * 4;                                            \
    const float* bbase = &g_cbT[(size_t)bk * KK + k0];                         \
    unsigned long long acc2[8][4];                                             \
    _Pragma("unroll")                                                          \
    for (int i = 0; i < 8; ++i)                                                \
        _Pragma("unroll")                                                      \
        for (int j = 0; j < 4; ++j) acc2[i][j] = 0ull;                         \
    float4 av0, av1, bv0, bv1;                                                 \
    auto LOAD = [&](int cc) {                                                  \
        av0 = *(const float4*)(aptr + cc);                                     \
        av1 = *(const float4*)(aptr + cc + 4);                                 \
        const float* bp = bbase + (size_t)cc * KK;                             \
        bv0 = *(const float4*)(bp + bn4);                                      \
        bv1 = *(const float4*)(bp + 64 + bn4);                                 \
    };                                                                         \
    auto STORE = [&](int p) {                                                  \
        As[p][8 * skq + 0][sm] = av0.x;                                        \
        As[p][8 * skq + 1][sm] = av0.y;                                        \
        As[p][8 * skq + 2][sm] = av0.z;                                        \
        As[p][8 * skq + 3][sm] = av0.w;                                        \
        As[p][8 * skq + 4][sm] = av1.x;                                        \
        As[p][8 * skq + 5][sm] = av1.y;                                        \
        As[p][8 * skq + 6][sm] = av1.z;                                        \
        As[p][8 * skq + 7][sm] = av1.w;                                        \
        *(float4*)&Bs[p][bk][bn4]      = bv0;                                  \
        *(float4*)&Bs[p][bk][64 + bn4] = bv1;                                  \
    };                                                                         \
    LOAD(0); STORE(0);                                                         \
    LOAD(16);                                                                  \
    __syncthreads();                                                           \
    for (int ch = 0; ch < 32; ++ch) {                                          \
        const int p = ch & 1;                                                  \
        if (ch + 1 < 32) STORE(p ^ 1);                                         \
        if (ch + 2 < 32) LOAD((ch + 2) * 16);                                  \
        _Pragma("unroll")                                                      \
        for (int kk = 0; kk < 16; ++kk) {                                      \
            float4 aL = *(const float4*)&As[p][kk][ty * 4];                    \
            float4 aH = *(const float4*)&As[p][kk][64 + ty * 4];               \
            float4 bL = *(const float4*)&Bs[p][kk][tx * 4];                    \
            float4 bH = *(const float4*)&Bs[p][kk][64 + tx * 4];               \
            unsigned long long b2[4], a2;                                      \
            pack2(b2[0], bL.x, bL.y);                                          \
            pack2(b2[1], bL.z, bL.w);                                          \
            pack2(b2[2], bH.x, bH.y);                                          \
            pack2(b2[3], bH.z, bH.w);                                          \
            float arr[8] = {aL.x, aL.y, aL.z, aL.w, aH.x, aH.y, aH.z, aH.w};   \
            _Pragma("unroll")                                                  \
            for (int i = 0; i < 8; ++i) {                                      \
                splat2(a2, arr[i]);                                            \
                _Pragma("unroll")                                              \
                for (int j = 0; j < 4; ++j) ffma2(acc2[i][j], a2, b2[j]);      \
            }                                                                  \
        }                                                                      \
        __syncthreads();                                                       \
    }

// ---------------- stage-0 GEMM: dot = z · cbT, store to g_dist -------------
__global__ void __launch_bounds__(256, 2) vq_gemm(const float* __restrict__ zin) {
    __shared__ __align__(16) float As[2][16][SAS];
    __shared__ __align__(16) float Bs[2][16][SAS];
    const int tid = threadIdx.x;
    const int tx = tid & 15, ty = tid >> 4;
    const int r0 = blockIdx.x * 64;
    const int k0 = blockIdx.y * 128;
    const float* Abase = zin;
    GEMM_BODY((tid >> 1) < 64 ? (r0 + (tid >> 1)) : (8192 + r0 + (tid >> 1) - 64))

#pragma unroll
    for (int i = 0; i < 8; ++i) {
        int m = (i < 4) ? (ty * 4 + i) : (64 + ty * 4 + (i - 4));
        int bt = (m < 64) ? (r0 + m) : (8192 + r0 + (m - 64));
        float d0, d1, d2, d3;
        unpack2(d0, d1, acc2[i][0]);
        unpack2(d2, d3, acc2[i][1]);
        *(float4*)&g_dist[(size_t)bt * KK + k0 + tx * 4] = make_float4(d0, d1, d2, d3);
        unpack2(d0, d1, acc2[i][2]);
        unpack2(d2, d3, acc2[i][3]);
        *(float4*)&g_dist[(size_t)bt * KK + k0 + 64 + tx * 4] = make_float4(d0, d1, d2, d3);
    }
}

// ---------------- Gram GEMM: G = cb · cbT + csq = diag(G) ------------------
__global__ void __launch_bounds__(256, 2) gram_gemm(const float* __restrict__ cb) {
    __shared__ __align__(16) float As[2][16][SAS];
    __shared__ __align__(16) float Bs[2][16][SAS];
    const int tid = threadIdx.x;
    const int tx = tid & 15, ty = tid >> 4;
    const int r0 = blockIdx.x * 128;
    const int k0 = blockIdx.y * 128;
    const float* Abase = cb;
    GEMM_BODY(r0 + (tid >> 1))

#pragma unroll
    for (int i = 0; i < 8; ++i) {
        int m = (i < 4) ? (ty * 4 + i) : (64 + ty * 4 + (i - 4));
        int row = r0 + m;
        float d0, d1, d2, d3;
        unpack2(d0, d1, acc2[i][0]);
        unpack2(d2, d3, acc2[i][1]);
        *(float4*)&g_G[(size_t)row * KK + k0 + tx * 4] = make_float4(d0, d1, d2, d3);
        if (r0 == k0) {
            int c0 = k0 + tx * 4;
            if (row >= c0 && row < c0 + 4) {
                float dd[4] = {d0, d1, d2, d3};
                g_csq[row] = dd[row - c0];
            }
        }
        unpack2(d0, d1, acc2[i][2]);
        unpack2(d2, d3, acc2[i][3]);
        *(float4*)&g_G[(size_t)row * KK + k0 + 64 + tx * 4] = make_float4(d0, d1, d2, d3);
        if (r0 == k0) {
            int c1 = k0 + 64 + tx * 4;
            if (row >= c1 && row < c1 + 4) {
                float dd[4] = {d0, d1, d2, d3};
                g_csq[row] = dd[row - c1];
            }
        }
    }
}

// ---------------- init_small: fk keys, window, accumulators ---------------
__global__ void init_small() {
    int tid = threadIdx.x;  // 32
    if (tid < 8) {
        unsigned a, b;
        tf2x32(0u, 42u, 0u, (unsigned)tid, a, b);
        g_fk[2 * tid] = a;
        g_fk[2 * tid + 1] = b;
    }
    if (tid < 2) g_acc[tid] = 0.0f;
    if (tid == 0) {
        float ghi = gumbel_from_bits(0xFFFFFFFFu);
        float glo = gumbel_from_bits(0u);
        g_window = (ghi - glo) + 0.5f;
    }
}

// ---------------- pick: rn2 + all 8 VQ stages per row, one block per bt ----
__global__ void __launch_bounds__(256) vq_pick(const float* __restrict__ cb) {
    const int bt = blockIdx.x;
    const int tid = threadIdx.x;
    __shared__ unsigned sMaxU;
    __shared__ unsigned long long sBest;
    __shared__ float sDotSel;
    __shared__ int sSel[8];
    __shared__ float red[256];

    if (tid == 0) { sMaxU = 0u; sBest = 0ull; }

    // fused rn2 = ||z_bt||^2
    {
        float z0 = g_res[(size_t)bt * DD + tid];
        float z1 = g_res[(size_t)bt * DD + tid + 256];
        red[tid] = z0 * z0 + z1 * z1;
    }

    float d[4], cs[4], s[4];
    const float* drow = &g_dist[(size_t)bt * KK];
#pragma unroll
    for (int j = 0; j < 4; ++j) {
        d[j] = drow[tid + 256 * j];
        cs[j] = g_csq[tid + 256 * j];
        s[j] = fmaf(20.0f, d[j], -10.0f * cs[j]);
    }
    __syncthreads();
    for (int ss = 128; ss > 0; ss >>= 1) {
        if (tid < ss) red[tid] += red[tid + ss];
        __syncthreads();
    }
    const float win = g_window;
    const unsigned btL = (bt < 8192) ? (unsigned)bt : (unsigned)(bt - 8192);
    const bool hi = (bt >= 8192);
    float rn2 = (tid == 0) ? red[0] : 0.0f;
    float commit = 0.0f;

    for (int i = 0; i < 8; ++i) {
        float lm = fmaxf(fmaxf(s[0], s[1]), fmaxf(s[2], s[3]));
#pragma unroll
        for (int off = 16; off > 0; off >>= 1)
            lm = fmaxf(lm, __shfl_xor_sync(0xffffffffu, lm, off));
        if ((tid & 31) == 0) atomicMax(&sMaxU, fmap(lm));
        __syncthreads();
        const float tau = unfmap(sMaxU) - win;

        const unsigned fk0 = g_fk[2 * i], fk1 = g_fk[2 * i + 1];
#pragma unroll
        for (int j = 0; j < 4; ++j) {
            if (s[j] >= tau) {
                unsigned k = (unsigned)(tid + 256 * j);
                unsigned n = btL * 1024u + k;
                unsigned b0, b1;
                tf2x32(fk0, fk1, n, n + HALF_N, b0, b1);
                float g = gumbel_from_bits(hi ? b1 : b0);
                float sc = s[j] + g;
                unsigned long long cand =
                    ((unsigned long long)fmap(sc) << 32) | (unsigned long long)(~k);
                atomicMax(&sBest, cand);
            }
        }
        __syncthreads();
        const unsigned sel = ~(unsigned)(sBest & 0xffffffffull);
        if (tid == (int)(sel & 255u)) sDotSel = d[sel >> 8];
        __syncthreads();
        if (tid == 0) {
            float rn2n = rn2 - 2.0f * sDotSel + g_csq[sel];
            commit += rn2n;
            rn2 = rn2n;
            sSel[i] = (int)sel;
            sMaxU = 0u;
            sBest = 0ull;
        }
        if (i < 7) {
            const float* grow = &g_G[(size_t)sel * KK];
#pragma unroll
            for (int j = 0; j < 4; ++j) {
                d[j] -= grow[tid + 256 * j];
                s[j] = fmaf(20.0f, d[j], -10.0f * cs[j]);
            }
        }
        __syncthreads();
    }

    float a0 = 0.0f, a1 = 0.0f;
#pragma unroll
    for (int i = 0; i < 8; ++i) {
        const float* cp = cb + (size_t)sSel[i] * DD;
        a0 += cp[tid];
        a1 += cp[tid + 256];
    }
    g_qout[(size_t)bt * DD + tid] = a0;
    g_qout[(size_t)bt * DD + tid + 256] = a1;

    if (tid == 0) atomicAdd(&g_acc[0], commit);
}

__global__ void finalize_k(float* __restrict__ out) {
    out[0] = g_acc[1] * (1.0f / 1638400.0f)      // mse /(BT*100)
           + g_acc[0] * (1.0f / 67108864.0f);    // commit /(8*BT*512)
}

// ---------------- streams/events (created once, pre-baseline) --------------
struct SideStream {
    cudaStream_t s;
    cudaEvent_t fork, join;
    SideStream() {
        cudaStreamCreateWithFlags(&s, cudaStreamNonBlocking);
        cudaEventCreateWithFlags(&fork, cudaEventDisableTiming);
        cudaEventCreateWithFlags(&join, cudaEventDisableTiming);
    }
};
static SideStream g_ss;

// ---------------- host launcher (graph-capturable, alloc-free) -------------
extern "C" void kernel_launch(void* const* d_in, const int* in_sizes, int n_in,
                              void* d_out, int out_size) {
    const float* x   = (const float*)d_in[0];
    const float* ew1 = (const float*)d_in[1];
    const float* eb1 = (const float*)d_in[2];
    const float* ew2 = (const float*)d_in[3];
    const float* eb2 = (const float*)d_in[4];
    const float* cb  = (const float*)d_in[5];
    const float* dw1 = (const float*)d_in[6];
    const float* db1 = (const float*)d_in[7];
    const float* dw2 = (const float*)d_in[8];
    const float* db2 = (const float*)d_in[9];
    float* out = (float*)d_out;

    float *h1, *res, *qout, *wT;
    cudaGetSymbolAddress((void**)&h1,   g_h1);
    cudaGetSymbolAddress((void**)&res,  g_res);
    cudaGetSymbolAddress((void**)&qout, g_qout);
    cudaGetSymbolAddress((void**)&wT,   g_wT);

    // fork side branch: cbT -> Gram(+csq) -> init_small (independent of convs)
    cudaEventRecord(g_ss.fork, 0);
    cudaStreamWaitEvent(g_ss.s, g_ss.fork, 0);
    transpose_cb<<<dim3(KK / 32, DD / 32), dim3(32, 8), 0, g_ss.s>>>(cb);
    gram_gemm<<<dim3(8, 8), 256, 0, g_ss.s>>>(cb);
    init_small<<<1, 32, 0, g_ss.s>>>();
    cudaEventRecord(g_ss.join, g_ss.s);

    // main branch: weights -> encoder
    transpose_w_all<<<(WT_END + 255) / 256, 256>>>(ew1, ew2, dw1, dw2);
    conv3f<100, 256, 256, false><<<dim3(128, 2), 256>>>(x,  wT + WT_O1, eb1, h1,  nullptr);
    conv3f<256, 512, 512, false><<<dim3(128, 4), 256>>>(h1, wT + WT_O2, eb2, res, nullptr);

    // join: vq needs cbT / G / csq / fk / window
    cudaStreamWaitEvent(0, g_ss.join, 0);

    // residual VQ: one GEMM + per-row 8-stage walk (rn2 fused into pick)
    vq_gemm<<<dim3(128, 8), 256>>>(res);
    vq_pick<<<BT, 256>>>(cb);

    // decoder (+ fused MSE on the last conv)
    conv3f<512, 256, 256, false><<<dim3(128, 2), 256>>>(qout, wT + WT_O3, db1, h1, nullptr);
    conv3f<256, 100, 128, true ><<<dim3(128, 1), 256>>>(h1,  wT + WT_O4, db2, nullptr, x);

    finalize_k<<<1, 1>>>(out);
}

// round 12
// speedup vs baseline: 4.6050x; 1.2394x over previous
#include <cuda_runtime.h>
#include <cstdint>

#define TT 2048
#define BT 16384
#define DD 512
#define KK 1024
#define HALF_N 8388608u   // BT*KK/2

// ---------------- scratch (static device allocations only) ----------------
__device__ float g_h1[BT * 256];
__device__ float g_res[BT * DD];          // encoder output z
__device__ float g_cbT[DD * KK];          // codebook transposed [d][k]
__device__ float g_dist[BT * KK];         // dot products <z, c_k>  (64MB)
__device__ float g_G[KK * KK];            // Gram matrix cb·cbT     (4MB)
__device__ float g_csq[KK];               // = diag(G)
__device__ float g_wT[1048576];           // transposed padded weights (4MB)
__device__ float g_U[3 * KK * 256];       // U[tap][k][co] = cb·W1_tap^T (3MB)
__device__ int   g_sel[BT * 8];           // selected code per row per stage
__device__ unsigned g_fk[16];             // per-stage threefry fold-in keys
__device__ float g_window;                // gumbel hi-lo window + margin
__device__ float g_acc[2];   // [0]=commit sum, [1]=mse sum

// wT offsets (floats): enc1 3*112*256, enc2 3*256*512, dec1 3*512*256, dec2 3*256*128
#define WT_O1 0
#define WT_O2 86016
#define WT_O3 479232
#define WT_O4 872448
#define WT_END 970752

// ---------------- packed f32x2 helpers ----------------
__device__ __forceinline__ void splat2(unsigned long long& d, float a) {
    asm("mov.b64 %0, {%1, %1};" : "=l"(d) : "f"(a));
}
__device__ __forceinline__ void pack2(unsigned long long& d, float a, float b) {
    asm("mov.b64 %0, {%1, %2};" : "=l"(d) : "f"(a), "f"(b));
}
__device__ __forceinline__ void unpack2(float& a, float& b, unsigned long long d) {
    asm("mov.b64 {%0, %1}, %2;" : "=f"(a), "=f"(b) : "l"(d));
}
__device__ __forceinline__ void ffma2(unsigned long long& acc,
                                      unsigned long long a, unsigned long long b) {
    asm("fma.rn.f32x2 %0, %1, %2, %0;" : "+l"(acc) : "l"(a), "l"(b));
}

// ---------------- JAX threefry2x32 (exact) ----------------
__host__ __device__ inline void tf2x32(unsigned k0, unsigned k1,
                                       unsigned x0, unsigned x1,
                                       unsigned& o0, unsigned& o1) {
    unsigned ks2 = k0 ^ k1 ^ 0x1BD11BDAu;
    x0 += k0; x1 += k1;
#define TF_RND(r) { x0 += x1; x1 = (x1 << (r)) | (x1 >> (32 - (r))); x1 ^= x0; }
    TF_RND(13) TF_RND(15) TF_RND(26) TF_RND(6)
    x0 += k1;  x1 += ks2 + 1u;
    TF_RND(17) TF_RND(29) TF_RND(16) TF_RND(24)
    x0 += ks2; x1 += k0 + 2u;
    TF_RND(13) TF_RND(15) TF_RND(26) TF_RND(6)
    x0 += k0;  x1 += k1 + 3u;
    TF_RND(17) TF_RND(29) TF_RND(16) TF_RND(24)
    x0 += k1;  x1 += ks2 + 4u;
    TF_RND(13) TF_RND(15) TF_RND(26) TF_RND(6)
    x0 += ks2; x1 += k0 + 5u;
#undef TF_RND
    o0 = x0; o1 = x1;
}

__device__ inline float gumbel_from_bits(unsigned bits) {
    float f = __uint_as_float((bits >> 9) | 0x3f800000u) - 1.0f;
    float u = (f == 0.0f) ? 1.17549435e-38f : f;
    return -__logf(-__logf(u));
}

__device__ inline unsigned fmap(float f) {   // monotone float -> uint
    unsigned u = __float_as_uint(f);
    return (u & 0x80000000u) ? ~u : (u | 0x80000000u);
}
__device__ inline float unfmap(unsigned u) {
    unsigned v = (u & 0x80000000u) ? (u ^ 0x80000000u) : ~u;
    return __uint_as_float(v);
}

__device__ inline float gelu_exact(float v) {
    return 0.5f * v * (1.0f + erff(v * 0.7071067811865476f));
}

// ---------------- codebook transpose: cbT[d][k] = cb[k][d] ----------------
__global__ void transpose_cb(const float* __restrict__ cb) {
    __shared__ float t[32][33];
    int k0 = blockIdx.x * 32;
    int d0 = blockIdx.y * 32;
    int tx = threadIdx.x, ty = threadIdx.y;  // 32 x 8
    for (int l = 0; l < 32; l += 8)
        t[ty + l][tx] = cb[(k0 + ty + l) * DD + d0 + tx];
    __syncthreads();
    for (int l = 0; l < 32; l += 8)
        g_cbT[(d0 + ty + l) * KK + k0 + tx] = t[tx][ty + l];
}

// ---------------- merged weight transpose: all 4 conv weights --------------
__device__ __forceinline__ void wt_range(int local, const float* __restrict__ w,
                                         int CIN, int COUT, int CIN16, int PAD,
                                         float* __restrict__ dst) {
    int co = local % PAD;
    int rest = local / PAD;
    int ci = rest % CIN16;
    int tap = rest / CIN16;
    float v = 0.0f;
    if (ci < CIN && co < COUT)
        v = w[((size_t)co * CIN + ci) * 3 + tap];
    dst[local] = v;
}
__global__ void transpose_w_all(const float* __restrict__ w1, const float* __restrict__ w2,
                                const float* __restrict__ w3, const float* __restrict__ w4) {
    int idx = blockIdx.x * 256 + threadIdx.x;
    if (idx >= WT_END) return;
    if (idx < WT_O2)      wt_range(idx - WT_O1, w1, 100, 256, 112, 256, g_wT + WT_O1);
    else if (idx < WT_O3) wt_range(idx - WT_O2, w2, 256, 512, 256, 512, g_wT + WT_O2);
    else if (idx < WT_O4) wt_range(idx - WT_O3, w3, 512, 256, 512, 256, g_wT + WT_O3);
    else                  wt_range(idx - WT_O4, w4, 256, 100, 256, 128, g_wT + WT_O4);
}

// ---------------- conv3f: vq_gemm-style conv (float4 smem, wT operand) -----
#define SAS 136
template<int CIN, int COUT, int COUT_PAD, bool FUSE_MSE>
__global__ void __launch_bounds__(256, 2) conv3f(
    const float* __restrict__ in, const float* __restrict__ wT,
    const float* __restrict__ bias, float* __restrict__ out,
    const float* __restrict__ xref)
{
    __shared__ __align__(16) float As[2][16][SAS];
    __shared__ __align__(16) float Bs[2][16][SAS];
    constexpr int NC = (CIN + 15) / 16;
    constexpr int CIN16 = NC * 16;
    constexpr int NS = 3 * NC;
    const int tid = threadIdx.x;
    const int tx = tid & 15, ty = tid >> 4;
    const int r0 = blockIdx.x * 128;
    const int n0 = blockIdx.y * 128;

    const int sm  = tid >> 1;
    const int skq = tid & 1;
    const int aRow = r0 + sm;
    const int tt = aRow & (TT - 1);
    const int bk  = tid >> 4;
    const int bn4 = (tid & 15) * 4;

    unsigned long long acc2[8][4];
#pragma unroll
    for (int i = 0; i < 8; ++i)
#pragma unroll
        for (int j = 0; j < 4; ++j) acc2[i][j] = 0ull;

    float4 av0, av1, bv0, bv1;

    auto LOAD = [&](int s) {
        const int tap = s / NC;
        const int ccc = (s - tap * NC) * 16;
        const int ci = ccc + 8 * skq;
        const int st = tt + tap - 1;
        const bool rv = (st >= 0 && st < TT);
        const float* ap = in + (size_t)(aRow + tap - 1) * CIN + ci;
        if ((CIN % 16 == 0) || (ccc + 16 <= CIN)) {
            if (rv) {
                av0 = *(const float4*)(ap);
                av1 = *(const float4*)(ap + 4);
            } else {
                av0 = make_float4(0.f, 0.f, 0.f, 0.f);
                av1 = av0;
            }
        } else {
            float t0[8];
#pragma unroll
            for (int q = 0; q < 8; ++q)
                t0[q] = (rv && ci + q < CIN) ? ap[q] : 0.0f;
            av0 = make_float4(t0[0], t0[1], t0[2], t0[3]);
            av1 = make_float4(t0[4], t0[5], t0[6], t0[7]);
        }
        const float* bp = wT + (size_t)(tap * CIN16 + ccc + bk) * COUT_PAD + n0;
        bv0 = *(const float4*)(bp + bn4);
        bv1 = *(const float4*)(bp + 64 + bn4);
    };
    auto STORE = [&](int p) {
        As[p][8 * skq + 0][sm] = av0.x;
        As[p][8 * skq + 1][sm] = av0.y;
        As[p][8 * skq + 2][sm] = av0.z;
        As[p][8 * skq + 3][sm] = av0.w;
        As[p][8 * skq + 4][sm] = av1.x;
        As[p][8 * skq + 5][sm] = av1.y;
        As[p][8 * skq + 6][sm] = av1.z;
        As[p][8 * skq + 7][sm] = av1.w;
        *(float4*)&Bs[p][bk][bn4]      = bv0;
        *(float4*)&Bs[p][bk][64 + bn4] = bv1;
    };

    LOAD(0); STORE(0);
    LOAD(1);
    __syncthreads();

    for (int s = 0; s < NS; ++s) {
        const int p = s & 1;
        if (s + 1 < NS) STORE(p ^ 1);
        if (s + 2 < NS) LOAD(s + 2);
#pragma unroll
        for (int kk = 0; kk < 16; ++kk) {
            float4 aL = *(const float4*)&As[p][kk][ty * 4];
            float4 aH = *(const float4*)&As[p][kk][64 + ty * 4];
            float4 bL = *(const float4*)&Bs[p][kk][tx * 4];
            float4 bH = *(const float4*)&Bs[p][kk][64 + tx * 4];
            unsigned long long b2[4], a2;
            pack2(b2[0], bL.x, bL.y);
            pack2(b2[1], bL.z, bL.w);
            pack2(b2[2], bH.x, bH.y);
            pack2(b2[3], bH.z, bH.w);
            float arr[8] = {aL.x, aL.y, aL.z, aL.w, aH.x, aH.y, aH.z, aH.w};
#pragma unroll
            for (int i = 0; i < 8; ++i) {
                splat2(a2, arr[i]);
#pragma unroll
                for (int j = 0; j < 4; ++j) ffma2(acc2[i][j], a2, b2[j]);
            }
        }
        __syncthreads();
    }

    float bl[8];
#pragma unroll
    for (int c = 0; c < 4; ++c) {
        int coL = n0 + tx * 4 + c;
        int coH = n0 + 64 + tx * 4 + c;
        bl[c]     = (COUT % 128 == 0 || coL < COUT) ? bias[coL] : 0.0f;
        bl[4 + c] = (COUT % 128 == 0 || coH < COUT) ? bias[coH] : 0.0f;
    }
    float local = 0.0f;
#pragma unroll
    for (int i = 0; i < 8; ++i) {
        int m = (i < 4) ? (ty * 4 + i) : (64 + ty * 4 + (i - 4));
        int r = r0 + m;
        float v[8];
        unpack2(v[0], v[1], acc2[i][0]);
        unpack2(v[2], v[3], acc2[i][1]);
        unpack2(v[4], v[5], acc2[i][2]);
        unpack2(v[6], v[7], acc2[i][3]);
#pragma unroll
        for (int hf = 0; hf < 2; ++hf) {
            int cobase = n0 + 64 * hf + tx * 4;
            float g0 = gelu_exact(v[4 * hf + 0] + bl[4 * hf + 0]);
            float g1 = gelu_exact(v[4 * hf + 1] + bl[4 * hf + 1]);
            float g2 = gelu_exact(v[4 * hf + 2] + bl[4 * hf + 2]);
            float g3 = gelu_exact(v[4 * hf + 3] + bl[4 * hf + 3]);
            if (FUSE_MSE) {
                float gg[4] = {g0, g1, g2, g3};
#pragma unroll
                for (int c = 0; c < 4; ++c) {
                    int co = cobase + c;
                    if (co < COUT) {
                        float d = xref[(size_t)r * COUT + co] - gg[c];
                        local += d * d;
                    }
                }
            } else if (COUT % 128 == 0) {
                *(float4*)&out[(size_t)r * COUT + cobase] = make_float4(g0, g1, g2, g3);
            } else {
                float gg[4] = {g0, g1, g2, g3};
#pragma unroll
                for (int c = 0; c < 4; ++c) {
                    int co = cobase + c;
                    if (co < COUT) out[(size_t)r * COUT + co] = gg[c];
                }
            }
        }
    }
    if (FUSE_MSE) {
        __shared__ float red[256];
        red[tid] = local;
        __syncthreads();
        for (int s = 128; s > 0; s >>= 1) {
            if (tid < s) red[tid] += red[tid + s];
            __syncthreads();
        }
        if (tid == 0) atomicAdd(&g_acc[1], red[0]);
    }
}

// ---------------- shared pipelined-GEMM body (generalized B) --------------
#define GEMM_BODY(AROW_EXPR, BBASE, BSTRIDE)                                   \
    const int sm  = tid >> 1;                                                  \
    const int skq = tid & 1;                                                   \
    const int arow = (AROW_EXPR);                                              \
    const float* aptr = Abase + (size_t)arow * DD + 8 * skq;                   \
    const int bk  = tid >> 4;                                                  \
    const int bn4 = (tid & 15) * 4;                                            \
    const float* bbase = (BBASE) + (size_t)bk * (BSTRIDE) + k0;                \
    unsigned long long acc2[8][4];                                             \
    _Pragma("unroll")                                                          \
    for (int i = 0; i < 8; ++i)                                                \
        _Pragma("unroll")                                                      \
        for (int j = 0; j < 4; ++j) acc2[i][j] = 0ull;                         \
    float4 av0, av1, bv0, bv1;                                                 \
    auto LOAD = [&](int cc) {                                                  \
        av0 = *(const float4*)(aptr + cc);                                     \
        av1 = *(const float4*)(aptr + cc + 4);                                 \
        const float* bp = bbase + (size_t)cc * (BSTRIDE);                      \
        bv0 = *(const float4*)(bp + bn4);                                      \
        bv1 = *(const float4*)(bp + 64 + bn4);                                 \
    };                                                                         \
    auto STORE = [&](int p) {                                                  \
        As[p][8 * skq + 0][sm] = av0.x;                                        \
        As[p][8 * skq + 1][sm] = av0.y;                                        \
        As[p][8 * skq + 2][sm] = av0.z;                                        \
        As[p][8 * skq + 3][sm] = av0.w;                                        \
        As[p][8 * skq + 4][sm] = av1.x;                                        \
        As[p][8 * skq + 5][sm] = av1.y;                                        \
        As[p][8 * skq + 6][sm] = av1.z;                                        \
        As[p][8 * skq + 7][sm] = av1.w;                                        \
        *(float4*)&Bs[p][bk][bn4]      = bv0;                                  \
        *(float4*)&Bs[p][bk][64 + bn4] = bv1;                                  \
    };                                                                         \
    LOAD(0); STORE(0);                                                         \
    LOAD(16);                                                                  \
    __syncthreads();                                                           \
    for (int ch = 0; ch < 32; ++ch) {                                          \
        const int p = ch & 1;                                                  \
        if (ch + 1 < 32) STORE(p ^ 1);                                         \
        if (ch + 2 < 32) LOAD((ch + 2) * 16);                                  \
        _Pragma("unroll")                                                      \
        for (int kk = 0; kk < 16; ++kk) {                                      \
            float4 aL = *(const float4*)&As[p][kk][ty * 4];                    \
            float4 aH = *(const float4*)&As[p][kk][64 + ty * 4];               \
            float4 bL = *(const float4*)&Bs[p][kk][tx * 4];                    \
            float4 bH = *(const float4*)&Bs[p][kk][64 + tx * 4];               \
            unsigned long long b2[4], a2;                                      \
            pack2(b2[0], bL.x, bL.y);                                          \
            pack2(b2[1], bL.z, bL.w);                                          \
            pack2(b2[2], bH.x, bH.y);                                          \
            pack2(b2[3], bH.z, bH.w);                                          \
            float arr[8] = {aL.x, aL.y, aL.z, aL.w, aH.x, aH.y, aH.z, aH.w};   \
            _Pragma("unroll")                                                  \
            for (int i = 0; i < 8; ++i) {                                      \
                splat2(a2, arr[i]);                                            \
                _Pragma("unroll")                                              \
                for (int j = 0; j < 4; ++j) ffma2(acc2[i][j], a2, b2[j]);      \
            }                                                                  \
        }                                                                      \
        __syncthreads();                                                       \
    }

// ---------------- stage-0 GEMM: dot = z · cbT, store to g_dist -------------
__global__ void __launch_bounds__(256, 2) vq_gemm(const float* __restrict__ zin) {
    __shared__ __align__(16) float As[2][16][SAS];
    __shared__ __align__(16) float Bs[2][16][SAS];
    const int tid = threadIdx.x;
    const int tx = tid & 15, ty = tid >> 4;
    const int r0 = blockIdx.x * 64;
    const int k0 = blockIdx.y * 128;
    const float* Abase = zin;
    GEMM_BODY((tid >> 1) < 64 ? (r0 + (tid >> 1)) : (8192 + r0 + (tid >> 1) - 64),
              g_cbT, KK)

#pragma unroll
    for (int i = 0; i < 8; ++i) {
        int m = (i < 4) ? (ty * 4 + i) : (64 + ty * 4 + (i - 4));
        int bt = (m < 64) ? (r0 + m) : (8192 + r0 + (m - 64));
        float d0, d1, d2, d3;
        unpack2(d0, d1, acc2[i][0]);
        unpack2(d2, d3, acc2[i][1]);
        *(float4*)&g_dist[(size_t)bt * KK + k0 + tx * 4] = make_float4(d0, d1, d2, d3);
        unpack2(d0, d1, acc2[i][2]);
        unpack2(d2, d3, acc2[i][3]);
        *(float4*)&g_dist[(size_t)bt * KK + k0 + 64 + tx * 4] = make_float4(d0, d1, d2, d3);
    }
}

// ---------------- Gram GEMM: G = cb · cbT + csq = diag(G) ------------------
__global__ void __launch_bounds__(256, 2) gram_gemm(const float* __restrict__ cb) {
    __shared__ __align__(16) float As[2][16][SAS];
    __shared__ __align__(16) float Bs[2][16][SAS];
    const int tid = threadIdx.x;
    const int tx = tid & 15, ty = tid >> 4;
    const int r0 = blockIdx.x * 128;
    const int k0 = blockIdx.y * 128;
    const float* Abase = cb;
    GEMM_BODY(r0 + (tid >> 1), g_cbT, KK)

#pragma unroll
    for (int i = 0; i < 8; ++i) {
        int m = (i < 4) ? (ty * 4 + i) : (64 + ty * 4 + (i - 4));
        int row = r0 + m;
        float d0, d1, d2, d3;
        unpack2(d0, d1, acc2[i][0]);
        unpack2(d2, d3, acc2[i][1]);
        *(float4*)&g_G[(size_t)row * KK + k0 + tx * 4] = make_float4(d0, d1, d2, d3);
        if (r0 == k0) {
            int c0 = k0 + tx * 4;
            if (row >= c0 && row < c0 + 4) {
                float dd[4] = {d0, d1, d2, d3};
                g_csq[row] = dd[row - c0];
            }
        }
        unpack2(d0, d1, acc2[i][2]);
        unpack2(d2, d3, acc2[i][3]);
        *(float4*)&g_G[(size_t)row * KK + k0 + 64 + tx * 4] = make_float4(d0, d1, d2, d3);
        if (r0 == k0) {
            int c1 = k0 + 64 + tx * 4;
            if (row >= c1 && row < c1 + 4) {
                float dd[4] = {d0, d1, d2, d3};
                g_csq[row] = dd[row - c1];
            }
        }
    }
}

// ---------------- U GEMM: U[tap] = cb · W1_tap^T  (grid 8 x 2 x 3) ---------
__global__ void __launch_bounds__(256, 2) u_gemm(const float* __restrict__ cb) {
    __shared__ __align__(16) float As[2][16][SAS];
    __shared__ __align__(16) float Bs[2][16][SAS];
    const int tid = threadIdx.x;
    const int tx = tid & 15, ty = tid >> 4;
    const int r0 = blockIdx.x * 128;       // codebook rows
    const int k0 = blockIdx.y * 128;       // output channels
    const int tap = blockIdx.z;
    const float* Abase = cb;
    const float* wt3 = g_wT + WT_O3 + (size_t)tap * 512 * 256;
    GEMM_BODY(r0 + (tid >> 1), wt3, 256)

#pragma unroll
    for (int i = 0; i < 8; ++i) {
        int m = (i < 4) ? (ty * 4 + i) : (64 + ty * 4 + (i - 4));
        int row = r0 + m;
        float* urow = &g_U[((size_t)tap * KK + row) * 256 + k0];
        float d0, d1, d2, d3;
        unpack2(d0, d1, acc2[i][0]);
        unpack2(d2, d3, acc2[i][1]);
        *(float4*)(urow + tx * 4) = make_float4(d0, d1, d2, d3);
        unpack2(d0, d1, acc2[i][2]);
        unpack2(d2, d3, acc2[i][3]);
        *(float4*)(urow + 64 + tx * 4) = make_float4(d0, d1, d2, d3);
    }
}

// ---------------- init_small: fk keys, window, accumulators ---------------
__global__ void init_small() {
    int tid = threadIdx.x;  // 32
    if (tid < 8) {
        unsigned a, b;
        tf2x32(0u, 42u, 0u, (unsigned)tid, a, b);
        g_fk[2 * tid] = a;
        g_fk[2 * tid + 1] = b;
    }
    if (tid < 2) g_acc[tid] = 0.0f;
    if (tid == 0) {
        float ghi = gumbel_from_bits(0xFFFFFFFFu);
        float glo = gumbel_from_bits(0u);
        g_window = (ghi - glo) + 0.5f;
    }
}

// ---------------- pick: rn2 + all 8 VQ stages per row -> g_sel -------------
__global__ void __launch_bounds__(256) vq_pick() {
    const int bt = blockIdx.x;
    const int tid = threadIdx.x;
    __shared__ unsigned sMaxU;
    __shared__ unsigned long long sBest;
    __shared__ float sDotSel;
    __shared__ int sSel[8];
    __shared__ float red[256];

    if (tid == 0) { sMaxU = 0u; sBest = 0ull; }

    // fused rn2 = ||z_bt||^2
    {
        float z0 = g_res[(size_t)bt * DD + tid];
        float z1 = g_res[(size_t)bt * DD + tid + 256];
        red[tid] = z0 * z0 + z1 * z1;
    }

    float d[4], cs[4], s[4];
    const float* drow = &g_dist[(size_t)bt * KK];
#pragma unroll
    for (int j = 0; j < 4; ++j) {
        d[j] = drow[tid + 256 * j];
        cs[j] = g_csq[tid + 256 * j];
        s[j] = fmaf(20.0f, d[j], -10.0f * cs[j]);
    }
    __syncthreads();
    for (int ss = 128; ss > 0; ss >>= 1) {
        if (tid < ss) red[tid] += red[tid + ss];
        __syncthreads();
    }
    const float win = g_window;
    const unsigned btL = (bt < 8192) ? (unsigned)bt : (unsigned)(bt - 8192);
    const bool hi = (bt >= 8192);
    float rn2 = (tid == 0) ? red[0] : 0.0f;
    float commit = 0.0f;

    for (int i = 0; i < 8; ++i) {
        float lm = fmaxf(fmaxf(s[0], s[1]), fmaxf(s[2], s[3]));
#pragma unroll
        for (int off = 16; off > 0; off >>= 1)
            lm = fmaxf(lm, __shfl_xor_sync(0xffffffffu, lm, off));
        if ((tid & 31) == 0) atomicMax(&sMaxU, fmap(lm));
        __syncthreads();
        const float tau = unfmap(sMaxU) - win;

        const unsigned fk0 = g_fk[2 * i], fk1 = g_fk[2 * i + 1];
#pragma unroll
        for (int j = 0; j < 4; ++j) {
            if (s[j] >= tau) {
                unsigned k = (unsigned)(tid + 256 * j);
                unsigned n = btL * 1024u + k;
                unsigned b0, b1;
                tf2x32(fk0, fk1, n, n + HALF_N, b0, b1);
                float g = gumbel_from_bits(hi ? b1 : b0);
                float sc = s[j] + g;
                unsigned long long cand =
                    ((unsigned long long)fmap(sc) << 32) | (unsigned long long)(~k);
                atomicMax(&sBest, cand);
            }
        }
        __syncthreads();
        const unsigned sel = ~(unsigned)(sBest & 0xffffffffull);
        if (tid == (int)(sel & 255u)) sDotSel = d[sel >> 8];
        __syncthreads();
        if (tid == 0) {
            float rn2n = rn2 - 2.0f * sDotSel + g_csq[sel];
            commit += rn2n;
            rn2 = rn2n;
            sSel[i] = (int)sel;
            sMaxU = 0u;
            sBest = 0ull;
        }
        if (i < 7) {
            const float* grow = &g_G[(size_t)sel * KK];
#pragma unroll
            for (int j = 0; j < 4; ++j) {
                d[j] -= grow[tid + 256 * j];
                s[j] = fmaf(20.0f, d[j], -10.0f * cs[j]);
            }
        }
        __syncthreads();
    }

    if (tid < 8) g_sel[bt * 8 + tid] = sSel[tid];
    if (tid == 0) atomicAdd(&g_acc[0], commit);
}

// ---------------- dec1 gather: h1[bt] = gelu(bias + sum U rows) ------------
__global__ void __launch_bounds__(256) dec1_gather(const float* __restrict__ bias) {
    const int bt = blockIdx.x;
    const int c = threadIdx.x;   // 256 output channels
    __shared__ int sIdx[24];

    if (c < 24) {
        int tap = c >> 3, i = c & 7;
        int t = bt & (TT - 1);
        int st = t + tap - 1;
        int idx = -1;
        if (st >= 0 && st < TT)
            idx = tap * KK + g_sel[(bt + tap - 1) * 8 + i];
        sIdx[c] = idx;
    }
    __syncthreads();

    float acc = bias[c];
#pragma unroll
    for (int j = 0; j < 24; ++j) {
        int idx = sIdx[j];
        if (idx >= 0) acc += g_U[(size_t)idx * 256 + c];
    }
    g_h1[(size_t)bt * 256 + c] = gelu_exact(acc);
}

__global__ void finalize_k(float* __restrict__ out) {
    out[0] = g_acc[1] * (1.0f / 1638400.0f)      // mse /(BT*100)
           + g_acc[0] * (1.0f / 67108864.0f);    // commit /(8*BT*512)
}

// ---------------- streams/events (created once, pre-baseline) --------------
struct SideStream {
    cudaStream_t s;
    cudaEvent_t fork, wtev, join1, join2;
    SideStream() {
        cudaStreamCreateWithFlags(&s, cudaStreamNonBlocking);
        cudaEventCreateWithFlags(&fork, cudaEventDisableTiming);
        cudaEventCreateWithFlags(&wtev, cudaEventDisableTiming);
        cudaEventCreateWithFlags(&join1, cudaEventDisableTiming);
        cudaEventCreateWithFlags(&join2, cudaEventDisableTiming);
    }
};
static SideStream g_ss;

// ---------------- host launcher (graph-capturable, alloc-free) -------------
extern "C" void kernel_launch(void* const* d_in, const int* in_sizes, int n_in,
                              void* d_out, int out_size) {
    const float* x   = (const float*)d_in[0];
    const float* ew1 = (const float*)d_in[1];
    const float* eb1 = (const float*)d_in[2];
    const float* ew2 = (const float*)d_in[3];
    const float* eb2 = (const float*)d_in[4];
    const float* cb  = (const float*)d_in[5];
    const float* dw1 = (const float*)d_in[6];
    const float* db1 = (const float*)d_in[7];
    const float* dw2 = (const float*)d_in[8];
    const float* db2 = (const float*)d_in[9];
    float* out = (float*)d_out;

    float *h1, *res, *wT;
    cudaGetSymbolAddress((void**)&h1,  g_h1);
    cudaGetSymbolAddress((void**)&res, g_res);
    cudaGetSymbolAddress((void**)&wT,  g_wT);

    // fork side branch: cbT -> Gram(+csq) -> init_small
    cudaEventRecord(g_ss.fork, 0);
    cudaStreamWaitEvent(g_ss.s, g_ss.fork, 0);
    transpose_cb<<<dim3(KK / 32, DD / 32), dim3(32, 8), 0, g_ss.s>>>(cb);
    gram_gemm<<<dim3(8, 8), 256, 0, g_ss.s>>>(cb);
    init_small<<<1, 32, 0, g_ss.s>>>();
    cudaEventRecord(g_ss.join1, g_ss.s);

    // main branch: weights -> encoder
    transpose_w_all<<<(WT_END + 255) / 256, 256>>>(ew1, ew2, dw1, dw2);
    cudaEventRecord(g_ss.wtev, 0);

    // side: U = cb · dec_w1^T per tap (needs wT3) — overlaps encoder convs
    cudaStreamWaitEvent(g_ss.s, g_ss.wtev, 0);
    u_gemm<<<dim3(8, 2, 3), 256, 0, g_ss.s>>>(cb);
    cudaEventRecord(g_ss.join2, g_ss.s);

    conv3f<100, 256, 256, false><<<dim3(128, 2), 256>>>(x,  wT + WT_O1, eb1, h1,  nullptr);
    conv3f<256, 512, 512, false><<<dim3(128, 4), 256>>>(h1, wT + WT_O2, eb2, res, nullptr);

    // join: vq needs cbT / G / csq / fk / window
    cudaStreamWaitEvent(0, g_ss.join1, 0);
    vq_gemm<<<dim3(128, 8), 256>>>(res);
    vq_pick<<<BT, 256>>>();

    // decoder: gathered dec1 (needs U), then dec2 conv with fused MSE
    cudaStreamWaitEvent(0, g_ss.join2, 0);
    dec1_gather<<<BT, 256>>>(db1);
    conv3f<256, 100, 128, true><<<dim3(128, 1), 256>>>(h1, wT + WT_O4, db2, nullptr, x);

    finalize_k<<<1, 1>>>(out);
}

// round 13
// speedup vs baseline: 5.0840x; 1.1040x over previous
#include <cuda_runtime.h>
#include <cuda_bf16.h>
#include <cstdint>

#define TT 2048
#define BT 16384
#define DD 512
#define KK 1024
#define HALF_N 8388608u   // BT*KK/2

// ---------------- scratch (static device allocations only) ----------------
__device__ float g_h1[BT * 256];
__device__ float g_res[BT * DD];          // encoder output z
__device__ float g_cbT[DD * KK];          // codebook transposed [d][k]
__device__ float g_dist[BT * KK];         // dot products <z, c_k>  (64MB)
__device__ float g_G[KK * KK];            // Gram matrix cb·cbT     (4MB)
__device__ float g_csq[KK];               // = diag(G)
__device__ float g_wT[1048576];           // transposed padded weights (4MB)
__device__ float g_U[3 * KK * 256];       // U[tap][k][co] = cb·W1_tap^T (3MB)
__device__ int   g_sel[BT * 8];           // selected code per row per stage
__device__ unsigned g_fk[16];             // per-stage threefry fold-in keys
__device__ float g_window;                // gumbel hi-lo window + margin
__device__ float g_acc[2];   // [0]=commit sum, [1]=mse sum

#define WT_O1 0
#define WT_O2 86016
#define WT_O3 479232
#define WT_O4 872448
#define WT_END 970752

// ---------------- packed f32x2 helpers ----------------
__device__ __forceinline__ void splat2(unsigned long long& d, float a) {
    asm("mov.b64 %0, {%1, %1};" : "=l"(d) : "f"(a));
}
__device__ __forceinline__ void pack2(unsigned long long& d, float a, float b) {
    asm("mov.b64 %0, {%1, %2};" : "=l"(d) : "f"(a), "f"(b));
}
__device__ __forceinline__ void unpack2(float& a, float& b, unsigned long long d) {
    asm("mov.b64 {%0, %1}, %2;" : "=f"(a), "=f"(b) : "l"(d));
}
__device__ __forceinline__ void ffma2(unsigned long long& acc,
                                      unsigned long long a, unsigned long long b) {
    asm("fma.rn.f32x2 %0, %1, %2, %0;" : "+l"(acc) : "l"(a), "l"(b));
}

// ---------------- mma.sync / ldmatrix helpers ----------------
__device__ __forceinline__ uint32_t smem_u32(const void* p) {
    uint32_t a;
    asm("{ .reg .u64 t; cvta.to.shared.u64 t, %1; cvt.u32.u64 %0, t; }"
        : "=r"(a) : "l"(p));
    return a;
}
#define LDSM_X4(r0, r1, r2, r3, addr) \
    asm volatile("ldmatrix.sync.aligned.m8n8.x4.shared.b16 {%0,%1,%2,%3}, [%4];" \
        : "=r"(r0), "=r"(r1), "=r"(r2), "=r"(r3) : "r"(addr))
#define MMA_BF16(d, a, b0, b1) \
    asm volatile("mma.sync.aligned.m16n8k16.row.col.f32.bf16.bf16.f32 " \
        "{%0,%1,%2,%3}, {%4,%5,%6,%7}, {%8,%9}, {%0,%1,%2,%3};" \
        : "+f"((d)[0]), "+f"((d)[1]), "+f"((d)[2]), "+f"((d)[3]) \
        : "r"((a)[0]), "r"((a)[1]), "r"((a)[2]), "r"((a)[3]), "r"(b0), "r"(b1))

// ---------------- JAX threefry2x32 (exact) ----------------
__host__ __device__ inline void tf2x32(unsigned k0, unsigned k1,
                                       unsigned x0, unsigned x1,
                                       unsigned& o0, unsigned& o1) {
    unsigned ks2 = k0 ^ k1 ^ 0x1BD11BDAu;
    x0 += k0; x1 += k1;
#define TF_RND(r) { x0 += x1; x1 = (x1 << (r)) | (x1 >> (32 - (r))); x1 ^= x0; }
    TF_RND(13) TF_RND(15) TF_RND(26) TF_RND(6)
    x0 += k1;  x1 += ks2 + 1u;
    TF_RND(17) TF_RND(29) TF_RND(16) TF_RND(24)
    x0 += ks2; x1 += k0 + 2u;
    TF_RND(13) TF_RND(15) TF_RND(26) TF_RND(6)
    x0 += k0;  x1 += k1 + 3u;
    TF_RND(17) TF_RND(29) TF_RND(16) TF_RND(24)
    x0 += k1;  x1 += ks2 + 4u;
    TF_RND(13) TF_RND(15) TF_RND(26) TF_RND(6)
    x0 += ks2; x1 += k0 + 5u;
#undef TF_RND
    o0 = x0; o1 = x1;
}

__device__ inline float gumbel_from_bits(unsigned bits) {
    float f = __uint_as_float((bits >> 9) | 0x3f800000u) - 1.0f;
    float u = (f == 0.0f) ? 1.17549435e-38f : f;
    return -__logf(-__logf(u));
}

__device__ inline unsigned fmap(float f) {
    unsigned u = __float_as_uint(f);
    return (u & 0x80000000u) ? ~u : (u | 0x80000000u);
}
__device__ inline float unfmap(unsigned u) {
    unsigned v = (u & 0x80000000u) ? (u ^ 0x80000000u) : ~u;
    return __uint_as_float(v);
}

__device__ inline float gelu_exact(float v) {
    return 0.5f * v * (1.0f + erff(v * 0.7071067811865476f));
}

// ---------------- codebook transpose: cbT[d][k] = cb[k][d] ----------------
__global__ void transpose_cb(const float* __restrict__ cb) {
    __shared__ float t[32][33];
    int k0 = blockIdx.x * 32;
    int d0 = blockIdx.y * 32;
    int tx = threadIdx.x, ty = threadIdx.y;  // 32 x 8
    for (int l = 0; l < 32; l += 8)
        t[ty + l][tx] = cb[(k0 + ty + l) * DD + d0 + tx];
    __syncthreads();
    for (int l = 0; l < 32; l += 8)
        g_cbT[(d0 + ty + l) * KK + k0 + tx] = t[tx][ty + l];
}

// ---------------- merged weight transpose: all 4 conv weights --------------
__device__ __forceinline__ void wt_range(int local, const float* __restrict__ w,
                                         int CIN, int COUT, int CIN16, int PAD,
                                         float* __restrict__ dst) {
    int co = local % PAD;
    int rest = local / PAD;
    int ci = rest % CIN16;
    int tap = rest / CIN16;
    float v = 0.0f;
    if (ci < CIN && co < COUT)
        v = w[((size_t)co * CIN + ci) * 3 + tap];
    dst[local] = v;
}
__global__ void transpose_w_all(const float* __restrict__ w1, const float* __restrict__ w2,
                                const float* __restrict__ w3, const float* __restrict__ w4) {
    int idx = blockIdx.x * 256 + threadIdx.x;
    if (idx >= WT_END) return;
    if (idx < WT_O2)      wt_range(idx - WT_O1, w1, 100, 256, 112, 256, g_wT + WT_O1);
    else if (idx < WT_O3) wt_range(idx - WT_O2, w2, 256, 512, 256, 512, g_wT + WT_O2);
    else if (idx < WT_O4) wt_range(idx - WT_O3, w3, 512, 256, 512, 256, g_wT + WT_O3);
    else                  wt_range(idx - WT_O4, w4, 256, 100, 256, 128, g_wT + WT_O4);
}

// ---------------- conv3f: FFMA2 conv (unchanged, passing) ------------------
#define SAS 136
template<int CIN, int COUT, int COUT_PAD, bool FUSE_MSE>
__global__ void __launch_bounds__(256, 2) conv3f(
    const float* __restrict__ in, const float* __restrict__ wT,
    const float* __restrict__ bias, float* __restrict__ out,
    const float* __restrict__ xref)
{
    __shared__ __align__(16) float As[2][16][SAS];
    __shared__ __align__(16) float Bs[2][16][SAS];
    constexpr int NC = (CIN + 15) / 16;
    constexpr int CIN16 = NC * 16;
    constexpr int NS = 3 * NC;
    const int tid = threadIdx.x;
    const int tx = tid & 15, ty = tid >> 4;
    const int r0 = blockIdx.x * 128;
    const int n0 = blockIdx.y * 128;

    const int sm  = tid >> 1;
    const int skq = tid & 1;
    const int aRow = r0 + sm;
    const int tt = aRow & (TT - 1);
    const int bk  = tid >> 4;
    const int bn4 = (tid & 15) * 4;

    unsigned long long acc2[8][4];
#pragma unroll
    for (int i = 0; i < 8; ++i)
#pragma unroll
        for (int j = 0; j < 4; ++j) acc2[i][j] = 0ull;

    float4 av0, av1, bv0, bv1;

    auto LOAD = [&](int s) {
        const int tap = s / NC;
        const int ccc = (s - tap * NC) * 16;
        const int ci = ccc + 8 * skq;
        const int st = tt + tap - 1;
        const bool rv = (st >= 0 && st < TT);
        const float* ap = in + (size_t)(aRow + tap - 1) * CIN + ci;
        if ((CIN % 16 == 0) || (ccc + 16 <= CIN)) {
            if (rv) {
                av0 = *(const float4*)(ap);
                av1 = *(const float4*)(ap + 4);
            } else {
                av0 = make_float4(0.f, 0.f, 0.f, 0.f);
                av1 = av0;
            }
        } else {
            float t0[8];
#pragma unroll
            for (int q = 0; q < 8; ++q)
                t0[q] = (rv && ci + q < CIN) ? ap[q] : 0.0f;
            av0 = make_float4(t0[0], t0[1], t0[2], t0[3]);
            av1 = make_float4(t0[4], t0[5], t0[6], t0[7]);
        }
        const float* bp = wT + (size_t)(tap * CIN16 + ccc + bk) * COUT_PAD + n0;
        bv0 = *(const float4*)(bp + bn4);
        bv1 = *(const float4*)(bp + 64 + bn4);
    };
    auto STORE = [&](int p) {
        As[p][8 * skq + 0][sm] = av0.x;
        As[p][8 * skq + 1][sm] = av0.y;
        As[p][8 * skq + 2][sm] = av0.z;
        As[p][8 * skq + 3][sm] = av0.w;
        As[p][8 * skq + 4][sm] = av1.x;
        As[p][8 * skq + 5][sm] = av1.y;
        As[p][8 * skq + 6][sm] = av1.z;
        As[p][8 * skq + 7][sm] = av1.w;
        *(float4*)&Bs[p][bk][bn4]      = bv0;
        *(float4*)&Bs[p][bk][64 + bn4] = bv1;
    };

    LOAD(0); STORE(0);
    LOAD(1);
    __syncthreads();

    for (int s = 0; s < NS; ++s) {
        const int p = s & 1;
        if (s + 1 < NS) STORE(p ^ 1);
        if (s + 2 < NS) LOAD(s + 2);
#pragma unroll
        for (int kk = 0; kk < 16; ++kk) {
            float4 aL = *(const float4*)&As[p][kk][ty * 4];
            float4 aH = *(const float4*)&As[p][kk][64 + ty * 4];
            float4 bL = *(const float4*)&Bs[p][kk][tx * 4];
            float4 bH = *(const float4*)&Bs[p][kk][64 + tx * 4];
            unsigned long long b2[4], a2;
            pack2(b2[0], bL.x, bL.y);
            pack2(b2[1], bL.z, bL.w);
            pack2(b2[2], bH.x, bH.y);
            pack2(b2[3], bH.z, bH.w);
            float arr[8] = {aL.x, aL.y, aL.z, aL.w, aH.x, aH.y, aH.z, aH.w};
#pragma unroll
            for (int i = 0; i < 8; ++i) {
                splat2(a2, arr[i]);
#pragma unroll
                for (int j = 0; j < 4; ++j) ffma2(acc2[i][j], a2, b2[j]);
            }
        }
        __syncthreads();
    }

    float bl[8];
#pragma unroll
    for (int c = 0; c < 4; ++c) {
        int coL = n0 + tx * 4 + c;
        int coH = n0 + 64 + tx * 4 + c;
        bl[c]     = (COUT % 128 == 0 || coL < COUT) ? bias[coL] : 0.0f;
        bl[4 + c] = (COUT % 128 == 0 || coH < COUT) ? bias[coH] : 0.0f;
    }
    float local = 0.0f;
#pragma unroll
    for (int i = 0; i < 8; ++i) {
        int m = (i < 4) ? (ty * 4 + i) : (64 + ty * 4 + (i - 4));
        int r = r0 + m;
        float v[8];
        unpack2(v[0], v[1], acc2[i][0]);
        unpack2(v[2], v[3], acc2[i][1]);
        unpack2(v[4], v[5], acc2[i][2]);
        unpack2(v[6], v[7], acc2[i][3]);
#pragma unroll
        for (int hf = 0; hf < 2; ++hf) {
            int cobase = n0 + 64 * hf + tx * 4;
            float g0 = gelu_exact(v[4 * hf + 0] + bl[4 * hf + 0]);
            float g1 = gelu_exact(v[4 * hf + 1] + bl[4 * hf + 1]);
            float g2 = gelu_exact(v[4 * hf + 2] + bl[4 * hf + 2]);
            float g3 = gelu_exact(v[4 * hf + 3] + bl[4 * hf + 3]);
            if (FUSE_MSE) {
                float gg[4] = {g0, g1, g2, g3};
#pragma unroll
                for (int c = 0; c < 4; ++c) {
                    int co = cobase + c;
                    if (co < COUT) {
                        float d = xref[(size_t)r * COUT + co] - gg[c];
                        local += d * d;
                    }
                }
            } else if (COUT % 128 == 0) {
                *(float4*)&out[(size_t)r * COUT + cobase] = make_float4(g0, g1, g2, g3);
            } else {
                float gg[4] = {g0, g1, g2, g3};
#pragma unroll
                for (int c = 0; c < 4; ++c) {
                    int co = cobase + c;
                    if (co < COUT) out[(size_t)r * COUT + co] = gg[c];
                }
            }
        }
    }
    if (FUSE_MSE) {
        __shared__ float red[256];
        red[tid] = local;
        __syncthreads();
        for (int s = 128; s > 0; s >>= 1) {
            if (tid < s) red[tid] += red[tid + s];
            __syncthreads();
        }
        if (tid == 0) atomicAdd(&g_acc[1], red[0]);
    }
}

// ---------------- shared pipelined-GEMM body (generalized B) --------------
#define GEMM_BODY(AROW_EXPR, BBASE, BSTRIDE)                                   \
    const int sm  = tid >> 1;                                                  \
    const int skq = tid & 1;                                                   \
    const int arow = (AROW_EXPR);                                              \
    const float* aptr = Abase + (size_t)arow * DD + 8 * skq;                   \
    const int bk  = tid >> 4;                                                  \
    const int bn4 = (tid & 15) * 4;                                            \
    const float* bbase = (BBASE) + (size_t)bk * (BSTRIDE) + k0;                \
    unsigned long long acc2[8][4];                                             \
    _Pragma("unroll")                                                          \
    for (int i = 0; i < 8; ++i)                                                \
        _Pragma("unroll")                                                      \
        for (int j = 0; j < 4; ++j) acc2[i][j] = 0ull;                         \
    float4 av0, av1, bv0, bv1;                                                 \
    auto LOAD = [&](int cc) {                                                  \
        av0 = *(const float4*)(aptr + cc);                                     \
        av1 = *(const float4*)(aptr + cc + 4);                                 \
        const float* bp = bbase + (size_t)cc * (BSTRIDE);                      \
        bv0 = *(const float4*)(bp + bn4);                                      \
        bv1 = *(const float4*)(bp + 64 + bn4);                                 \
    };                                                                         \
    auto STORE = [&](int p) {                                                  \
        As[p][8 * skq + 0][sm] = av0.x;                                        \
        As[p][8 * skq + 1][sm] = av0.y;                                        \
        As[p][8 * skq + 2][sm] = av0.z;                                        \
        As[p][8 * skq + 3][sm] = av0.w;                                        \
        As[p][8 * skq + 4][sm] = av1.x;                                        \
        As[p][8 * skq + 5][sm] = av1.y;                                        \
        As[p][8 * skq + 6][sm] = av1.z;                                        \
        As[p][8 * skq + 7][sm] = av1.w;                                        \
        *(float4*)&Bs[p][bk][bn4]      = bv0;                                  \
        *(float4*)&Bs[p][bk][64 + bn4] = bv1;                                  \
    };                                                                         \
    LOAD(0); STORE(0);                                                         \
    LOAD(16);                                                                  \
    __syncthreads();                                                           \
    for (int ch = 0; ch < 32; ++ch) {                                          \
        const int p = ch & 1;                                                  \
        if (ch + 1 < 32) STORE(p ^ 1);                                         \
        if (ch + 2 < 32) LOAD((ch + 2) * 16);                                  \
        _Pragma("unroll")                                                      \
        for (int kk = 0; kk < 16; ++kk) {                                      \
            float4 aL = *(const float4*)&As[p][kk][ty * 4];                    \
            float4 aH = *(const float4*)&As[p][kk][64 + ty * 4];               \
            float4 bL = *(const float4*)&Bs[p][kk][tx * 4];                    \
            float4 bH = *(const float4*)&Bs[p][kk][64 + tx * 4];               \
            unsigned long long b2[4], a2;                                      \
            pack2(b2[0], bL.x, bL.y);                                          \
            pack2(b2[1], bL.z, bL.w);                                          \
            pack2(b2[2], bH.x, bH.y);                                          \
            pack2(b2[3], bH.z, bH.w);                                          \
            float arr[8] = {aL.x, aL.y, aL.z, aL.w, aH.x, aH.y, aH.z, aH.w};   \
            _Pragma("unroll")                                                  \
            for (int i = 0; i < 8; ++i) {                                      \
                splat2(a2, arr[i]);                                            \
                _Pragma("unroll")                                              \
                for (int j = 0; j < 4; ++j) ffma2(acc2[i][j], a2, b2[j]);      \
            }                                                                  \
        }                                                                      \
        __syncthreads();                                                       \
    }

// ---------------- stage-0 GEMM via mma.sync bf16-split ---------------------
// D[128 rows x 64 cols] per block; grid (128, 16). 8 warps: warp w owns rows
// w*16..w*16+15, all 64 cols. 3-term Dekker split = fp32-grade accuracy.
__global__ void __launch_bounds__(256, 2) vq_gemm_mma(
    const float* __restrict__ zin, const float* __restrict__ cb)
{
    __shared__ __align__(16) __nv_bfloat16 sAh[2][128][24];
    __shared__ __align__(16) __nv_bfloat16 sAl[2][128][24];
    __shared__ __align__(16) __nv_bfloat16 sBh[2][64][24];
    __shared__ __align__(16) __nv_bfloat16 sBl[2][64][24];

    const int tid = threadIdx.x;
    const int w = tid >> 5, l = tid & 31;
    const int r0 = blockIdx.x * 128;
    const int k0 = blockIdx.y * 64;

    // staging maps
    const int arow = tid >> 1;             // 0..127
    const int adh  = (tid & 1) * 8;        // d offset within 16-chunk
    const float* aP = zin + (size_t)(r0 + arow) * DD + adh;
    const int brow = tid >> 2;             // 0..63
    const int bdq  = (tid & 3) * 4;
    const float* bP = cb + (size_t)(k0 + brow) * DD + bdq;

    float acc[8][4];
#pragma unroll
    for (int j = 0; j < 8; ++j)
#pragma unroll
        for (int c = 0; c < 4; ++c) acc[j][c] = 0.0f;

    float4 a0v, a1v, bv;
    auto LDG = [&](int ks) {
        a0v = *(const float4*)(aP + ks * 16);
        a1v = *(const float4*)(aP + ks * 16 + 4);
        bv  = *(const float4*)(bP + ks * 16);
    };
    auto cvtst = [](__nv_bfloat16* hi, __nv_bfloat16* lo, float x, float y) {
        __nv_bfloat16 xh = __float2bfloat16(x);
        __nv_bfloat16 yh = __float2bfloat16(y);
        __nv_bfloat16 xl = __float2bfloat16(x - __bfloat162float(xh));
        __nv_bfloat16 yl = __float2bfloat16(y - __bfloat162float(yh));
        *(__nv_bfloat162*)hi = __halves2bfloat162(xh, yh);
        *(__nv_bfloat162*)lo = __halves2bfloat162(xl, yl);
    };
    auto CVTSTS = [&](int p) {
        cvtst(&sAh[p][arow][adh + 0], &sAl[p][arow][adh + 0], a0v.x, a0v.y);
        cvtst(&sAh[p][arow][adh + 2], &sAl[p][arow][adh + 2], a0v.z, a0v.w);
        cvtst(&sAh[p][arow][adh + 4], &sAl[p][arow][adh + 4], a1v.x, a1v.y);
        cvtst(&sAh[p][arow][adh + 6], &sAl[p][arow][adh + 6], a1v.z, a1v.w);
        cvtst(&sBh[p][brow][bdq + 0], &sBl[p][brow][bdq + 0], bv.x, bv.y);
        cvtst(&sBh[p][brow][bdq + 2], &sBl[p][brow][bdq + 2], bv.z, bv.w);
    };

    // ldmatrix address lanes
    const int arl = l & 15, ach = (l >> 4) * 8;              // A frag
    const int bg = l >> 3;
    const int bn = ((bg >= 2) ? 8 : 0) + (l & 7);            // B frag n
    const int bkoff = (bg & 1) * 8;                          // B frag k-half

    LDG(0); CVTSTS(0);
    __syncthreads();

    for (int ks = 0; ks < 32; ++ks) {
        const int p = ks & 1;
        if (ks + 1 < 32) LDG(ks + 1);

        uint32_t ah[4], al[4];
        LDSM_X4(ah[0], ah[1], ah[2], ah[3], smem_u32(&sAh[p][w * 16 + arl][ach]));
        LDSM_X4(al[0], al[1], al[2], al[3], smem_u32(&sAl[p][w * 16 + arl][ach]));
        uint32_t bh[4][4], blr[4][4];
#pragma unroll
        for (int nb = 0; nb < 4; ++nb) {
            LDSM_X4(bh[nb][0], bh[nb][1], bh[nb][2], bh[nb][3],
                    smem_u32(&sBh[p][nb * 16 + bn][bkoff]));
            LDSM_X4(blr[nb][0], blr[nb][1], blr[nb][2], blr[nb][3],
                    smem_u32(&sBl[p][nb * 16 + bn][bkoff]));
        }
#pragma unroll
        for (int nb = 0; nb < 4; ++nb) {
#pragma unroll
            for (int h = 0; h < 2; ++h) {
                const int j = nb * 2 + h;
                MMA_BF16(acc[j], ah, bh[nb][2 * h], bh[nb][2 * h + 1]);
                MMA_BF16(acc[j], ah, blr[nb][2 * h], blr[nb][2 * h + 1]);
                MMA_BF16(acc[j], al, bh[nb][2 * h], bh[nb][2 * h + 1]);
            }
        }
        if (ks + 1 < 32) CVTSTS(p ^ 1);
        __syncthreads();
    }

    // epilogue: fragment -> g_dist
    const int row0 = r0 + w * 16 + (l >> 2);
    const int col0 = k0 + 2 * (l & 3);
#pragma unroll
    for (int j = 0; j < 8; ++j) {
        *(float2*)&g_dist[(size_t)row0 * KK + col0 + j * 8] =
            make_float2(acc[j][0], acc[j][1]);
        *(float2*)&g_dist[(size_t)(row0 + 8) * KK + col0 + j * 8] =
            make_float2(acc[j][2], acc[j][3]);
    }
}

// ---------------- Gram GEMM: G = cb · cbT + csq = diag(G) ------------------
__global__ void __launch_bounds__(256, 2) gram_gemm(const float* __restrict__ cb) {
    __shared__ __align__(16) float As[2][16][SAS];
    __shared__ __align__(16) float Bs[2][16][SAS];
    const int tid = threadIdx.x;
    const int tx = tid & 15, ty = tid >> 4;
    const int r0 = blockIdx.x * 128;
    const int k0 = blockIdx.y * 128;
    const float* Abase = cb;
    GEMM_BODY(r0 + (tid >> 1), g_cbT, KK)

#pragma unroll
    for (int i = 0; i < 8; ++i) {
        int m = (i < 4) ? (ty * 4 + i) : (64 + ty * 4 + (i - 4));
        int row = r0 + m;
        float d0, d1, d2, d3;
        unpack2(d0, d1, acc2[i][0]);
        unpack2(d2, d3, acc2[i][1]);
        *(float4*)&g_G[(size_t)row * KK + k0 + tx * 4] = make_float4(d0, d1, d2, d3);
        if (r0 == k0) {
            int c0 = k0 + tx * 4;
            if (row >= c0 && row < c0 + 4) {
                float dd[4] = {d0, d1, d2, d3};
                g_csq[row] = dd[row - c0];
            }
        }
        unpack2(d0, d1, acc2[i][2]);
        unpack2(d2, d3, acc2[i][3]);
        *(float4*)&g_G[(size_t)row * KK + k0 + 64 + tx * 4] = make_float4(d0, d1, d2, d3);
        if (r0 == k0) {
            int c1 = k0 + 64 + tx * 4;
            if (row >= c1 && row < c1 + 4) {
                float dd[4] = {d0, d1, d2, d3};
                g_csq[row] = dd[row - c1];
            }
        }
    }
}

// ---------------- U GEMM: U[tap] = cb · W1_tap^T  (grid 8 x 2 x 3) ---------
__global__ void __launch_bounds__(256, 2) u_gemm(const float* __restrict__ cb) {
    __shared__ __align__(16) float As[2][16][SAS];
    __shared__ __align__(16) float Bs[2][16][SAS];
    const int tid = threadIdx.x;
    const int tx = tid & 15, ty = tid >> 4;
    const int r0 = blockIdx.x * 128;
    const int k0 = blockIdx.y * 128;
    const int tap = blockIdx.z;
    const float* Abase = cb;
    const float* wt3 = g_wT + WT_O3 + (size_t)tap * 512 * 256;
    GEMM_BODY(r0 + (tid >> 1), wt3, 256)

#pragma unroll
    for (int i = 0; i < 8; ++i) {
        int m = (i < 4) ? (ty * 4 + i) : (64 + ty * 4 + (i - 4));
        int row = r0 + m;
        float* urow = &g_U[((size_t)tap * KK + row) * 256 + k0];
        float d0, d1, d2, d3;
        unpack2(d0, d1, acc2[i][0]);
        unpack2(d2, d3, acc2[i][1]);
        *(float4*)(urow + tx * 4) = make_float4(d0, d1, d2, d3);
        unpack2(d0, d1, acc2[i][2]);
        unpack2(d2, d3, acc2[i][3]);
        *(float4*)(urow + 64 + tx * 4) = make_float4(d0, d1, d2, d3);
    }
}

// ---------------- init_small: fk keys, window, accumulators ---------------
__global__ void init_small() {
    int tid = threadIdx.x;  // 32
    if (tid < 8) {
        unsigned a, b;
        tf2x32(0u, 42u, 0u, (unsigned)tid, a, b);
        g_fk[2 * tid] = a;
        g_fk[2 * tid + 1] = b;
    }
    if (tid < 2) g_acc[tid] = 0.0f;
    if (tid == 0) {
        float ghi = gumbel_from_bits(0xFFFFFFFFu);
        float glo = gumbel_from_bits(0u);
        g_window = (ghi - glo) + 0.5f;
    }
}

// ---------------- pick: rn2 + all 8 VQ stages per row -> g_sel -------------
__global__ void __launch_bounds__(256) vq_pick() {
    const int bt = blockIdx.x;
    const int tid = threadIdx.x;
    __shared__ unsigned sMaxU;
    __shared__ unsigned long long sBest;
    __shared__ float sDotSel;
    __shared__ int sSel[8];
    __shared__ float red[256];

    if (tid == 0) { sMaxU = 0u; sBest = 0ull; }

    {
        float z0 = g_res[(size_t)bt * DD + tid];
        float z1 = g_res[(size_t)bt * DD + tid + 256];
        red[tid] = z0 * z0 + z1 * z1;
    }

    float d[4], cs[4], s[4];
    const float* drow = &g_dist[(size_t)bt * KK];
#pragma unroll
    for (int j = 0; j < 4; ++j) {
        d[j] = drow[tid + 256 * j];
        cs[j] = g_csq[tid + 256 * j];
        s[j] = fmaf(20.0f, d[j], -10.0f * cs[j]);
    }
    __syncthreads();
    for (int ss = 128; ss > 0; ss >>= 1) {
        if (tid < ss) red[tid] += red[tid + ss];
        __syncthreads();
    }
    const float win = g_window;
    const unsigned btL = (bt < 8192) ? (unsigned)bt : (unsigned)(bt - 8192);
    const bool hi = (bt >= 8192);
    float rn2 = (tid == 0) ? red[0] : 0.0f;
    float commit = 0.0f;

    for (int i = 0; i < 8; ++i) {
        float lm = fmaxf(fmaxf(s[0], s[1]), fmaxf(s[2], s[3]));
#pragma unroll
        for (int off = 16; off > 0; off >>= 1)
            lm = fmaxf(lm, __shfl_xor_sync(0xffffffffu, lm, off));
        if ((tid & 31) == 0) atomicMax(&sMaxU, fmap(lm));
        __syncthreads();
        const float tau = unfmap(sMaxU) - win;

        const unsigned fk0 = g_fk[2 * i], fk1 = g_fk[2 * i + 1];
#pragma unroll
        for (int j = 0; j < 4; ++j) {
            if (s[j] >= tau) {
                unsigned k = (unsigned)(tid + 256 * j);
                unsigned n = btL * 1024u + k;
                unsigned b0, b1;
                tf2x32(fk0, fk1, n, n + HALF_N, b0, b1);
                float g = gumbel_from_bits(hi ? b1 : b0);
                float sc = s[j] + g;
                unsigned long long cand =
                    ((unsigned long long)fmap(sc) << 32) | (unsigned long long)(~k);
                atomicMax(&sBest, cand);
            }
        }
        __syncthreads();
        const unsigned sel = ~(unsigned)(sBest & 0xffffffffull);
        if (tid == (int)(sel & 255u)) sDotSel = d[sel >> 8];
        __syncthreads();
        if (tid == 0) {
            float rn2n = rn2 - 2.0f * sDotSel + g_csq[sel];
            commit += rn2n;
            rn2 = rn2n;
            sSel[i] = (int)sel;
            sMaxU = 0u;
            sBest = 0ull;
        }
        if (i < 7) {
            const float* grow = &g_G[(size_t)sel * KK];
#pragma unroll
            for (int j = 0; j < 4; ++j) {
                d[j] -= grow[tid + 256 * j];
                s[j] = fmaf(20.0f, d[j], -10.0f * cs[j]);
            }
        }
        __syncthreads();
    }

    if (tid < 8) g_sel[bt * 8 + tid] = sSel[tid];
    if (tid == 0) atomicAdd(&g_acc[0], commit);
}

// ---------------- dec1 gather: h1[bt] = gelu(bias + sum U rows) ------------
__global__ void __launch_bounds__(256) dec1_gather(const float* __restrict__ bias) {
    const int bt = blockIdx.x;
    const int c = threadIdx.x;
    __shared__ int sIdx[24];

    if (c < 24) {
        int tap = c >> 3, i = c & 7;
        int t = bt & (TT - 1);
        int st = t + tap - 1;
        int idx = -1;
        if (st >= 0 && st < TT)
            idx = tap * KK + g_sel[(bt + tap - 1) * 8 + i];
        sIdx[c] = idx;
    }
    __syncthreads();

    float acc = bias[c];
#pragma unroll
    for (int j = 0; j < 24; ++j) {
        int idx = sIdx[j];
        if (idx >= 0) acc += g_U[(size_t)idx * 256 + c];
    }
    g_h1[(size_t)bt * 256 + c] = gelu_exact(acc);
}

__global__ void finalize_k(float* __restrict__ out) {
    out[0] = g_acc[1] * (1.0f / 1638400.0f)
           + g_acc[0] * (1.0f / 67108864.0f);
}

// ---------------- streams/events (created once, pre-baseline) --------------
struct SideStream {
    cudaStream_t s;
    cudaEvent_t fork, wtev, join1, join2;
    SideStream() {
        cudaStreamCreateWithFlags(&s, cudaStreamNonBlocking);
        cudaEventCreateWithFlags(&fork, cudaEventDisableTiming);
        cudaEventCreateWithFlags(&wtev, cudaEventDisableTiming);
        cudaEventCreateWithFlags(&join1, cudaEventDisableTiming);
        cudaEventCreateWithFlags(&join2, cudaEventDisableTiming);
    }
};
static SideStream g_ss;

// ---------------- host launcher (graph-capturable, alloc-free) -------------
extern "C" void kernel_launch(void* const* d_in, const int* in_sizes, int n_in,
                              void* d_out, int out_size) {
    const float* x   = (const float*)d_in[0];
    const float* ew1 = (const float*)d_in[1];
    const float* eb1 = (const float*)d_in[2];
    const float* ew2 = (const float*)d_in[3];
    const float* eb2 = (const float*)d_in[4];
    const float* cb  = (const float*)d_in[5];
    const float* dw1 = (const float*)d_in[6];
    const float* db1 = (const float*)d_in[7];
    const float* dw2 = (const float*)d_in[8];
    const float* db2 = (const float*)d_in[9];
    float* out = (float*)d_out;

    float *h1, *res, *wT;
    cudaGetSymbolAddress((void**)&h1,  g_h1);
    cudaGetSymbolAddress((void**)&res, g_res);
    cudaGetSymbolAddress((void**)&wT,  g_wT);

    // fork side branch: cbT -> Gram(+csq) -> init_small
    cudaEventRecord(g_ss.fork, 0);
    cudaStreamWaitEvent(g_ss.s, g_ss.fork, 0);
    transpose_cb<<<dim3(KK / 32, DD / 32), dim3(32, 8), 0, g_ss.s>>>(cb);
    gram_gemm<<<dim3(8, 8), 256, 0, g_ss.s>>>(cb);
    init_small<<<1, 32, 0, g_ss.s>>>();
    cudaEventRecord(g_ss.join1, g_ss.s);

    // main branch: weights -> encoder
    transpose_w_all<<<(WT_END + 255) / 256, 256>>>(ew1, ew2, dw1, dw2);
    cudaEventRecord(g_ss.wtev, 0);

    // side: U = cb · dec_w1^T per tap (needs wT3) — overlaps encoder convs
    cudaStreamWaitEvent(g_ss.s, g_ss.wtev, 0);
    u_gemm<<<dim3(8, 2, 3), 256, 0, g_ss.s>>>(cb);
    cudaEventRecord(g_ss.join2, g_ss.s);

    conv3f<100, 256, 256, false><<<dim3(128, 2), 256>>>(x,  wT + WT_O1, eb1, h1,  nullptr);
    conv3f<256, 512, 512, false><<<dim3(128, 4), 256>>>(h1, wT + WT_O2, eb2, res, nullptr);

    // join: vq needs cbT / G / csq / fk / window
    cudaStreamWaitEvent(0, g_ss.join1, 0);
    vq_gemm_mma<<<dim3(128, 16), 256>>>(res, cb);
    vq_pick<<<BT, 256>>>();

    // decoder: gathered dec1 (needs U), then dec2 conv with fused MSE
    cudaStreamWaitEvent(0, g_ss.join2, 0);
    dec1_gather<<<BT, 256>>>(db1);
    conv3f<256, 100, 128, true><<<dim3(128, 1), 256>>>(h1, wT + WT_O4, db2, nullptr, x);

    finalize_k<<<1, 1>>>(out);
}

// round 14
// speedup vs baseline: 5.8022x; 1.1413x over previous
#include <cuda_runtime.h>
#include <cuda_bf16.h>
#include <cstdint>

#define TT 2048
#define BT 16384
#define DD 512
#define KK 1024
#define HALF_N 8388608u   // BT*KK/2

// ---------------- scratch (static device allocations only) ----------------
__device__ float g_h1[BT * 256];
__device__ float g_res[BT * DD];          // encoder output z
__device__ float g_cbT[DD * KK];          // codebook transposed [d][k]
__device__ float g_dist[BT * KK];         // dot products <z, c_k>  (64MB)
__device__ float g_G[KK * KK];            // Gram matrix cb·cbT     (4MB)
__device__ float g_csq[KK];               // = diag(G)
__device__ float g_wT[1048576];           // [tap][ci][co] padded weights (4MB)
__device__ float g_wTT[491520];           // [tap][co][ci] for mma convs (2MB)
__device__ float g_U[3 * KK * 256];       // U[tap][k][co] = cb·W1_tap^T (3MB)
__device__ int   g_sel[BT * 8];           // selected code per row per stage
__device__ unsigned g_fk[16];             // per-stage threefry fold-in keys
__device__ float g_window;                // gumbel hi-lo window + margin
__device__ float g_acc[2];   // [0]=commit sum, [1]=mse sum

#define WT_O1 0
#define WT_O2 86016
#define WT_O3 479232
#define WT_O4 872448
#define WT_END 970752
// wTT offsets: conv2 [3][512][256], dec2 [3][128][256] (co>=100 zero)
#define WTT_O2 0
#define WTT_O4 393216
#define WTT_END 491520

// ---------------- packed f32x2 helpers ----------------
__device__ __forceinline__ void splat2(unsigned long long& d, float a) {
    asm("mov.b64 %0, {%1, %1};" : "=l"(d) : "f"(a));
}
__device__ __forceinline__ void pack2(unsigned long long& d, float a, float b) {
    asm("mov.b64 %0, {%1, %2};" : "=l"(d) : "f"(a), "f"(b));
}
__device__ __forceinline__ void unpack2(float& a, float& b, unsigned long long d) {
    asm("mov.b64 {%0, %1}, %2;" : "=f"(a), "=f"(b) : "l"(d));
}
__device__ __forceinline__ void ffma2(unsigned long long& acc,
                                      unsigned long long a, unsigned long long b) {
    asm("fma.rn.f32x2 %0, %1, %2, %0;" : "+l"(acc) : "l"(a), "l"(b));
}

// ---------------- mma.sync / ldmatrix helpers ----------------
__device__ __forceinline__ uint32_t smem_u32(const void* p) {
    uint32_t a;
    asm("{ .reg .u64 t; cvta.to.shared.u64 t, %1; cvt.u32.u64 %0, t; }"
        : "=r"(a) : "l"(p));
    return a;
}
#define LDSM_X4(r0, r1, r2, r3, addr) \
    asm volatile("ldmatrix.sync.aligned.m8n8.x4.shared.b16 {%0,%1,%2,%3}, [%4];" \
        : "=r"(r0), "=r"(r1), "=r"(r2), "=r"(r3) : "r"(addr))
#define MMA_BF16(d, a, b0, b1) \
    asm volatile("mma.sync.aligned.m16n8k16.row.col.f32.bf16.bf16.f32 " \
        "{%0,%1,%2,%3}, {%4,%5,%6,%7}, {%8,%9}, {%0,%1,%2,%3};" \
        : "+f"((d)[0]), "+f"((d)[1]), "+f"((d)[2]), "+f"((d)[3]) \
        : "r"((a)[0]), "r"((a)[1]), "r"((a)[2]), "r"((a)[3]), "r"(b0), "r"(b1))

// ---------------- JAX threefry2x32 (exact) ----------------
__host__ __device__ inline void tf2x32(unsigned k0, unsigned k1,
                                       unsigned x0, unsigned x1,
                                       unsigned& o0, unsigned& o1) {
    unsigned ks2 = k0 ^ k1 ^ 0x1BD11BDAu;
    x0 += k0; x1 += k1;
#define TF_RND(r) { x0 += x1; x1 = (x1 << (r)) | (x1 >> (32 - (r))); x1 ^= x0; }
    TF_RND(13) TF_RND(15) TF_RND(26) TF_RND(6)
    x0 += k1;  x1 += ks2 + 1u;
    TF_RND(17) TF_RND(29) TF_RND(16) TF_RND(24)
    x0 += ks2; x1 += k0 + 2u;
    TF_RND(13) TF_RND(15) TF_RND(26) TF_RND(6)
    x0 += k0;  x1 += k1 + 3u;
    TF_RND(17) TF_RND(29) TF_RND(16) TF_RND(24)
    x0 += k1;  x1 += ks2 + 4u;
    TF_RND(13) TF_RND(15) TF_RND(26) TF_RND(6)
    x0 += ks2; x1 += k0 + 5u;
#undef TF_RND
    o0 = x0; o1 = x1;
}

__device__ inline float gumbel_from_bits(unsigned bits) {
    float f = __uint_as_float((bits >> 9) | 0x3f800000u) - 1.0f;
    float u = (f == 0.0f) ? 1.17549435e-38f : f;
    return -__logf(-__logf(u));
}

__device__ inline unsigned fmap(float f) {
    unsigned u = __float_as_uint(f);
    return (u & 0x80000000u) ? ~u : (u | 0x80000000u);
}
__device__ inline float unfmap(unsigned u) {
    unsigned v = (u & 0x80000000u) ? (u ^ 0x80000000u) : ~u;
    return __uint_as_float(v);
}

__device__ inline float gelu_exact(float v) {
    return 0.5f * v * (1.0f + erff(v * 0.7071067811865476f));
}

// ---------------- codebook transpose: cbT[d][k] = cb[k][d] ----------------
__global__ void transpose_cb(const float* __restrict__ cb) {
    __shared__ float t[32][33];
    int k0 = blockIdx.x * 32;
    int d0 = blockIdx.y * 32;
    int tx = threadIdx.x, ty = threadIdx.y;  // 32 x 8
    for (int l = 0; l < 32; l += 8)
        t[ty + l][tx] = cb[(k0 + ty + l) * DD + d0 + tx];
    __syncthreads();
    for (int l = 0; l < 32; l += 8)
        g_cbT[(d0 + ty + l) * KK + k0 + tx] = t[tx][ty + l];
}

// ---------------- merged weight transpose (both layouts) -------------------
__device__ __forceinline__ void wt_range(int local, const float* __restrict__ w,
                                         int CIN, int COUT, int CIN16, int PAD,
                                         float* __restrict__ dst) {
    int co = local % PAD;
    int rest = local / PAD;
    int ci = rest % CIN16;
    int tap = rest / CIN16;
    float v = 0.0f;
    if (ci < CIN && co < COUT)
        v = w[((size_t)co * CIN + ci) * 3 + tap];
    dst[local] = v;
}
__device__ __forceinline__ void wtt_range(int local, const float* __restrict__ w,
                                          int CIN, int COUT, int ROWS,
                                          float* __restrict__ dst) {
    int ci = local % CIN;
    int rest = local / CIN;
    int co = rest % ROWS;
    int tap = rest / ROWS;
    float v = 0.0f;
    if (co < COUT)
        v = w[((size_t)co * CIN + ci) * 3 + tap];
    dst[local] = v;
}
__global__ void transpose_w_all(const float* __restrict__ w1, const float* __restrict__ w2,
                                const float* __restrict__ w3, const float* __restrict__ w4) {
    int idx = blockIdx.x * 256 + threadIdx.x;
    if (idx < WT_END) {
        if (idx < WT_O2)      wt_range(idx - WT_O1, w1, 100, 256, 112, 256, g_wT + WT_O1);
        else if (idx < WT_O3) wt_range(idx - WT_O2, w2, 256, 512, 256, 512, g_wT + WT_O2);
        else if (idx < WT_O4) wt_range(idx - WT_O3, w3, 512, 256, 512, 256, g_wT + WT_O3);
        else                  wt_range(idx - WT_O4, w4, 256, 100, 256, 128, g_wT + WT_O4);
    } else {
        int j = idx - WT_END;
        if (j >= WTT_END) return;
        if (j < WTT_O4) wtt_range(j - WTT_O2, w2, 256, 512, 512, g_wTT + WTT_O2);
        else            wtt_range(j - WTT_O4, w4, 256, 100, 128, g_wTT + WTT_O4);
    }
}

// ---------------- conv3f: FFMA2 conv (kept for conv1, CIN=100) -------------
#define SAS 136
template<int CIN, int COUT, int COUT_PAD, bool FUSE_MSE>
__global__ void __launch_bounds__(256, 2) conv3f(
    const float* __restrict__ in, const float* __restrict__ wT,
    const float* __restrict__ bias, float* __restrict__ out,
    const float* __restrict__ xref)
{
    __shared__ __align__(16) float As[2][16][SAS];
    __shared__ __align__(16) float Bs[2][16][SAS];
    constexpr int NC = (CIN + 15) / 16;
    constexpr int CIN16 = NC * 16;
    constexpr int NS = 3 * NC;
    const int tid = threadIdx.x;
    const int tx = tid & 15, ty = tid >> 4;
    const int r0 = blockIdx.x * 128;
    const int n0 = blockIdx.y * 128;

    const int sm  = tid >> 1;
    const int skq = tid & 1;
    const int aRow = r0 + sm;
    const int tt = aRow & (TT - 1);
    const int bk  = tid >> 4;
    const int bn4 = (tid & 15) * 4;

    unsigned long long acc2[8][4];
#pragma unroll
    for (int i = 0; i < 8; ++i)
#pragma unroll
        for (int j = 0; j < 4; ++j) acc2[i][j] = 0ull;

    float4 av0, av1, bv0, bv1;

    auto LOAD = [&](int s) {
        const int tap = s / NC;
        const int ccc = (s - tap * NC) * 16;
        const int ci = ccc + 8 * skq;
        const int st = tt + tap - 1;
        const bool rv = (st >= 0 && st < TT);
        const float* ap = in + (size_t)(aRow + tap - 1) * CIN + ci;
        if ((CIN % 16 == 0) || (ccc + 16 <= CIN)) {
            if (rv) {
                av0 = *(const float4*)(ap);
                av1 = *(const float4*)(ap + 4);
            } else {
                av0 = make_float4(0.f, 0.f, 0.f, 0.f);
                av1 = av0;
            }
        } else {
            float t0[8];
#pragma unroll
            for (int q = 0; q < 8; ++q)
                t0[q] = (rv && ci + q < CIN) ? ap[q] : 0.0f;
            av0 = make_float4(t0[0], t0[1], t0[2], t0[3]);
            av1 = make_float4(t0[4], t0[5], t0[6], t0[7]);
        }
        const float* bp = wT + (size_t)(tap * CIN16 + ccc + bk) * COUT_PAD + n0;
        bv0 = *(const float4*)(bp + bn4);
        bv1 = *(const float4*)(bp + 64 + bn4);
    };
    auto STORE = [&](int p) {
        As[p][8 * skq + 0][sm] = av0.x;
        As[p][8 * skq + 1][sm] = av0.y;
        As[p][8 * skq + 2][sm] = av0.z;
        As[p][8 * skq + 3][sm] = av0.w;
        As[p][8 * skq + 4][sm] = av1.x;
        As[p][8 * skq + 5][sm] = av1.y;
        As[p][8 * skq + 6][sm] = av1.z;
        As[p][8 * skq + 7][sm] = av1.w;
        *(float4*)&Bs[p][bk][bn4]      = bv0;
        *(float4*)&Bs[p][bk][64 + bn4] = bv1;
    };

    LOAD(0); STORE(0);
    LOAD(1);
    __syncthreads();

    for (int s = 0; s < NS; ++s) {
        const int p = s & 1;
        if (s + 1 < NS) STORE(p ^ 1);
        if (s + 2 < NS) LOAD(s + 2);
#pragma unroll
        for (int kk = 0; kk < 16; ++kk) {
            float4 aL = *(const float4*)&As[p][kk][ty * 4];
            float4 aH = *(const float4*)&As[p][kk][64 + ty * 4];
            float4 bL = *(const float4*)&Bs[p][kk][tx * 4];
            float4 bH = *(const float4*)&Bs[p][kk][64 + tx * 4];
            unsigned long long b2[4], a2;
            pack2(b2[0], bL.x, bL.y);
            pack2(b2[1], bL.z, bL.w);
            pack2(b2[2], bH.x, bH.y);
            pack2(b2[3], bH.z, bH.w);
            float arr[8] = {aL.x, aL.y, aL.z, aL.w, aH.x, aH.y, aH.z, aH.w};
#pragma unroll
            for (int i = 0; i < 8; ++i) {
                splat2(a2, arr[i]);
#pragma unroll
                for (int j = 0; j < 4; ++j) ffma2(acc2[i][j], a2, b2[j]);
            }
        }
        __syncthreads();
    }

    float bl[8];
#pragma unroll
    for (int c = 0; c < 4; ++c) {
        int coL = n0 + tx * 4 + c;
        int coH = n0 + 64 + tx * 4 + c;
        bl[c]     = (COUT % 128 == 0 || coL < COUT) ? bias[coL] : 0.0f;
        bl[4 + c] = (COUT % 128 == 0 || coH < COUT) ? bias[coH] : 0.0f;
    }
    float local = 0.0f;
#pragma unroll
    for (int i = 0; i < 8; ++i) {
        int m = (i < 4) ? (ty * 4 + i) : (64 + ty * 4 + (i - 4));
        int r = r0 + m;
        float v[8];
        unpack2(v[0], v[1], acc2[i][0]);
        unpack2(v[2], v[3], acc2[i][1]);
        unpack2(v[4], v[5], acc2[i][2]);
        unpack2(v[6], v[7], acc2[i][3]);
#pragma unroll
        for (int hf = 0; hf < 2; ++hf) {
            int cobase = n0 + 64 * hf + tx * 4;
            float g0 = gelu_exact(v[4 * hf + 0] + bl[4 * hf + 0]);
            float g1 = gelu_exact(v[4 * hf + 1] + bl[4 * hf + 1]);
            float g2 = gelu_exact(v[4 * hf + 2] + bl[4 * hf + 2]);
            float g3 = gelu_exact(v[4 * hf + 3] + bl[4 * hf + 3]);
            if (FUSE_MSE) {
                float gg[4] = {g0, g1, g2, g3};
#pragma unroll
                for (int c = 0; c < 4; ++c) {
                    int co = cobase + c;
                    if (co < COUT) {
                        float d = xref[(size_t)r * COUT + co] - gg[c];
                        local += d * d;
                    }
                }
            } else if (COUT % 128 == 0) {
                *(float4*)&out[(size_t)r * COUT + cobase] = make_float4(g0, g1, g2, g3);
            } else {
                float gg[4] = {g0, g1, g2, g3};
#pragma unroll
                for (int c = 0; c < 4; ++c) {
                    int co = cobase + c;
                    if (co < COUT) out[(size_t)r * COUT + co] = gg[c];
                }
            }
        }
    }
    if (FUSE_MSE) {
        __shared__ float red[256];
        red[tid] = local;
        __syncthreads();
        for (int s = 128; s > 0; s >>= 1) {
            if (tid < s) red[tid] += red[tid + s];
            __syncthreads();
        }
        if (tid == 0) atomicAdd(&g_acc[1], red[0]);
    }
}

// ---------------- bf16 split helper ----------------
__device__ __forceinline__ void cvt_split2(__nv_bfloat16* hi, __nv_bfloat16* lo,
                                           float x, float y) {
    __nv_bfloat16 xh = __float2bfloat16(x);
    __nv_bfloat16 yh = __float2bfloat16(y);
    __nv_bfloat16 xl = __float2bfloat16(x - __bfloat162float(xh));
    __nv_bfloat16 yl = __float2bfloat16(y - __bfloat162float(yh));
    *(__nv_bfloat162*)hi = __halves2bfloat162(xh, yh);
    *(__nv_bfloat162*)lo = __halves2bfloat162(xl, yl);
}

// ---------------- conv_mma: mma.sync bf16-split conv (CIN mult of 16) ------
// D tile 128 rows x 64 cols; grid (BT/128, ceil(COUT/64)). 8 warps.
template<int CIN, int COUT, int NBPAD, bool FUSE_MSE>
__global__ void __launch_bounds__(256, 2) conv_mma(
    const float* __restrict__ in, const float* __restrict__ wTT,
    const float* __restrict__ bias, float* __restrict__ out,
    const float* __restrict__ xref)
{
    __shared__ __align__(16) __nv_bfloat16 sAh[2][128][24];
    __shared__ __align__(16) __nv_bfloat16 sAl[2][128][24];
    __shared__ __align__(16) __nv_bfloat16 sBh[2][64][24];
    __shared__ __align__(16) __nv_bfloat16 sBl[2][64][24];
    constexpr int NC = CIN / 16;
    constexpr int NS = 3 * NC;

    const int tid = threadIdx.x;
    const int w = tid >> 5, l = tid & 31;
    const int r0 = blockIdx.x * 128;
    const int n0 = blockIdx.y * 64;

    const int arow = tid >> 1;
    const int adh  = (tid & 1) * 8;
    const int aRow = r0 + arow;
    const int tt = aRow & (TT - 1);
    const int brow = tid >> 2;
    const int bdq  = (tid & 3) * 4;
    const float* bBase = wTT + ((size_t)(n0 + brow)) * CIN + bdq;

    float acc[8][4];
#pragma unroll
    for (int j = 0; j < 8; ++j)
#pragma unroll
        for (int c = 0; c < 4; ++c) acc[j][c] = 0.0f;

    float4 a0v, a1v, bv;
    auto LDG = [&](int s) {
        const int tap = s / NC;
        const int ccc = (s - tap * NC) * 16;
        const int st = tt + tap - 1;
        if (st >= 0 && st < TT) {
            const float* ap = in + (size_t)(aRow + tap - 1) * CIN + ccc + adh;
            a0v = *(const float4*)(ap);
            a1v = *(const float4*)(ap + 4);
        } else {
            a0v = make_float4(0.f, 0.f, 0.f, 0.f);
            a1v = a0v;
        }
        bv = *(const float4*)(bBase + (size_t)tap * NBPAD * CIN + ccc);
    };
    auto CVTSTS = [&](int p) {
        cvt_split2(&sAh[p][arow][adh + 0], &sAl[p][arow][adh + 0], a0v.x, a0v.y);
        cvt_split2(&sAh[p][arow][adh + 2], &sAl[p][arow][adh + 2], a0v.z, a0v.w);
        cvt_split2(&sAh[p][arow][adh + 4], &sAl[p][arow][adh + 4], a1v.x, a1v.y);
        cvt_split2(&sAh[p][arow][adh + 6], &sAl[p][arow][adh + 6], a1v.z, a1v.w);
        cvt_split2(&sBh[p][brow][bdq + 0], &sBl[p][brow][bdq + 0], bv.x, bv.y);
        cvt_split2(&sBh[p][brow][bdq + 2], &sBl[p][brow][bdq + 2], bv.z, bv.w);
    };

    const int arl = l & 15, ach = (l >> 4) * 8;
    const int bg = l >> 3;
    const int bn = ((bg >= 2) ? 8 : 0) + (l & 7);
    const int bkoff = (bg & 1) * 8;

    LDG(0); CVTSTS(0);
    __syncthreads();

    for (int s = 0; s < NS; ++s) {
        const int p = s & 1;
        if (s + 1 < NS) LDG(s + 1);

        uint32_t ah[4], al[4];
        LDSM_X4(ah[0], ah[1], ah[2], ah[3], smem_u32(&sAh[p][w * 16 + arl][ach]));
        LDSM_X4(al[0], al[1], al[2], al[3], smem_u32(&sAl[p][w * 16 + arl][ach]));
        uint32_t bh[4][4], blr[4][4];
#pragma unroll
        for (int nb = 0; nb < 4; ++nb) {
            LDSM_X4(bh[nb][0], bh[nb][1], bh[nb][2], bh[nb][3],
                    smem_u32(&sBh[p][nb * 16 + bn][bkoff]));
            LDSM_X4(blr[nb][0], blr[nb][1], blr[nb][2], blr[nb][3],
                    smem_u32(&sBl[p][nb * 16 + bn][bkoff]));
        }
#pragma unroll
        for (int nb = 0; nb < 4; ++nb) {
#pragma unroll
            for (int h = 0; h < 2; ++h) {
                const int j = nb * 2 + h;
                MMA_BF16(acc[j], ah, bh[nb][2 * h], bh[nb][2 * h + 1]);
                MMA_BF16(acc[j], ah, blr[nb][2 * h], blr[nb][2 * h + 1]);
                MMA_BF16(acc[j], al, bh[nb][2 * h], bh[nb][2 * h + 1]);
            }
        }
        if (s + 1 < NS) CVTSTS(p ^ 1);
        __syncthreads();
    }

    // epilogue: bias + gelu (+ optional fused MSE)
    const int row0 = r0 + w * 16 + (l >> 2);
    const int col0 = n0 + 2 * (l & 3);
    float local = 0.0f;
#pragma unroll
    for (int j = 0; j < 8; ++j) {
        int c0 = col0 + j * 8;
        float b0 = 0.f, b1 = 0.f;
        if (COUT % 64 == 0 || c0 < COUT)     b0 = bias[c0];
        if (COUT % 64 == 0 || c0 + 1 < COUT) b1 = bias[c0 + 1];
        float g00 = gelu_exact(acc[j][0] + b0);
        float g01 = gelu_exact(acc[j][1] + b1);
        float g10 = gelu_exact(acc[j][2] + b0);
        float g11 = gelu_exact(acc[j][3] + b1);
        if (FUSE_MSE) {
            if (c0 < COUT) {
                float d0 = xref[(size_t)row0 * COUT + c0] - g00;
                float d1 = xref[(size_t)(row0 + 8) * COUT + c0] - g10;
                local += d0 * d0 + d1 * d1;
            }
            if (c0 + 1 < COUT) {
                float d0 = xref[(size_t)row0 * COUT + c0 + 1] - g01;
                float d1 = xref[(size_t)(row0 + 8) * COUT + c0 + 1] - g11;
                local += d0 * d0 + d1 * d1;
            }
        } else {
            *(float2*)&out[(size_t)row0 * COUT + c0] = make_float2(g00, g01);
            *(float2*)&out[(size_t)(row0 + 8) * COUT + c0] = make_float2(g10, g11);
        }
    }
    if (FUSE_MSE) {
        __shared__ float red[256];
        red[tid] = local;
        __syncthreads();
        for (int ss = 128; ss > 0; ss >>= 1) {
            if (tid < ss) red[tid] += red[tid + ss];
            __syncthreads();
        }
        if (tid == 0) atomicAdd(&g_acc[1], red[0]);
    }
}

// ---------------- shared pipelined-GEMM body (generalized B) --------------
#define GEMM_BODY(AROW_EXPR, BBASE, BSTRIDE)                                   \
    const int sm  = tid >> 1;                                                  \
    const int skq = tid & 1;                                                   \
    const int arow = (AROW_EXPR);                                              \
    const float* aptr = Abase + (size_t)arow * DD + 8 * skq;                   \
    const int bk  = tid >> 4;                                                  \
    const int bn4 = (tid & 15) * 4;                                            \
    const float* bbase = (BBASE) + (size_t)bk * (BSTRIDE) + k0;                \
    unsigned long long acc2[8][4];                                             \
    _Pragma("unroll")                                                          \
    for (int i = 0; i < 8; ++i)                                                \
        _Pragma("unroll")                                                      \
        for (int j = 0; j < 4; ++j) acc2[i][j] = 0ull;                         \
    float4 av0, av1, bv0, bv1;                                                 \
    auto LOAD = [&](int cc) {                                                  \
        av0 = *(const float4*)(aptr + cc);                                     \
        av1 = *(const float4*)(aptr + cc + 4);                                 \
        const float* bp = bbase + (size_t)cc * (BSTRIDE);                      \
        bv0 = *(const float4*)(bp + bn4);                                      \
        bv1 = *(const float4*)(bp + 64 + bn4);                                 \
    };                                                                         \
    auto STORE = [&](int p) {                                                  \
        As[p][8 * skq + 0][sm] = av0.x;                                        \
        As[p][8 * skq + 1][sm] = av0.y;                                        \
        As[p][8 * skq + 2][sm] = av0.z;                                        \
        As[p][8 * skq + 3][sm] = av0.w;                                        \
        As[p][8 * skq + 4][sm] = av1.x;                                        \
        As[p][8 * skq + 5][sm] = av1.y;                                        \
        As[p][8 * skq + 6][sm] = av1.z;                                        \
        As[p][8 * skq + 7][sm] = av1.w;                                        \
        *(float4*)&Bs[p][bk][bn4]      = bv0;                                  \
        *(float4*)&Bs[p][bk][64 + bn4] = bv1;                                  \
    };                                                                         \
    LOAD(0); STORE(0);                                                         \
    LOAD(16);                                                                  \
    __syncthreads();                                                           \
    for (int ch = 0; ch < 32; ++ch) {                                          \
        const int p = ch & 1;                                                  \
        if (ch + 1 < 32) STORE(p ^ 1);                                         \
        if (ch + 2 < 32) LOAD((ch + 2) * 16);                                  \
        _Pragma("unroll")                                                      \
        for (int kk = 0; kk < 16; ++kk) {                                      \
            float4 aL = *(const float4*)&As[p][kk][ty * 4];                    \
            float4 aH = *(const float4*)&As[p][kk][64 + ty * 4];               \
            float4 bL = *(const float4*)&Bs[p][kk][tx * 4];                    \
            float4 bH = *(const float4*)&Bs[p][kk][64 + tx * 4];               \
            unsigned long long b2[4], a2;                                      \
            pack2(b2[0], bL.x, bL.y);                                          \
            pack2(b2[1], bL.z, bL.w);                                          \
            pack2(b2[2], bH.x, bH.y);                                          \
            pack2(b2[3], bH.z, bH.w);                                          \
            float arr[8] = {aL.x, aL.y, aL.z, aL.w, aH.x, aH.y, aH.z, aH.w};   \
            _Pragma("unroll")                                                  \
            for (int i = 0; i < 8; ++i) {                                      \
                splat2(a2, arr[i]);                                            \
                _Pragma("unroll")                                              \
                for (int j = 0; j < 4; ++j) ffma2(acc2[i][j], a2, b2[j]);      \
            }                                                                  \
        }                                                                      \
        __syncthreads();                                                       \
    }

// ---------------- stage-0 GEMM via mma.sync bf16-split ---------------------
__global__ void __launch_bounds__(256, 2) vq_gemm_mma(
    const float* __restrict__ zin, const float* __restrict__ cb)
{
    __shared__ __align__(16) __nv_bfloat16 sAh[2][128][24];
    __shared__ __align__(16) __nv_bfloat16 sAl[2][128][24];
    __shared__ __align__(16) __nv_bfloat16 sBh[2][64][24];
    __shared__ __align__(16) __nv_bfloat16 sBl[2][64][24];

    const int tid = threadIdx.x;
    const int w = tid >> 5, l = tid & 31;
    const int r0 = blockIdx.x * 128;
    const int k0 = blockIdx.y * 64;

    const int arow = tid >> 1;
    const int adh  = (tid & 1) * 8;
    const float* aP = zin + (size_t)(r0 + arow) * DD + adh;
    const int brow = tid >> 2;
    const int bdq  = (tid & 3) * 4;
    const float* bP = cb + (size_t)(k0 + brow) * DD + bdq;

    float acc[8][4];
#pragma unroll
    for (int j = 0; j < 8; ++j)
#pragma unroll
        for (int c = 0; c < 4; ++c) acc[j][c] = 0.0f;

    float4 a0v, a1v, bv;
    auto LDG = [&](int ks) {
        a0v = *(const float4*)(aP + ks * 16);
        a1v = *(const float4*)(aP + ks * 16 + 4);
        bv  = *(const float4*)(bP + ks * 16);
    };
    auto CVTSTS = [&](int p) {
        cvt_split2(&sAh[p][arow][adh + 0], &sAl[p][arow][adh + 0], a0v.x, a0v.y);
        cvt_split2(&sAh[p][arow][adh + 2], &sAl[p][arow][adh + 2], a0v.z, a0v.w);
        cvt_split2(&sAh[p][arow][adh + 4], &sAl[p][arow][adh + 4], a1v.x, a1v.y);
        cvt_split2(&sAh[p][arow][adh + 6], &sAl[p][arow][adh + 6], a1v.z, a1v.w);
        cvt_split2(&sBh[p][brow][bdq + 0], &sBl[p][brow][bdq + 0], bv.x, bv.y);
        cvt_split2(&sBh[p][brow][bdq + 2], &sBl[p][brow][bdq + 2], bv.z, bv.w);
    };

    const int arl = l & 15, ach = (l >> 4) * 8;
    const int bg = l >> 3;
    const int bn = ((bg >= 2) ? 8 : 0) + (l & 7);
    const int bkoff = (bg & 1) * 8;

    LDG(0); CVTSTS(0);
    __syncthreads();

    for (int ks = 0; ks < 32; ++ks) {
        const int p = ks & 1;
        if (ks + 1 < 32) LDG(ks + 1);

        uint32_t ah[4], al[4];
        LDSM_X4(ah[0], ah[1], ah[2], ah[3], smem_u32(&sAh[p][w * 16 + arl][ach]));
        LDSM_X4(al[0], al[1], al[2], al[3], smem_u32(&sAl[p][w * 16 + arl][ach]));
        uint32_t bh[4][4], blr[4][4];
#pragma unroll
        for (int nb = 0; nb < 4; ++nb) {
            LDSM_X4(bh[nb][0], bh[nb][1], bh[nb][2], bh[nb][3],
                    smem_u32(&sBh[p][nb * 16 + bn][bkoff]));
            LDSM_X4(blr[nb][0], blr[nb][1], blr[nb][2], blr[nb][3],
                    smem_u32(&sBl[p][nb * 16 + bn][bkoff]));
        }
#pragma unroll
        for (int nb = 0; nb < 4; ++nb) {
#pragma unroll
            for (int h = 0; h < 2; ++h) {
                const int j = nb * 2 + h;
                MMA_BF16(acc[j], ah, bh[nb][2 * h], bh[nb][2 * h + 1]);
                MMA_BF16(acc[j], ah, blr[nb][2 * h], blr[nb][2 * h + 1]);
                MMA_BF16(acc[j], al, bh[nb][2 * h], bh[nb][2 * h + 1]);
            }
        }
        if (ks + 1 < 32) CVTSTS(p ^ 1);
        __syncthreads();
    }

    const int row0 = r0 + w * 16 + (l >> 2);
    const int col0 = k0 + 2 * (l & 3);
#pragma unroll
    for (int j = 0; j < 8; ++j) {
        *(float2*)&g_dist[(size_t)row0 * KK + col0 + j * 8] =
            make_float2(acc[j][0], acc[j][1]);
        *(float2*)&g_dist[(size_t)(row0 + 8) * KK + col0 + j * 8] =
            make_float2(acc[j][2], acc[j][3]);
    }
}

// ---------------- Gram GEMM: G = cb · cbT + csq = diag(G) ------------------
__global__ void __launch_bounds__(256, 2) gram_gemm(const float* __restrict__ cb) {
    __shared__ __align__(16) float As[2][16][SAS];
    __shared__ __align__(16) float Bs[2][16][SAS];
    const int tid = threadIdx.x;
    const int tx = tid & 15, ty = tid >> 4;
    const int r0 = blockIdx.x * 128;
    const int k0 = blockIdx.y * 128;
    const float* Abase = cb;
    GEMM_BODY(r0 + (tid >> 1), g_cbT, KK)

#pragma unroll
    for (int i = 0; i < 8; ++i) {
        int m = (i < 4) ? (ty * 4 + i) : (64 + ty * 4 + (i - 4));
        int row = r0 + m;
        float d0, d1, d2, d3;
        unpack2(d0, d1, acc2[i][0]);
        unpack2(d2, d3, acc2[i][1]);
        *(float4*)&g_G[(size_t)row * KK + k0 + tx * 4] = make_float4(d0, d1, d2, d3);
        if (r0 == k0) {
            int c0 = k0 + tx * 4;
            if (row >= c0 && row < c0 + 4) {
                float dd[4] = {d0, d1, d2, d3};
                g_csq[row] = dd[row - c0];
            }
        }
        unpack2(d0, d1, acc2[i][2]);
        unpack2(d2, d3, acc2[i][3]);
        *(float4*)&g_G[(size_t)row * KK + k0 + 64 + tx * 4] = make_float4(d0, d1, d2, d3);
        if (r0 == k0) {
            int c1 = k0 + 64 + tx * 4;
            if (row >= c1 && row < c1 + 4) {
                float dd[4] = {d0, d1, d2, d3};
                g_csq[row] = dd[row - c1];
            }
        }
    }
}

// ---------------- U GEMM: U[tap] = cb · W1_tap^T  (grid 8 x 2 x 3) ---------
__global__ void __launch_bounds__(256, 2) u_gemm(const float* __restrict__ cb) {
    __shared__ __align__(16) float As[2][16][SAS];
    __shared__ __align__(16) float Bs[2][16][SAS];
    const int tid = threadIdx.x;
    const int tx = tid & 15, ty = tid >> 4;
    const int r0 = blockIdx.x * 128;
    const int k0 = blockIdx.y * 128;
    const int tap = blockIdx.z;
    const float* Abase = cb;
    const float* wt3 = g_wT + WT_O3 + (size_t)tap * 512 * 256;
    GEMM_BODY(r0 + (tid >> 1), wt3, 256)

#pragma unroll
    for (int i = 0; i < 8; ++i) {
        int m = (i < 4) ? (ty * 4 + i) : (64 + ty * 4 + (i - 4));
        int row = r0 + m;
        float* urow = &g_U[((size_t)tap * KK + row) * 256 + k0];
        float d0, d1, d2, d3;
        unpack2(d0, d1, acc2[i][0]);
        unpack2(d2, d3, acc2[i][1]);
        *(float4*)(urow + tx * 4) = make_float4(d0, d1, d2, d3);
        unpack2(d0, d1, acc2[i][2]);
        unpack2(d2, d3, acc2[i][3]);
        *(float4*)(urow + 64 + tx * 4) = make_float4(d0, d1, d2, d3);
    }
}

// ---------------- init_small ----------------
__global__ void init_small() {
    int tid = threadIdx.x;  // 32
    if (tid < 8) {
        unsigned a, b;
        tf2x32(0u, 42u, 0u, (unsigned)tid, a, b);
        g_fk[2 * tid] = a;
        g_fk[2 * tid + 1] = b;
    }
    if (tid < 2) g_acc[tid] = 0.0f;
    if (tid == 0) {
        float ghi = gumbel_from_bits(0xFFFFFFFFu);
        float glo = gumbel_from_bits(0u);
        g_window = (ghi - glo) + 0.5f;
    }
}

// ---------------- pick: rn2 + all 8 VQ stages per row -> g_sel -------------
__global__ void __launch_bounds__(256) vq_pick() {
    const int bt = blockIdx.x;
    const int tid = threadIdx.x;
    __shared__ unsigned sMaxU;
    __shared__ unsigned long long sBest;
    __shared__ float sDotSel;
    __shared__ int sSel[8];
    __shared__ float red[256];

    if (tid == 0) { sMaxU = 0u; sBest = 0ull; }

    {
        float z0 = g_res[(size_t)bt * DD + tid];
        float z1 = g_res[(size_t)bt * DD + tid + 256];
        red[tid] = z0 * z0 + z1 * z1;
    }

    float d[4], cs[4], s[4];
    const float* drow = &g_dist[(size_t)bt * KK];
#pragma unroll
    for (int j = 0; j < 4; ++j) {
        d[j] = drow[tid + 256 * j];
        cs[j] = g_csq[tid + 256 * j];
        s[j] = fmaf(20.0f, d[j], -10.0f * cs[j]);
    }
    __syncthreads();
    for (int ss = 128; ss > 0; ss >>= 1) {
        if (tid < ss) red[tid] += red[tid + ss];
        __syncthreads();
    }
    const float win = g_window;
    const unsigned btL = (bt < 8192) ? (unsigned)bt : (unsigned)(bt - 8192);
    const bool hi = (bt >= 8192);
    float rn2 = (tid == 0) ? red[0] : 0.0f;
    float commit = 0.0f;

    for (int i = 0; i < 8; ++i) {
        float lm = fmaxf(fmaxf(s[0], s[1]), fmaxf(s[2], s[3]));
#pragma unroll
        for (int off = 16; off > 0; off >>= 1)
            lm = fmaxf(lm, __shfl_xor_sync(0xffffffffu, lm, off));
        if ((tid & 31) == 0) atomicMax(&sMaxU, fmap(lm));
        __syncthreads();
        const float tau = unfmap(sMaxU) - win;

        const unsigned fk0 = g_fk[2 * i], fk1 = g_fk[2 * i + 1];
#pragma unroll
        for (int j = 0; j < 4; ++j) {
            if (s[j] >= tau) {
                unsigned k = (unsigned)(tid + 256 * j);
                unsigned n = btL * 1024u + k;
                unsigned b0, b1;
                tf2x32(fk0, fk1, n, n + HALF_N, b0, b1);
                float g = gumbel_from_bits(hi ? b1 : b0);
                float sc = s[j] + g;
                unsigned long long cand =
                    ((unsigned long long)fmap(sc) << 32) | (unsigned long long)(~k);
                atomicMax(&sBest, cand);
            }
        }
        __syncthreads();
        const unsigned sel = ~(unsigned)(sBest & 0xffffffffull);
        if (tid == (int)(sel & 255u)) sDotSel = d[sel >> 8];
        __syncthreads();
        if (tid == 0) {
            float rn2n = rn2 - 2.0f * sDotSel + g_csq[sel];
            commit += rn2n;
            rn2 = rn2n;
            sSel[i] = (int)sel;
            sMaxU = 0u;
            sBest = 0ull;
        }
        if (i < 7) {
            const float* grow = &g_G[(size_t)sel * KK];
#pragma unroll
            for (int j = 0; j < 4; ++j) {
                d[j] -= grow[tid + 256 * j];
                s[j] = fmaf(20.0f, d[j], -10.0f * cs[j]);
            }
        }
        __syncthreads();
    }

    if (tid < 8) g_sel[bt * 8 + tid] = sSel[tid];
    if (tid == 0) atomicAdd(&g_acc[0], commit);
}

// ---------------- dec1 gather: h1[bt] = gelu(bias + sum U rows) ------------
__global__ void __launch_bounds__(256) dec1_gather(const float* __restrict__ bias) {
    const int bt = blockIdx.x;
    const int c = threadIdx.x;
    __shared__ int sIdx[24];

    if (c < 24) {
        int tap = c >> 3, i = c & 7;
        int t = bt & (TT - 1);
        int st = t + tap - 1;
        int idx = -1;
        if (st >= 0 && st < TT)
            idx = tap * KK + g_sel[(bt + tap - 1) * 8 + i];
        sIdx[c] = idx;
    }
    __syncthreads();

    float acc = bias[c];
#pragma unroll
    for (int j = 0; j < 24; ++j) {
        int idx = sIdx[j];
        if (idx >= 0) acc += g_U[(size_t)idx * 256 + c];
    }
    g_h1[(size_t)bt * 256 + c] = gelu_exact(acc);
}

__global__ void finalize_k(float* __restrict__ out) {
    out[0] = g_acc[1] * (1.0f / 1638400.0f)
           + g_acc[0] * (1.0f / 67108864.0f);
}

// ---------------- streams/events (created once, pre-baseline) --------------
struct SideStream {
    cudaStream_t s;
    cudaEvent_t fork, wtev, join1, join2;
    SideStream() {
        cudaStreamCreateWithFlags(&s, cudaStreamNonBlocking);
        cudaEventCreateWithFlags(&fork, cudaEventDisableTiming);
        cudaEventCreateWithFlags(&wtev, cudaEventDisableTiming);
        cudaEventCreateWithFlags(&join1, cudaEventDisableTiming);
        cudaEventCreateWithFlags(&join2, cudaEventDisableTiming);
    }
};
static SideStream g_ss;

// ---------------- host launcher (graph-capturable, alloc-free) -------------
extern "C" void kernel_launch(void* const* d_in, const int* in_sizes, int n_in,
                              void* d_out, int out_size) {
    const float* x   = (const float*)d_in[0];
    const float* ew1 = (const float*)d_in[1];
    const float* eb1 = (const float*)d_in[2];
    const float* ew2 = (const float*)d_in[3];
    const float* eb2 = (const float*)d_in[4];
    const float* cb  = (const float*)d_in[5];
    const float* dw1 = (const float*)d_in[6];
    const float* db1 = (const float*)d_in[7];
    const float* dw2 = (const float*)d_in[8];
    const float* db2 = (const float*)d_in[9];
    float* out = (float*)d_out;

    float *h1, *res, *wT, *wTT;
    cudaGetSymbolAddress((void**)&h1,  g_h1);
    cudaGetSymbolAddress((void**)&res, g_res);
    cudaGetSymbolAddress((void**)&wT,  g_wT);
    cudaGetSymbolAddress((void**)&wTT, g_wTT);

    // fork side branch: cbT -> Gram(+csq) -> init_small
    cudaEventRecord(g_ss.fork, 0);
    cudaStreamWaitEvent(g_ss.s, g_ss.fork, 0);
    transpose_cb<<<dim3(KK / 32, DD / 32), dim3(32, 8), 0, g_ss.s>>>(cb);
    gram_gemm<<<dim3(8, 8), 256, 0, g_ss.s>>>(cb);
    init_small<<<1, 32, 0, g_ss.s>>>();
    cudaEventRecord(g_ss.join1, g_ss.s);

    // main branch: weights (both layouts) -> encoder
    transpose_w_all<<<(WT_END + WTT_END + 255) / 256, 256>>>(ew1, ew2, dw1, dw2);
    cudaEventRecord(g_ss.wtev, 0);

    // side: U = cb · dec_w1^T per tap (needs wT3) — overlaps encoder convs
    cudaStreamWaitEvent(g_ss.s, g_ss.wtev, 0);
    u_gemm<<<dim3(8, 2, 3), 256, 0, g_ss.s>>>(cb);
    cudaEventRecord(g_ss.join2, g_ss.s);

    conv3f<100, 256, 256, false><<<dim3(128, 2), 256>>>(x, wT + WT_O1, eb1, h1, nullptr);
    conv_mma<256, 512, 512, false><<<dim3(128, 8), 256>>>(h1, wTT + WTT_O2, eb2, res, nullptr);

    // join: vq needs cbT / G / csq / fk / window
    cudaStreamWaitEvent(0, g_ss.join1, 0);
    vq_gemm_mma<<<dim3(128, 16), 256>>>(res, cb);
    vq_pick<<<BT, 256>>>();

    // decoder: gathered dec1 (needs U), then dec2 mma conv with fused MSE
    cudaStreamWaitEvent(0, g_ss.join2, 0);
    dec1_gather<<<BT, 256>>>(db1);
    conv_mma<256, 100, 128, true><<<dim3(128, 2), 256>>>(h1, wTT + WTT_O4, db2, nullptr, x);

    finalize_k<<<1, 1>>>(out);
}